// round 1
// baseline (speedup 1.0000x reference)
#include <cuda_runtime.h>
#include <math.h>

#define NBASE 40000
#define NJOINT 480000
#define NFOOT 160000
#define HDIM 128
#define NEG_SLOPE 0.2f

// ---------------- scratch (device globals; no allocation allowed) ----------------
__device__ float g_xb[(size_t)NBASE * HDIM];
__device__ float g_xj[(size_t)NJOINT * HDIM];
__device__ float g_xf[(size_t)NFOOT * HDIM];
__device__ float g_ab[(size_t)NBASE * HDIM];
__device__ float g_aj[(size_t)NJOINT * HDIM];
__device__ float g_af[(size_t)NFOOT * HDIM];
__device__ float g_xl[(size_t)NJOINT * HDIM];
__device__ float g_xr[(size_t)NJOINT * HDIM];
__device__ float g_num[(size_t)NJOINT * HDIM];
__device__ float g_sbuf[320000];
__device__ unsigned g_menc[NJOINT];
__device__ float g_den[NJOINT];

// ---------------- helpers ----------------
static __device__ __forceinline__ unsigned fenc(float f) {
    unsigned u = __float_as_uint(f);
    return (u & 0x80000000u) ? ~u : (u | 0x80000000u);
}
static __device__ __forceinline__ float fdec(unsigned u) {
    return (u & 0x80000000u) ? __uint_as_float(u ^ 0x80000000u) : __uint_as_float(~u);
}

__global__ void fill_u32_k(unsigned* p, unsigned v, int n) {
    int i = blockIdx.x * blockDim.x + threadIdx.x;
    if (i < n) p[i] = v;
}

// ---------------- encoder: y[n,h] = relu(sum_k x[n,k] W[k,h] + b[h]) ----------------
__global__ void encode_k(const float* __restrict__ x, const float* __restrict__ W,
                         const float* __restrict__ b, float* __restrict__ y,
                         int N, int K) {
    int idx = blockIdx.x * blockDim.x + threadIdx.x;
    if (idx >= N * HDIM) return;
    int n = idx >> 7, h = idx & 127;
    float acc = b[h];
    for (int k = 0; k < K; k++) acc += x[n * K + k] * W[k * HDIM + h];
    y[idx] = fmaxf(acc, 0.f);
}

// ---------------- GEMM: Y[M,128] = X[M,128] @ W[128,128] + b ----------------
// 256 threads, 64 rows/block, W fully in smem, X tile in smem, 8x4 microtile.
__global__ void gemm128_k(const float* __restrict__ X, const float* __restrict__ W,
                          const float* __restrict__ b, float* __restrict__ Y, int M) {
    extern __shared__ float sm[];
    float* Ws = sm;            // 128*128
    float* Xs = sm + 16384;    // 64*128
    int tid = threadIdx.x;

    const float4* Wv = (const float4*)W;
    float4* Wsv = (float4*)Ws;
#pragma unroll
    for (int i = 0; i < 16; i++) Wsv[tid + 256 * i] = Wv[tid + 256 * i];

    long row0 = (long)blockIdx.x * 64;
    const float4* Xv = (const float4*)X;
    float4* Xsv = (float4*)Xs;
#pragma unroll
    for (int i = 0; i < 8; i++) {
        int idx = tid + 256 * i;
        int r = idx >> 5, c = idx & 31;
        float4 v = (row0 + r < M) ? Xv[(row0 + r) * 32 + c] : make_float4(0.f, 0.f, 0.f, 0.f);
        Xsv[idx] = v;
    }
    __syncthreads();

    int tx = tid & 31;   // cols tx*4 .. tx*4+3
    int ty = tid >> 5;   // rows ty*8 .. ty*8+7
    float acc[8][4];
#pragma unroll
    for (int r = 0; r < 8; r++)
#pragma unroll
        for (int c = 0; c < 4; c++) acc[r][c] = 0.f;

#pragma unroll 4
    for (int k4 = 0; k4 < 32; k4++) {
        float4 w0 = ((float4*)(Ws + (k4 * 4 + 0) * 128))[tx];
        float4 w1 = ((float4*)(Ws + (k4 * 4 + 1) * 128))[tx];
        float4 w2 = ((float4*)(Ws + (k4 * 4 + 2) * 128))[tx];
        float4 w3 = ((float4*)(Ws + (k4 * 4 + 3) * 128))[tx];
#pragma unroll
        for (int r = 0; r < 8; r++) {
            float4 xv = ((float4*)(Xs + (ty * 8 + r) * 128))[k4];
            acc[r][0] += xv.x * w0.x + xv.y * w1.x + xv.z * w2.x + xv.w * w3.x;
            acc[r][1] += xv.x * w0.y + xv.y * w1.y + xv.z * w2.y + xv.w * w3.y;
            acc[r][2] += xv.x * w0.z + xv.y * w1.z + xv.z * w2.z + xv.w * w3.z;
            acc[r][3] += xv.x * w0.w + xv.y * w1.w + xv.z * w2.w + xv.w * w3.w;
        }
    }

    float4 bb = ((const float4*)b)[tx];
#pragma unroll
    for (int r = 0; r < 8; r++) {
        long row = row0 + ty * 8 + r;
        if (row < M) {
            float4 o;
            o.x = acc[r][0] + bb.x; o.y = acc[r][1] + bb.y;
            o.z = acc[r][2] + bb.z; o.w = acc[r][3] + bb.w;
            ((float4*)(Y + row * 128))[tx] = o;
        }
    }
}

// ---------------- edge pass 1: logits + segment max ----------------
__global__ void edge_logits_k(const float* __restrict__ xl, const float* __restrict__ xr,
                              const int* __restrict__ src, const int* __restrict__ dst,
                              const float* __restrict__ att, float* __restrict__ s_out,
                              unsigned* __restrict__ menc, int E) {
    int e = blockIdx.x * 8 + (threadIdx.x >> 5);
    if (e >= E) return;
    int lane = threadIdx.x & 31;
    int si = src[e], di = dst[e];
    float4 a = ((const float4*)(xl + (size_t)si * 128))[lane];
    float4 r = ((const float4*)(xr + (size_t)di * 128))[lane];
    float4 at = ((const float4*)att)[lane];
    float vx = a.x + r.x, vy = a.y + r.y, vz = a.z + r.z, vw = a.w + r.w;
    vx = vx > 0.f ? vx : NEG_SLOPE * vx;
    vy = vy > 0.f ? vy : NEG_SLOPE * vy;
    vz = vz > 0.f ? vz : NEG_SLOPE * vz;
    vw = vw > 0.f ? vw : NEG_SLOPE * vw;
    float sum = vx * at.x + vy * at.y + vz * at.z + vw * at.w;
#pragma unroll
    for (int o = 16; o; o >>= 1) sum += __shfl_xor_sync(0xffffffffu, sum, o);
    if (lane == 0) {
        s_out[e] = sum;
        atomicMax(menc + di, fenc(sum));
    }
}

// ---------------- edge pass 2: softmax weights + weighted scatter-add ----------------
__global__ void edge_accum_k(const float* __restrict__ xl, const float* __restrict__ s,
                             const int* __restrict__ src, const int* __restrict__ dst,
                             const unsigned* __restrict__ menc, float* __restrict__ den,
                             float* __restrict__ num, int E) {
    int e = blockIdx.x * 8 + (threadIdx.x >> 5);
    if (e >= E) return;
    int lane = threadIdx.x & 31;
    int si = src[e], di = dst[e];
    float m = fdec(menc[di]);
    float a = expf(s[e] - m);
    if (lane == 0) atomicAdd(den + di, a);
    float4 x = ((const float4*)(xl + (size_t)si * 128))[lane];
    float* np = num + (size_t)di * 128 + lane * 4;
    atomicAdd(np + 0, a * x.x);
    atomicAdd(np + 1, a * x.y);
    atomicAdd(np + 2, a * x.z);
    atomicAdd(np + 3, a * x.w);
}

// ---------------- finalize: agg += num/den + bias ----------------
__global__ void finalize_k(const float* __restrict__ num, const float* __restrict__ den,
                           const float* __restrict__ bias, float* __restrict__ agg, int Nd) {
    int idx = blockIdx.x * blockDim.x + threadIdx.x;
    if (idx >= Nd * HDIM) return;
    int n = idx >> 7, h = idx & 127;
    agg[idx] += num[idx] / fmaxf(den[n], 1e-16f) + bias[h];
}

__global__ void relu_copy_k(const float* __restrict__ a, float* __restrict__ x, int n) {
    int i = blockIdx.x * blockDim.x + threadIdx.x;
    if (i < n) x[i] = fmaxf(a[i], 0.f);
}

// ---------------- decoder: out[f,0..2] = xf[f,:] @ Wdec + bdec ----------------
__global__ void decode_k(const float* __restrict__ xf, const float* __restrict__ W,
                         const float* __restrict__ b, float* __restrict__ out, int N) {
    int f = blockIdx.x * 8 + (threadIdx.x >> 5);
    if (f >= N) return;
    int lane = threadIdx.x & 31;
    float4 v = ((const float4*)(xf + (size_t)f * 128))[lane];
    float s0 = 0.f, s1 = 0.f, s2 = 0.f;
    int h = lane * 4;
    s0 += v.x * W[(h + 0) * 3 + 0] + v.y * W[(h + 1) * 3 + 0] + v.z * W[(h + 2) * 3 + 0] + v.w * W[(h + 3) * 3 + 0];
    s1 += v.x * W[(h + 0) * 3 + 1] + v.y * W[(h + 1) * 3 + 1] + v.z * W[(h + 2) * 3 + 1] + v.w * W[(h + 3) * 3 + 1];
    s2 += v.x * W[(h + 0) * 3 + 2] + v.y * W[(h + 1) * 3 + 2] + v.z * W[(h + 2) * 3 + 2] + v.w * W[(h + 3) * 3 + 2];
#pragma unroll
    for (int o = 16; o; o >>= 1) {
        s0 += __shfl_xor_sync(0xffffffffu, s0, o);
        s1 += __shfl_xor_sync(0xffffffffu, s1, o);
        s2 += __shfl_xor_sync(0xffffffffu, s2, o);
    }
    if (lane == 0) {
        out[f * 3 + 0] = s0 + b[0];
        out[f * 3 + 1] = s1 + b[1];
        out[f * 3 + 2] = s2 + b[2];
    }
}

// ---------------- host orchestration ----------------
extern "C" void kernel_launch(void* const* d_in, const int* in_sizes, int n_in,
                              void* d_out, int out_size) {
    // Logical order:
    // 0 x_base 1 x_joint 2 x_foot 3 Wenc_b 4 benc_b 5 Wenc_j 6 benc_j 7 Wenc_f 8 benc_f
    // 9 Wl 10 bl 11 Wr 12 br 13 att 14 conv_bias 15 W_dec 16 b_dec
    // 17..26 src/dst for (bj, jb, jj, jf, fj)
    int I[27];
    if (in_sizes[1] == 768) {
        // setup_inputs dict order
        const int m[27] = {0, 3, 6, 1, 2, 4, 5, 7, 8,
                           19, 20, 21, 22, 23, 24, 25, 26,
                           9, 10, 11, 12, 13, 14, 15, 16, 17, 18};
        for (int i = 0; i < 27; i++) I[i] = m[i];
    } else {
        // reference() signature order
        for (int i = 0; i < 27; i++) I[i] = i;
    }

    const float* x_base  = (const float*)d_in[I[0]];
    const float* x_joint = (const float*)d_in[I[1]];
    const float* x_foot  = (const float*)d_in[I[2]];
    const float* Wenc[3] = {(const float*)d_in[I[3]], (const float*)d_in[I[5]], (const float*)d_in[I[7]]};
    const float* benc[3] = {(const float*)d_in[I[4]], (const float*)d_in[I[6]], (const float*)d_in[I[8]]};
    const float* Wl   = (const float*)d_in[I[9]];
    const float* bl   = (const float*)d_in[I[10]];
    const float* Wr   = (const float*)d_in[I[11]];
    const float* br   = (const float*)d_in[I[12]];
    const float* att  = (const float*)d_in[I[13]];
    const float* cbias = (const float*)d_in[I[14]];
    const float* Wdec = (const float*)d_in[I[15]];
    const float* bdec = (const float*)d_in[I[16]];
    const int* srcA[5], *dstA[5];
    int E[5];
    for (int t = 0; t < 5; t++) {
        srcA[t] = (const int*)d_in[I[17 + 2 * t]];
        dstA[t] = (const int*)d_in[I[18 + 2 * t]];
        E[t] = in_sizes[I[17 + 2 * t]];
    }

    float *xb, *xj, *xf, *ab, *aj, *af, *xl, *xr, *num, *den, *sbuf;
    unsigned* menc;
    cudaGetSymbolAddress((void**)&xb, g_xb);
    cudaGetSymbolAddress((void**)&xj, g_xj);
    cudaGetSymbolAddress((void**)&xf, g_xf);
    cudaGetSymbolAddress((void**)&ab, g_ab);
    cudaGetSymbolAddress((void**)&aj, g_aj);
    cudaGetSymbolAddress((void**)&af, g_af);
    cudaGetSymbolAddress((void**)&xl, g_xl);
    cudaGetSymbolAddress((void**)&xr, g_xr);
    cudaGetSymbolAddress((void**)&num, g_num);
    cudaGetSymbolAddress((void**)&den, g_den);
    cudaGetSymbolAddress((void**)&sbuf, g_sbuf);
    cudaGetSymbolAddress((void**)&menc, g_menc);

    const int SMEM = (16384 + 8192) * 4;  // 96 KB
    cudaFuncSetAttribute(gemm128_k, cudaFuncAttributeMaxDynamicSharedMemorySize, SMEM);

    // encoders
    encode_k<<<(NBASE * HDIM + 255) / 256, 256>>>(x_base, Wenc[0], benc[0], xb, NBASE, 6);
    encode_k<<<(NJOINT * HDIM + 255) / 256, 256>>>(x_joint, Wenc[1], benc[1], xj, NJOINT, 2);
    encode_k<<<(NFOOT * HDIM + 255) / 256, 256>>>(x_foot, Wenc[2], benc[2], xf, NFOOT, 4);

    float* X[3] = {xb, xj, xf};
    float* A[3] = {ab, aj, af};
    const int Nn[3] = {NBASE, NJOINT, NFOOT};
    const int sT[5] = {0, 1, 1, 1, 2};
    const int dT[5] = {1, 0, 1, 2, 1};

    for (int l = 0; l < 4; l++) {
        cudaMemsetAsync(ab, 0, (size_t)NBASE * HDIM * 4);
        cudaMemsetAsync(aj, 0, (size_t)NJOINT * HDIM * 4);
        cudaMemsetAsync(af, 0, (size_t)NFOOT * HDIM * 4);
        for (int ei = 0; ei < 5; ei++) {
            int st = sT[ei], dt = dT[ei];
            int Ns = Nn[st], Nd = Nn[dt], Ee = E[ei];
            size_t po = (size_t)(l * 5 + ei);
            const float* Wl_ = Wl + po * 128 * 128;
            const float* bl_ = bl + po * 128;
            const float* Wr_ = Wr + po * 128 * 128;
            const float* br_ = br + po * 128;
            const float* att_ = att + po * 128;
            const float* cb_ = cbias + po * 128;

            gemm128_k<<<(Ns + 63) / 64, 256, SMEM>>>(X[st], Wl_, bl_, xl, Ns);
            gemm128_k<<<(Nd + 63) / 64, 256, SMEM>>>(X[dt], Wr_, br_, xr, Nd);

            fill_u32_k<<<(Nd + 255) / 256, 256>>>(menc, 0x007FFFFFu, Nd);  // fenc(-inf)
            cudaMemsetAsync(den, 0, (size_t)Nd * 4);
            cudaMemsetAsync(num, 0, (size_t)Nd * HDIM * 4);

            edge_logits_k<<<(Ee + 7) / 8, 256>>>(xl, xr, srcA[ei], dstA[ei], att_, sbuf, menc, Ee);
            edge_accum_k<<<(Ee + 7) / 8, 256>>>(xl, sbuf, srcA[ei], dstA[ei], menc, den, num, Ee);
            finalize_k<<<(Nd * HDIM + 255) / 256, 256>>>(num, den, cb_, A[dt], Nd);
        }
        for (int t = 0; t < 3; t++)
            relu_copy_k<<<(Nn[t] * HDIM + 255) / 256, 256>>>(A[t], X[t], Nn[t] * HDIM);
    }

    decode_k<<<(NFOOT + 7) / 8, 256>>>(xf, Wdec, bdec, (float*)d_out, NFOOT);
}

// round 3
// speedup vs baseline: 2.2540x; 2.2540x over previous
#include <cuda_runtime.h>
#include <cuda_bf16.h>
#include <math.h>

#define NBASE 40000
#define NJOINT 480000
#define NFOOT 160000
#define HDIM 128
#define NEG_SLOPE 0.2f

// ---------------- scratch (device globals; total ~1.19 GB, must stay < 2 GB for linker) ----
// bf16 hi/lo split node features: base @0, joint @ 40000*128, foot @ 520000*128
__device__ __nv_bfloat16 g_Xhi[(size_t)680000 * 128];
__device__ __nv_bfloat16 g_Xlo[(size_t)680000 * 128];
// reusable per-edge-type GEMM outputs (fp32), sized for the largest node set
__device__ float g_xl[(size_t)NJOINT * 128];
__device__ float g_xr[(size_t)NJOINT * 128];
// aggregation buffers
__device__ float g_ab[(size_t)NBASE * HDIM];
__device__ float g_aj[(size_t)NJOINT * HDIM];
__device__ float g_af[(size_t)NFOOT * HDIM];
// transposed + bf16-split weights: 40 matrices (20 Wl then 20 Wr), each [n][k] 128x128
__device__ __nv_bfloat16 g_Wthi[40 * 16384];
__device__ __nv_bfloat16 g_Wtlo[40 * 16384];
// edge scratch
__device__ float g_sbuf[320000];
__device__ unsigned g_menc[NJOINT];
__device__ float g_den[NJOINT];

// ---------------- helpers ----------------
static __device__ __forceinline__ unsigned fenc(float f) {
    unsigned u = __float_as_uint(f);
    return (u & 0x80000000u) ? ~u : (u | 0x80000000u);
}
static __device__ __forceinline__ float fdec(unsigned u) {
    return (u & 0x80000000u) ? __uint_as_float(u ^ 0x80000000u) : __uint_as_float(~u);
}

__global__ void fill_u32_k(unsigned* p, unsigned v, int n) {
    int i = blockIdx.x * blockDim.x + threadIdx.x;
    if (i < n) p[i] = v;
}

static __device__ __forceinline__ void bf16split(float v, __nv_bfloat16& h, __nv_bfloat16& l) {
    h = __float2bfloat16(v);
    l = __float2bfloat16(v - __bfloat162float(h));
}

// ---------------- weight prep: transpose to [n][k] and split to bf16 hi/lo ----------------
__global__ void wprep_k(const float* __restrict__ Wl, const float* __restrict__ Wr,
                        __nv_bfloat16* __restrict__ hi, __nv_bfloat16* __restrict__ lo) {
    int idx = blockIdx.x * 256 + threadIdx.x;   // 40*16384 total
    if (idx >= 40 * 16384) return;
    int m = idx >> 14;
    int e = idx & 16383;
    int n = e >> 7, k = e & 127;
    const float* src = (m < 20) ? (Wl + (size_t)m * 16384) : (Wr + (size_t)(m - 20) * 16384);
    float v = src[k * 128 + n];
    __nv_bfloat16 h, l;
    bf16split(v, h, l);
    hi[idx] = h; lo[idx] = l;
}

// ---------------- encoder: y = relu(x @ W + b), write bf16 hi/lo split ----------------
__global__ void encode_split_k(const float* __restrict__ x, const float* __restrict__ W,
                               const float* __restrict__ b,
                               __nv_bfloat16* __restrict__ yhi, __nv_bfloat16* __restrict__ ylo,
                               int N, int K) {
    int idx = blockIdx.x * blockDim.x + threadIdx.x;
    if (idx >= N * HDIM) return;
    int n = idx >> 7, h = idx & 127;
    float acc = b[h];
    for (int k = 0; k < K; k++) acc += x[n * K + k] * W[k * HDIM + h];
    float v = fmaxf(acc, 0.f);
    __nv_bfloat16 hh, ll;
    bf16split(v, hh, ll);
    yhi[idx] = hh; ylo[idx] = ll;
}

// ---------------- relu + split (layer transition) ----------------
__global__ void relu_split_k(const float* __restrict__ a,
                             __nv_bfloat16* __restrict__ hi, __nv_bfloat16* __restrict__ lo, int n) {
    int i = blockIdx.x * blockDim.x + threadIdx.x;
    if (i >= n) return;
    float v = fmaxf(a[i], 0.f);
    __nv_bfloat16 hh, ll;
    bf16split(v, hh, ll);
    hi[i] = hh; lo[i] = ll;
}

// ---------------- agg init with summed conv biases ----------------
__global__ void fill_agg_k(float* __restrict__ agg, const float* __restrict__ b0,
                           const float* __restrict__ b1, const float* __restrict__ b2, int n) {
    int i = blockIdx.x * blockDim.x + threadIdx.x;
    if (i >= n) return;
    int h = i & 127;
    float v = b0[h];
    if (b1) v += b1[h];
    if (b2) v += b2[h];
    agg[i] = v;
}

// ---------------- tensor-core multi-set GEMM ----------------
// Y[set] = X[M,128] @ W[set][128,128] + b[set], bf16 3-term split, fp32 accum.
// Block: 256 thr (8 warps 2Mx4N), tile 128x128, full K=128 resident.
struct GemmSet {
    const __nv_bfloat16* Bhi;
    const __nv_bfloat16* Blo;
    const float* bias;
    float* out;
};
struct GemmArgs { GemmSet s[2]; };

#define SA 17408  // 128*136 bf16 elems per matrix (pad 8 halves -> 272B row stride)

#define LDSM4(R, addr) asm volatile( \
    "ldmatrix.sync.aligned.m8n8.x4.shared.b16 {%0,%1,%2,%3}, [%4];" \
    : "=r"((R)[0]), "=r"((R)[1]), "=r"((R)[2]), "=r"((R)[3]) : "r"(addr))

#define MMA16816(C, A, b0, b1) asm volatile( \
    "mma.sync.aligned.m16n8k16.row.col.f32.bf16.bf16.f32 " \
    "{%0,%1,%2,%3},{%4,%5,%6,%7},{%8,%9},{%0,%1,%2,%3};" \
    : "+f"((C)[0]), "+f"((C)[1]), "+f"((C)[2]), "+f"((C)[3]) \
    : "r"((A)[0]), "r"((A)[1]), "r"((A)[2]), "r"((A)[3]), "r"(b0), "r"(b1))

static __device__ __forceinline__ void cpasync16(unsigned dst, const void* src, int sz) {
    asm volatile("cp.async.cg.shared.global [%0], [%1], 16, %2;" :: "r"(dst), "l"(src), "r"(sz));
}

__global__ void __launch_bounds__(256) gemm_multi_k(
    const __nv_bfloat16* __restrict__ Ahi_g, const __nv_bfloat16* __restrict__ Alo_g,
    int M, GemmArgs args, int nsets) {
    extern __shared__ __nv_bfloat16 smem[];
    const int tid = threadIdx.x;
    const long row0 = (long)blockIdx.x * 128;

    unsigned sA = (unsigned)__cvta_generic_to_shared(smem);
    unsigned sB = (unsigned)__cvta_generic_to_shared(smem + 2 * SA);

    // async load A hi/lo
#pragma unroll
    for (int i = 0; i < 8; i++) {
        int chunk = tid + i * 256;        // 2048 16B-chunks per matrix
        int row = chunk >> 4;
        int col = (chunk & 15) * 8;
        long grow = row0 + row;
        int ok = grow < M;
        size_t off = ok ? ((size_t)grow * 128 + col) : 0;
        unsigned d = sA + (unsigned)(row * 136 + col) * 2;
        int sz = ok ? 16 : 0;
        cpasync16(d, Ahi_g + off, sz);
        cpasync16(d + SA * 2, Alo_g + off, sz);
    }
    // load B set 0 -> buf 0
#pragma unroll
    for (int i = 0; i < 8; i++) {
        int chunk = tid + i * 256;
        int row = chunk >> 4;
        int col = (chunk & 15) * 8;
        size_t off = (size_t)row * 128 + col;
        unsigned d = sB + (unsigned)(row * 136 + col) * 2;
        cpasync16(d, args.s[0].Bhi + off, 16);
        cpasync16(d + SA * 2, args.s[0].Blo + off, 16);
    }
    asm volatile("cp.async.commit_group;");

    int warp = tid >> 5, lane = tid & 31;
    int m0 = (warp >> 2) * 64;
    int n0 = (warp & 3) * 32;
    int frow = lane & 15;
    int fcolo = (lane >> 4) * 8;

    for (int s = 0; s < nsets; s++) {
        if (s + 1 < nsets) {
            unsigned bb = sB + (unsigned)(((s + 1) & 1) * 2 * SA) * 2;
#pragma unroll
            for (int i = 0; i < 8; i++) {
                int chunk = tid + i * 256;
                int row = chunk >> 4;
                int col = (chunk & 15) * 8;
                size_t off = (size_t)row * 128 + col;
                unsigned d = bb + (unsigned)(row * 136 + col) * 2;
                cpasync16(d, args.s[s + 1].Bhi + off, 16);
                cpasync16(d + SA * 2, args.s[s + 1].Blo + off, 16);
            }
            asm volatile("cp.async.commit_group;");
            asm volatile("cp.async.wait_group 1;");
        } else {
            asm volatile("cp.async.wait_group 0;");
        }
        __syncthreads();

        unsigned bBase = sB + (unsigned)((s & 1) * 2 * SA) * 2;
        float acc[4][4][4];
#pragma unroll
        for (int a = 0; a < 4; a++)
#pragma unroll
            for (int c = 0; c < 4; c++)
#pragma unroll
                for (int r = 0; r < 4; r++) acc[a][c][r] = 0.f;

        for (int ks = 0; ks < 8; ks++) {
            int acol = ks * 16 + fcolo;
            unsigned ah[4][4], al[4][4];
#pragma unroll
            for (int mt = 0; mt < 4; mt++) {
                unsigned ad = sA + (unsigned)((m0 + mt * 16 + frow) * 136 + acol) * 2;
                LDSM4(ah[mt], ad);
                LDSM4(al[mt], ad + SA * 2);
            }
            unsigned bh[2][4], bl_[2][4];
#pragma unroll
            for (int p = 0; p < 2; p++) {
                unsigned bd = bBase + (unsigned)((n0 + p * 16 + frow) * 136 + acol) * 2;
                LDSM4(bh[p], bd);
                LDSM4(bl_[p], bd);
                LDSM4(bl_[p], bd + SA * 2);
            }
#pragma unroll
            for (int mt = 0; mt < 4; mt++)
#pragma unroll
                for (int nt = 0; nt < 4; nt++) {
                    int p = nt >> 1, o = nt & 1;
                    MMA16816(acc[mt][nt], ah[mt], bh[p][o], bh[p][2 + o]);
                    MMA16816(acc[mt][nt], ah[mt], bl_[p][o], bl_[p][2 + o]);
                    MMA16816(acc[mt][nt], al[mt], bh[p][o], bh[p][2 + o]);
                }
        }

        // epilogue: bias + store fp32
        const float* bias = args.s[s].bias;
        float* out = args.s[s].out;
        int crow = lane >> 2, ccol = (lane & 3) * 2;
#pragma unroll
        for (int nt = 0; nt < 4; nt++) {
            int col = n0 + nt * 8 + ccol;
            float b0v = bias[col], b1v = bias[col + 1];
#pragma unroll
            for (int mt = 0; mt < 4; mt++) {
                long r = row0 + m0 + mt * 16 + crow;
                if (r < M) {
                    float2 v = make_float2(acc[mt][nt][0] + b0v, acc[mt][nt][1] + b1v);
                    *(float2*)(out + (size_t)r * 128 + col) = v;
                }
                if (r + 8 < M) {
                    float2 v = make_float2(acc[mt][nt][2] + b0v, acc[mt][nt][3] + b1v);
                    *(float2*)(out + (size_t)(r + 8) * 128 + col) = v;
                }
            }
        }
        __syncthreads();
    }
}

// ---------------- edge pass 1: logits + segment max ----------------
__global__ void edge_logits_k(const float* __restrict__ xl, const float* __restrict__ xr,
                              const int* __restrict__ src, const int* __restrict__ dst,
                              const float* __restrict__ att, float* __restrict__ s_out,
                              unsigned* __restrict__ menc, int E) {
    int e = blockIdx.x * 8 + (threadIdx.x >> 5);
    if (e >= E) return;
    int lane = threadIdx.x & 31;
    int si = src[e], di = dst[e];
    float4 a = ((const float4*)(xl + (size_t)si * 128))[lane];
    float4 r = ((const float4*)(xr + (size_t)di * 128))[lane];
    float4 at = ((const float4*)att)[lane];
    float vx = a.x + r.x, vy = a.y + r.y, vz = a.z + r.z, vw = a.w + r.w;
    vx = vx > 0.f ? vx : NEG_SLOPE * vx;
    vy = vy > 0.f ? vy : NEG_SLOPE * vy;
    vz = vz > 0.f ? vz : NEG_SLOPE * vz;
    vw = vw > 0.f ? vw : NEG_SLOPE * vw;
    float sum = vx * at.x + vy * at.y + vz * at.z + vw * at.w;
#pragma unroll
    for (int o = 16; o; o >>= 1) sum += __shfl_xor_sync(0xffffffffu, sum, o);
    if (lane == 0) {
        s_out[e] = sum;
        atomicMax(menc + di, fenc(sum));
    }
}

// ---------------- edge pass 2: denominator ----------------
__global__ void edge_den_k(const float* __restrict__ s, const int* __restrict__ dst,
                           const unsigned* __restrict__ menc, float* __restrict__ den, int E) {
    int e = blockIdx.x * blockDim.x + threadIdx.x;
    if (e >= E) return;
    int di = dst[e];
    atomicAdd(den + di, __expf(s[e] - fdec(menc[di])));
}

// ---------------- edge pass 3: normalized scatter directly into agg ----------------
__global__ void edge_scatter_k(const float* __restrict__ xl, const float* __restrict__ s,
                               const int* __restrict__ src, const int* __restrict__ dst,
                               const unsigned* __restrict__ menc, const float* __restrict__ den,
                               float* __restrict__ agg, int E) {
    int e = blockIdx.x * 8 + (threadIdx.x >> 5);
    if (e >= E) return;
    int lane = threadIdx.x & 31;
    int si = src[e], di = dst[e];
    float a = __expf(s[e] - fdec(menc[di])) / den[di];
    float4 x = ((const float4*)(xl + (size_t)si * 128))[lane];
    float* p = agg + (size_t)di * 128 + lane * 4;
    atomicAdd(p + 0, a * x.x);
    atomicAdd(p + 1, a * x.y);
    atomicAdd(p + 2, a * x.z);
    atomicAdd(p + 3, a * x.w);
}

// ---------------- decoder with fused relu ----------------
__global__ void decode_k(const float* __restrict__ agg, const float* __restrict__ W,
                         const float* __restrict__ b, float* __restrict__ out, int N) {
    int f = blockIdx.x * 8 + (threadIdx.x >> 5);
    if (f >= N) return;
    int lane = threadIdx.x & 31;
    float4 v = ((const float4*)(agg + (size_t)f * 128))[lane];
    v.x = fmaxf(v.x, 0.f); v.y = fmaxf(v.y, 0.f); v.z = fmaxf(v.z, 0.f); v.w = fmaxf(v.w, 0.f);
    float s0, s1, s2;
    int h = lane * 4;
    s0 = v.x * W[(h + 0) * 3 + 0] + v.y * W[(h + 1) * 3 + 0] + v.z * W[(h + 2) * 3 + 0] + v.w * W[(h + 3) * 3 + 0];
    s1 = v.x * W[(h + 0) * 3 + 1] + v.y * W[(h + 1) * 3 + 1] + v.z * W[(h + 2) * 3 + 1] + v.w * W[(h + 3) * 3 + 1];
    s2 = v.x * W[(h + 0) * 3 + 2] + v.y * W[(h + 1) * 3 + 2] + v.z * W[(h + 2) * 3 + 2] + v.w * W[(h + 3) * 3 + 2];
#pragma unroll
    for (int o = 16; o; o >>= 1) {
        s0 += __shfl_xor_sync(0xffffffffu, s0, o);
        s1 += __shfl_xor_sync(0xffffffffu, s1, o);
        s2 += __shfl_xor_sync(0xffffffffu, s2, o);
    }
    if (lane == 0) {
        out[f * 3 + 0] = s0 + b[0];
        out[f * 3 + 1] = s1 + b[1];
        out[f * 3 + 2] = s2 + b[2];
    }
}

// ---------------- host orchestration ----------------
extern "C" void kernel_launch(void* const* d_in, const int* in_sizes, int n_in,
                              void* d_out, int out_size) {
    int I[27];
    if (in_sizes[1] == 768) {
        const int m[27] = {0, 3, 6, 1, 2, 4, 5, 7, 8,
                           19, 20, 21, 22, 23, 24, 25, 26,
                           9, 10, 11, 12, 13, 14, 15, 16, 17, 18};
        for (int i = 0; i < 27; i++) I[i] = m[i];
    } else {
        for (int i = 0; i < 27; i++) I[i] = i;
    }

    const float* x_in[3] = {(const float*)d_in[I[0]], (const float*)d_in[I[1]], (const float*)d_in[I[2]]};
    const float* Wenc[3] = {(const float*)d_in[I[3]], (const float*)d_in[I[5]], (const float*)d_in[I[7]]};
    const float* benc[3] = {(const float*)d_in[I[4]], (const float*)d_in[I[6]], (const float*)d_in[I[8]]};
    const float* Wl = (const float*)d_in[I[9]];
    const float* bl = (const float*)d_in[I[10]];
    const float* Wr = (const float*)d_in[I[11]];
    const float* br = (const float*)d_in[I[12]];
    const float* att = (const float*)d_in[I[13]];
    const float* cbias = (const float*)d_in[I[14]];
    const float* Wdec = (const float*)d_in[I[15]];
    const float* bdec = (const float*)d_in[I[16]];
    const int *srcA[5], *dstA[5];
    int E[5];
    for (int t = 0; t < 5; t++) {
        srcA[t] = (const int*)d_in[I[17 + 2 * t]];
        dstA[t] = (const int*)d_in[I[18 + 2 * t]];
        E[t] = in_sizes[I[17 + 2 * t]];
    }

    __nv_bfloat16 *Xhi, *Xlo, *Wthi, *Wtlo;
    float *xlb, *xrb, *ab, *aj, *af, *sbuf, *den;
    unsigned* menc;
    cudaGetSymbolAddress((void**)&Xhi, g_Xhi);
    cudaGetSymbolAddress((void**)&Xlo, g_Xlo);
    cudaGetSymbolAddress((void**)&Wthi, g_Wthi);
    cudaGetSymbolAddress((void**)&Wtlo, g_Wtlo);
    cudaGetSymbolAddress((void**)&xlb, g_xl);
    cudaGetSymbolAddress((void**)&xrb, g_xr);
    cudaGetSymbolAddress((void**)&ab, g_ab);
    cudaGetSymbolAddress((void**)&aj, g_aj);
    cudaGetSymbolAddress((void**)&af, g_af);
    cudaGetSymbolAddress((void**)&sbuf, g_sbuf);
    cudaGetSymbolAddress((void**)&den, g_den);
    cudaGetSymbolAddress((void**)&menc, g_menc);

    const int Nn[3] = {NBASE, NJOINT, NFOOT};
    const int Kin[3] = {6, 2, 4};
    const size_t XOFF[3] = {0, (size_t)NBASE * 128, (size_t)(NBASE + NJOINT) * 128};
    const int sT[5] = {0, 1, 1, 1, 2};
    const int dT[5] = {1, 0, 1, 2, 1};

    const int SMEM = 6 * SA * 2;  // 208896 bytes
    cudaFuncSetAttribute(gemm_multi_k, cudaFuncAttributeMaxDynamicSharedMemorySize, SMEM);

    // weight prep (transpose + bf16 split)
    wprep_k<<<(40 * 16384 + 255) / 256, 256>>>(Wl, Wr, Wthi, Wtlo);

    // encoders -> Xhi/Xlo
    for (int t = 0; t < 3; t++)
        encode_split_k<<<(Nn[t] * HDIM + 255) / 256, 256>>>(
            x_in[t], Wenc[t], benc[t], Xhi + XOFF[t], Xlo + XOFF[t], Nn[t], Kin[t]);

    float* aggP[3] = {ab, aj, af};

    for (int l = 0; l < 4; l++) {
        bool last = (l == 3);

        // --- agg init with summed conv biases ---
        if (!last) {
            fill_agg_k<<<(NJOINT * HDIM + 255) / 256, 256>>>(
                aj, cbias + (size_t)(l * 5 + 0) * 128, cbias + (size_t)(l * 5 + 2) * 128,
                cbias + (size_t)(l * 5 + 4) * 128, NJOINT * HDIM);
            fill_agg_k<<<(NBASE * HDIM + 255) / 256, 256>>>(
                ab, cbias + (size_t)(l * 5 + 1) * 128, nullptr, nullptr, NBASE * HDIM);
        }
        fill_agg_k<<<(NFOOT * HDIM + 255) / 256, 256>>>(
            af, cbias + (size_t)(l * 5 + 3) * 128, nullptr, nullptr, NFOOT * HDIM);

        // --- per edge type: GEMMs then edge stage ---
        int eiBeg = last ? 3 : 0, eiEnd = last ? 4 : 5;
        for (int ei = eiBeg; ei < eiEnd; ei++) {
            int st = sT[ei], dt = dT[ei];
            int Ns = Nn[st], Nd = Nn[dt], Ee = E[ei];
            int po = l * 5 + ei;

            GemmSet setL = {Wthi + (size_t)po * 16384, Wtlo + (size_t)po * 16384,
                            bl + (size_t)po * 128, xlb};
            GemmSet setR = {Wthi + (size_t)(20 + po) * 16384, Wtlo + (size_t)(20 + po) * 16384,
                            br + (size_t)po * 128, xrb};

            if (st == dt) {
                GemmArgs g; g.s[0] = setL; g.s[1] = setR;
                gemm_multi_k<<<(Ns + 127) / 128, 256, SMEM>>>(Xhi + XOFF[st], Xlo + XOFF[st], Ns, g, 2);
            } else {
                GemmArgs gL; gL.s[0] = setL; gL.s[1] = setL;
                gemm_multi_k<<<(Ns + 127) / 128, 256, SMEM>>>(Xhi + XOFF[st], Xlo + XOFF[st], Ns, gL, 1);
                GemmArgs gR; gR.s[0] = setR; gR.s[1] = setR;
                gemm_multi_k<<<(Nd + 127) / 128, 256, SMEM>>>(Xhi + XOFF[dt], Xlo + XOFF[dt], Nd, gR, 1);
            }

            const float* att_ = att + (size_t)po * 128;
            fill_u32_k<<<(Nd + 255) / 256, 256>>>(menc, 0x007FFFFFu, Nd);
            cudaMemsetAsync(den, 0, (size_t)Nd * 4);
            edge_logits_k<<<(Ee + 7) / 8, 256>>>(xlb, xrb, srcA[ei], dstA[ei], att_, sbuf, menc, Ee);
            edge_den_k<<<(Ee + 255) / 256, 256>>>(sbuf, dstA[ei], menc, den, Ee);
            edge_scatter_k<<<(Ee + 7) / 8, 256>>>(xlb, sbuf, srcA[ei], dstA[ei], menc, den, aggP[dt], Ee);
        }

        // --- layer transition ---
        if (!last) {
            for (int t = 0; t < 3; t++)
                relu_split_k<<<(Nn[t] * HDIM + 255) / 256, 256>>>(
                    aggP[t], Xhi + XOFF[t], Xlo + XOFF[t], Nn[t] * HDIM);
        }
    }

    decode_k<<<(NFOOT + 7) / 8, 256>>>(af, Wdec, bdec, (float*)d_out, NFOOT);
}

// round 4
// speedup vs baseline: 2.4441x; 1.0844x over previous
#include <cuda_runtime.h>
#include <cuda_bf16.h>
#include <math.h>

#define NBASE 40000
#define NJOINT 480000
#define NFOOT 160000
#define HDIM 128
#define NEG_SLOPE 0.2f

// ---------------- scratch (device globals; total ~1.53 GB, linker-safe) ----------------
__device__ float g_bufA[(size_t)680000 * 128];   // x / agg ping-pong (base@0, joint@40000, foot@520000)
__device__ float g_bufB[(size_t)680000 * 128];
__device__ float g_pool[(size_t)1600000 * 128];  // phase-local xl/xr pool
__device__ __nv_bfloat16 g_Wthi[40 * 16384];     // 20 Wl^T then 20 Wr^T, [n][k], bf16 hi
__device__ __nv_bfloat16 g_Wtlo[40 * 16384];
// CSR: per-type offset segments (Nd+1 each) and sorted src lists
__device__ int g_off[1640008];
__device__ int g_csr[960000];
__device__ int g_deg[480000];
__device__ int g_cur[480000];
__device__ int g_part[1032];

// ---------------- small utility kernels ----------------
static __device__ __forceinline__ void bf16split(float v, __nv_bfloat16& h, __nv_bfloat16& l) {
    h = __float2bfloat16(v);
    l = __float2bfloat16(v - __bfloat162float(h));
}

// weight prep: transpose to [n][k], split to bf16 hi/lo
__global__ void wprep_k(const float* __restrict__ Wl, const float* __restrict__ Wr,
                        __nv_bfloat16* __restrict__ hi, __nv_bfloat16* __restrict__ lo) {
    int idx = blockIdx.x * 256 + threadIdx.x;
    if (idx >= 40 * 16384) return;
    int m = idx >> 14, e = idx & 16383;
    int n = e >> 7, k = e & 127;
    const float* src = (m < 20) ? (Wl + (size_t)m * 16384) : (Wr + (size_t)(m - 20) * 16384);
    float v = src[k * 128 + n];
    __nv_bfloat16 h, l;
    bf16split(v, h, l);
    hi[idx] = h; lo[idx] = l;
}

// encoder: y = relu(x @ W + b)  (fp32 out)
__global__ void encode_k(const float* __restrict__ x, const float* __restrict__ W,
                         const float* __restrict__ b, float* __restrict__ y, int N, int K) {
    int idx = blockIdx.x * blockDim.x + threadIdx.x;
    if (idx >= N * HDIM) return;
    int n = idx >> 7, h = idx & 127;
    float acc = b[h];
    for (int k = 0; k < K; k++) acc += x[n * K + k] * W[k * HDIM + h];
    y[idx] = fmaxf(acc, 0.f);
}

// ---------------- CSR build ----------------
__global__ void hist_k(const int* __restrict__ dst, int* __restrict__ deg, int E) {
    int i = blockIdx.x * blockDim.x + threadIdx.x;
    if (i < E) atomicAdd(deg + dst[i], 1);
}
__global__ void scan1_k(const int* __restrict__ deg, int* __restrict__ off,
                        int* __restrict__ part, int n) {
    __shared__ int sh[1024];
    int i = blockIdx.x * 1024 + threadIdx.x;
    int v = (i < n) ? deg[i] : 0;
    sh[threadIdx.x] = v;
    __syncthreads();
#pragma unroll
    for (int o = 1; o < 1024; o <<= 1) {
        int t = (threadIdx.x >= o) ? sh[threadIdx.x - o] : 0;
        __syncthreads();
        sh[threadIdx.x] += t;
        __syncthreads();
    }
    int incl = sh[threadIdx.x];
    if (i < n) off[i] = incl - v;
    if (threadIdx.x == 1023) part[blockIdx.x] = incl;
}
__global__ void scan2_k(int* part, int nb) {
    __shared__ int sh[1024];
    int v = (threadIdx.x < nb) ? part[threadIdx.x] : 0;
    sh[threadIdx.x] = v;
    __syncthreads();
#pragma unroll
    for (int o = 1; o < 1024; o <<= 1) {
        int t = (threadIdx.x >= o) ? sh[threadIdx.x - o] : 0;
        __syncthreads();
        sh[threadIdx.x] += t;
        __syncthreads();
    }
    int excl = sh[threadIdx.x] - v;
    if (threadIdx.x <= nb) part[threadIdx.x] = excl;   // part[nb] = total
}
__global__ void scan3_k(int* __restrict__ off, const int* __restrict__ part, int n, int nb) {
    int i = blockIdx.x * blockDim.x + threadIdx.x;
    if (i < n) off[i] += part[i >> 10];
    if (i == 0) off[n] = part[nb];
}
__global__ void fill_k(const int* __restrict__ src, const int* __restrict__ dst,
                       int* __restrict__ cur, int* __restrict__ csr, int E) {
    int i = blockIdx.x * blockDim.x + threadIdx.x;
    if (i >= E) return;
    int p = atomicAdd(cur + dst[i], 1);
    csr[p] = src[i];
}

// ---------------- tensor-core multi-set GEMM ----------------
// Y[set] = relu(X_fp32)[M,128] @ W[set][128,128] + b[set]; bf16 3-term split, fp32 accum.
struct GemmSet {
    const __nv_bfloat16* Bhi;
    const __nv_bfloat16* Blo;
    const float* bias;
    float* out;
};
struct GemmArgs { GemmSet s[3]; };

#define SA 17408  // 128*136 bf16 elems per smem matrix (8-halfword pad)

#define LDSM4(R, addr) asm volatile( \
    "ldmatrix.sync.aligned.m8n8.x4.shared.b16 {%0,%1,%2,%3}, [%4];" \
    : "=r"((R)[0]), "=r"((R)[1]), "=r"((R)[2]), "=r"((R)[3]) : "r"(addr))

#define MMA16816(C, A, b0, b1) asm volatile( \
    "mma.sync.aligned.m16n8k16.row.col.f32.bf16.bf16.f32 " \
    "{%0,%1,%2,%3},{%4,%5,%6,%7},{%8,%9},{%0,%1,%2,%3};" \
    : "+f"((C)[0]), "+f"((C)[1]), "+f"((C)[2]), "+f"((C)[3]) \
    : "r"((A)[0]), "r"((A)[1]), "r"((A)[2]), "r"((A)[3]), "r"(b0), "r"(b1))

static __device__ __forceinline__ void cpasync16(unsigned dst, const void* src, int sz) {
    asm volatile("cp.async.cg.shared.global [%0], [%1], 16, %2;" :: "r"(dst), "l"(src), "r"(sz));
}

__global__ void __launch_bounds__(256) gemm_multi_k(
    const float* __restrict__ A_g, int M, GemmArgs args, int nsets) {
    extern __shared__ __nv_bfloat16 smem[];
    const int tid = threadIdx.x;
    const long row0 = (long)blockIdx.x * 128;

    unsigned sAhi = (unsigned)__cvta_generic_to_shared(smem);          // [0, SA)
    unsigned sAlo = sAhi + SA * 2;                                     // [SA, 2SA)
    unsigned sB   = sAhi + 2 * SA * 2;                                 // B slots: 4*SA
    float* stage = (float*)(smem + 2 * SA);                            // fp32 A staging overlays B area

    // 1) async load fp32 A tile into staging (zero-fill OOB rows)
#pragma unroll
    for (int i = 0; i < 16; i++) {
        int chunk = tid + i * 256;          // 4096 chunks of 16B
        int row = chunk >> 5;
        int c4 = (chunk & 31) * 4;          // float index within row
        long grow = row0 + row;
        int ok = grow < M;
        size_t off = ok ? ((size_t)grow * 128 + c4) : 0;
        unsigned d = (unsigned)__cvta_generic_to_shared(stage + row * 128 + c4);
        cpasync16(d, A_g + off, ok ? 16 : 0);
    }
    asm volatile("cp.async.commit_group;");
    asm volatile("cp.async.wait_group 0;");
    __syncthreads();

    // 2) relu + bf16 hi/lo split into padded smem
#pragma unroll
    for (int i = 0; i < 64; i++) {
        int idx = tid + i * 256;            // 16384 elems
        int row = idx >> 7, col = idx & 127;
        float v = fmaxf(stage[idx], 0.f);
        __nv_bfloat16 h, l;
        bf16split(v, h, l);
        smem[row * 136 + col] = h;
        smem[SA + row * 136 + col] = l;
    }
    __syncthreads();

    // 3) load B set 0 into slot 0
#pragma unroll
    for (int i = 0; i < 8; i++) {
        int chunk = tid + i * 256;          // 2048 chunks
        int row = chunk >> 4;
        int col = (chunk & 15) * 8;
        size_t off = (size_t)row * 128 + col;
        unsigned d = sB + (unsigned)(row * 136 + col) * 2;
        cpasync16(d, args.s[0].Bhi + off, 16);
        cpasync16(d + SA * 2, args.s[0].Blo + off, 16);
    }
    asm volatile("cp.async.commit_group;");

    int warp = tid >> 5, lane = tid & 31;
    int m0 = (warp >> 2) * 64;
    int n0 = (warp & 3) * 32;
    int frow = lane & 15;
    int fcolo = (lane >> 4) * 8;

    for (int s = 0; s < nsets; s++) {
        if (s + 1 < nsets) {
            unsigned bb = sB + (unsigned)(((s + 1) & 1) * 2 * SA) * 2;
#pragma unroll
            for (int i = 0; i < 8; i++) {
                int chunk = tid + i * 256;
                int row = chunk >> 4;
                int col = (chunk & 15) * 8;
                size_t off = (size_t)row * 128 + col;
                unsigned d = bb + (unsigned)(row * 136 + col) * 2;
                cpasync16(d, args.s[s + 1].Bhi + off, 16);
                cpasync16(d + SA * 2, args.s[s + 1].Blo + off, 16);
            }
            asm volatile("cp.async.commit_group;");
            asm volatile("cp.async.wait_group 1;");
        } else {
            asm volatile("cp.async.wait_group 0;");
        }
        __syncthreads();

        unsigned bBase = sB + (unsigned)((s & 1) * 2 * SA) * 2;
        float acc[4][4][4];
#pragma unroll
        for (int a = 0; a < 4; a++)
#pragma unroll
            for (int c = 0; c < 4; c++)
#pragma unroll
                for (int r = 0; r < 4; r++) acc[a][c][r] = 0.f;

        for (int ks = 0; ks < 8; ks++) {
            int acol = ks * 16 + fcolo;
            unsigned ah[4][4], al[4][4];
#pragma unroll
            for (int mt = 0; mt < 4; mt++) {
                unsigned ad = sAhi + (unsigned)((m0 + mt * 16 + frow) * 136 + acol) * 2;
                LDSM4(ah[mt], ad);
                LDSM4(al[mt], ad + SA * 2);
            }
            unsigned bh[2][4], blx[2][4];
#pragma unroll
            for (int p = 0; p < 2; p++) {
                unsigned bd = bBase + (unsigned)((n0 + p * 16 + frow) * 136 + acol) * 2;
                LDSM4(bh[p], bd);
                LDSM4(blx[p], bd + SA * 2);
            }
#pragma unroll
            for (int mt = 0; mt < 4; mt++)
#pragma unroll
                for (int nt = 0; nt < 4; nt++) {
                    int p = nt >> 1, o = nt & 1;
                    MMA16816(acc[mt][nt], ah[mt], bh[p][o], bh[p][2 + o]);
                    MMA16816(acc[mt][nt], ah[mt], blx[p][o], blx[p][2 + o]);
                    MMA16816(acc[mt][nt], al[mt], bh[p][o], bh[p][2 + o]);
                }
        }

        const float* bias = args.s[s].bias;
        float* out = args.s[s].out;
        int crow = lane >> 2, ccol = (lane & 3) * 2;
#pragma unroll
        for (int nt = 0; nt < 4; nt++) {
            int col = n0 + nt * 8 + ccol;
            float b0v = bias[col], b1v = bias[col + 1];
#pragma unroll
            for (int mt = 0; mt < 4; mt++) {
                long r = row0 + m0 + mt * 16 + crow;
                if (r < M)
                    *(float2*)(out + (size_t)r * 128 + col) =
                        make_float2(acc[mt][nt][0] + b0v, acc[mt][nt][1] + b1v);
                if (r + 8 < M)
                    *(float2*)(out + (size_t)(r + 8) * 128 + col) =
                        make_float2(acc[mt][nt][2] + b0v, acc[mt][nt][3] + b1v);
            }
        }
        __syncthreads();
    }
}

// ---------------- fused edge kernel: warp-per-dst, online softmax ----------------
__global__ void edge_csr_k(const float* __restrict__ xl, const float* __restrict__ xr,
                           const int* __restrict__ csr, const int* __restrict__ off,
                           const float* __restrict__ att,
                           const float* __restrict__ b0, const float* __restrict__ b1,
                           const float* __restrict__ b2,
                           float* __restrict__ agg, int addMode, int Nd) {
    int d = blockIdx.x * 8 + (threadIdx.x >> 5);
    if (d >= Nd) return;
    int lane = threadIdx.x & 31;
    float4 xr4 = ((const float4*)(xr + (size_t)d * 128))[lane];
    float4 at = ((const float4*)att)[lane];
    int s0 = off[d], s1 = off[d + 1];
    float m = -INFINITY, den = 0.f;
    float a0 = 0.f, a1 = 0.f, a2 = 0.f, a3 = 0.f;
    for (int e = s0; e < s1; e++) {
        int si = csr[e];
        float4 xv = ((const float4*)(xl + (size_t)si * 128))[lane];
        float t0 = xv.x + xr4.x, t1 = xv.y + xr4.y, t2 = xv.z + xr4.z, t3 = xv.w + xr4.w;
        t0 = t0 > 0.f ? t0 : NEG_SLOPE * t0;
        t1 = t1 > 0.f ? t1 : NEG_SLOPE * t1;
        t2 = t2 > 0.f ? t2 : NEG_SLOPE * t2;
        t3 = t3 > 0.f ? t3 : NEG_SLOPE * t3;
        float p = t0 * at.x + t1 * at.y + t2 * at.z + t3 * at.w;
#pragma unroll
        for (int o = 16; o; o >>= 1) p += __shfl_xor_sync(0xffffffffu, p, o);
        float mn = fmaxf(m, p);
        float corr = __expf(m - mn);      // 0 on first edge (m = -inf)
        float w = __expf(p - mn);
        den = den * corr + w;
        a0 = a0 * corr + w * xv.x;
        a1 = a1 * corr + w * xv.y;
        a2 = a2 * corr + w * xv.z;
        a3 = a3 * corr + w * xv.w;
        m = mn;
    }
    float inv = (s1 > s0) ? 1.f / den : 0.f;
    float4 r = make_float4(a0 * inv, a1 * inv, a2 * inv, a3 * inv);
    float* ap = agg + (size_t)d * 128 + lane * 4;
    if (addMode) {
        float4 old = *(const float4*)ap;
        r.x += old.x; r.y += old.y; r.z += old.z; r.w += old.w;
    } else {
        float4 bb = ((const float4*)b0)[lane];
        r.x += bb.x; r.y += bb.y; r.z += bb.z; r.w += bb.w;
        if (b1) {
            float4 c = ((const float4*)b1)[lane];
            r.x += c.x; r.y += c.y; r.z += c.z; r.w += c.w;
        }
        if (b2) {
            float4 c = ((const float4*)b2)[lane];
            r.x += c.x; r.y += c.y; r.z += c.z; r.w += c.w;
        }
    }
    *(float4*)ap = r;
}

// ---------------- decoder with fused relu ----------------
__global__ void decode_k(const float* __restrict__ agg, const float* __restrict__ W,
                         const float* __restrict__ b, float* __restrict__ out, int N) {
    int f = blockIdx.x * 8 + (threadIdx.x >> 5);
    if (f >= N) return;
    int lane = threadIdx.x & 31;
    float4 v = ((const float4*)(agg + (size_t)f * 128))[lane];
    v.x = fmaxf(v.x, 0.f); v.y = fmaxf(v.y, 0.f); v.z = fmaxf(v.z, 0.f); v.w = fmaxf(v.w, 0.f);
    int h = lane * 4;
    float s0 = v.x * W[(h + 0) * 3 + 0] + v.y * W[(h + 1) * 3 + 0] + v.z * W[(h + 2) * 3 + 0] + v.w * W[(h + 3) * 3 + 0];
    float s1 = v.x * W[(h + 0) * 3 + 1] + v.y * W[(h + 1) * 3 + 1] + v.z * W[(h + 2) * 3 + 1] + v.w * W[(h + 3) * 3 + 1];
    float s2 = v.x * W[(h + 0) * 3 + 2] + v.y * W[(h + 1) * 3 + 2] + v.z * W[(h + 2) * 3 + 2] + v.w * W[(h + 3) * 3 + 2];
#pragma unroll
    for (int o = 16; o; o >>= 1) {
        s0 += __shfl_xor_sync(0xffffffffu, s0, o);
        s1 += __shfl_xor_sync(0xffffffffu, s1, o);
        s2 += __shfl_xor_sync(0xffffffffu, s2, o);
    }
    if (lane == 0) {
        out[f * 3 + 0] = s0 + b[0];
        out[f * 3 + 1] = s1 + b[1];
        out[f * 3 + 2] = s2 + b[2];
    }
}

// ---------------- host orchestration ----------------
extern "C" void kernel_launch(void* const* d_in, const int* in_sizes, int n_in,
                              void* d_out, int out_size) {
    int I[27];
    if (in_sizes[1] == 768) {
        const int m[27] = {0, 3, 6, 1, 2, 4, 5, 7, 8,
                           19, 20, 21, 22, 23, 24, 25, 26,
                           9, 10, 11, 12, 13, 14, 15, 16, 17, 18};
        for (int i = 0; i < 27; i++) I[i] = m[i];
    } else {
        for (int i = 0; i < 27; i++) I[i] = i;
    }

    const float* x_in[3] = {(const float*)d_in[I[0]], (const float*)d_in[I[1]], (const float*)d_in[I[2]]};
    const float* Wenc[3] = {(const float*)d_in[I[3]], (const float*)d_in[I[5]], (const float*)d_in[I[7]]};
    const float* benc[3] = {(const float*)d_in[I[4]], (const float*)d_in[I[6]], (const float*)d_in[I[8]]};
    const float* Wl = (const float*)d_in[I[9]];
    const float* bl = (const float*)d_in[I[10]];
    const float* Wr = (const float*)d_in[I[11]];
    const float* br = (const float*)d_in[I[12]];
    const float* att = (const float*)d_in[I[13]];
    const float* cb = (const float*)d_in[I[14]];
    const float* Wdec = (const float*)d_in[I[15]];
    const float* bdec = (const float*)d_in[I[16]];
    const int *srcA[5], *dstA[5];
    int E[5];
    for (int t = 0; t < 5; t++) {
        srcA[t] = (const int*)d_in[I[17 + 2 * t]];
        dstA[t] = (const int*)d_in[I[18 + 2 * t]];
        E[t] = in_sizes[I[17 + 2 * t]];
    }

    float *bufA, *bufB, *pool;
    __nv_bfloat16 *Wthi, *Wtlo;
    int *off, *csr, *deg, *cur, *part;
    cudaGetSymbolAddress((void**)&bufA, g_bufA);
    cudaGetSymbolAddress((void**)&bufB, g_bufB);
    cudaGetSymbolAddress((void**)&pool, g_pool);
    cudaGetSymbolAddress((void**)&Wthi, g_Wthi);
    cudaGetSymbolAddress((void**)&Wtlo, g_Wtlo);
    cudaGetSymbolAddress((void**)&off, g_off);
    cudaGetSymbolAddress((void**)&csr, g_csr);
    cudaGetSymbolAddress((void**)&deg, g_deg);
    cudaGetSymbolAddress((void**)&cur, g_cur);
    cudaGetSymbolAddress((void**)&part, g_part);

    const int dstN[5] = {NJOINT, NBASE, NJOINT, NFOOT, NJOINT};
    const int offStart[5] = {0, 480001, 520002, 1000003, 1160004};
    const int csrStart[5] = {0, 160000, 320000, 640000, 800000};

    const int SMEM = 6 * SA * 2;  // 208896 B
    cudaFuncSetAttribute(gemm_multi_k, cudaFuncAttributeMaxDynamicSharedMemorySize, SMEM);

    // ---- once-per-call prep ----
    wprep_k<<<(40 * 16384 + 255) / 256, 256>>>(Wl, Wr, Wthi, Wtlo);
    const int Nn[3] = {NBASE, NJOINT, NFOOT};
    const int Kin[3] = {6, 2, 4};
    const size_t XOFF[3] = {0, (size_t)NBASE * 128, (size_t)(NBASE + NJOINT) * 128};
    for (int t = 0; t < 3; t++)
        encode_k<<<(Nn[t] * HDIM + 255) / 256, 256>>>(
            x_in[t], Wenc[t], benc[t], bufA + XOFF[t], Nn[t], Kin[t]);

    // CSR build (edges are layer-invariant)
    for (int t = 0; t < 5; t++) {
        int Nd = dstN[t], Ee = E[t];
        int nb = (Nd + 1023) / 1024;
        int* offT = off + offStart[t];
        cudaMemsetAsync(deg, 0, (size_t)Nd * 4);
        hist_k<<<(Ee + 255) / 256, 256>>>(dstA[t], deg, Ee);
        scan1_k<<<nb, 1024>>>(deg, offT, part, Nd);
        scan2_k<<<1, 1024>>>(part, nb);
        scan3_k<<<(Nd + 255) / 256, 256>>>(offT, part, Nd, nb);
        cudaMemcpyAsync(cur, offT, (size_t)Nd * 4, cudaMemcpyDeviceToDevice);
        fill_k<<<(Ee + 255) / 256, 256>>>(srcA[t], dstA[t], cur, csr + csrStart[t], Ee);
    }

    // pool row offsets
    const size_t A_XL_BJ = 0, A_XR_BJ = 40000, A_XL_JB = 520000, A_XR_JB = 1000000;
    const size_t BC_XL_JJ = 0, BC_XR_JJ = 480000, BC_XL_JF = 960000, BC_XR_JF = 1440000;
    const size_t D_XL_FJ = 0, D_XR_FJ = 160000;

    float* x = bufA;
    float* agg = bufB;

    auto WT = [&](int m) { return Wthi + (size_t)m * 16384; };
    auto WTl = [&](int m) { return Wtlo + (size_t)m * 16384; };

    for (int l = 0; l < 4; l++) {
        bool last = (l == 3);
        int po[5];
        for (int e = 0; e < 5; e++) po[e] = l * 5 + e;
        const float* xj = x + XOFF[1];
        const float* xb = x + XOFF[0];
        const float* xf = x + XOFF[2];
        float* agJ = agg + XOFF[1];
        float* agB = agg + XOFF[0];
        float* agF = agg + XOFF[2];

        if (!last) {
            // ---- Phase A: bj + jb ----
            GemmArgs gj;
            gj.s[0] = {WT(po[1]), WTl(po[1]), bl + (size_t)po[1] * 128, pool + A_XL_JB * 128};       // xl_jb
            gj.s[1] = {WT(20 + po[0]), WTl(20 + po[0]), br + (size_t)po[0] * 128, pool + A_XR_BJ * 128}; // xr_bj
            gemm_multi_k<<<(NJOINT + 127) / 128, 256, SMEM>>>(xj, NJOINT, gj, 2);
            GemmArgs gb;
            gb.s[0] = {WT(po[0]), WTl(po[0]), bl + (size_t)po[0] * 128, pool + A_XL_BJ * 128};       // xl_bj
            gb.s[1] = {WT(20 + po[1]), WTl(20 + po[1]), br + (size_t)po[1] * 128, pool + A_XR_JB * 128}; // xr_jb
            gemm_multi_k<<<(NBASE + 127) / 128, 256, SMEM>>>(xb, NBASE, gb, 2);

            edge_csr_k<<<(NJOINT + 7) / 8, 256>>>(pool + A_XL_BJ * 128, pool + A_XR_BJ * 128,
                csr + csrStart[0], off + offStart[0], att + (size_t)po[0] * 128,
                cb + (size_t)po[0] * 128, cb + (size_t)po[2] * 128, cb + (size_t)po[4] * 128,
                agJ, 0, NJOINT);
            edge_csr_k<<<(NBASE + 7) / 8, 256>>>(pool + A_XL_JB * 128, pool + A_XR_JB * 128,
                csr + csrStart[1], off + offStart[1], att + (size_t)po[1] * 128,
                cb + (size_t)po[1] * 128, nullptr, nullptr, agB, 0, NBASE);

            // ---- Phase BC: jj + jf ----
            GemmArgs g2;
            g2.s[0] = {WT(po[2]), WTl(po[2]), bl + (size_t)po[2] * 128, pool + BC_XL_JJ * 128};
            g2.s[1] = {WT(20 + po[2]), WTl(20 + po[2]), br + (size_t)po[2] * 128, pool + BC_XR_JJ * 128};
            g2.s[2] = {WT(po[3]), WTl(po[3]), bl + (size_t)po[3] * 128, pool + BC_XL_JF * 128};
            gemm_multi_k<<<(NJOINT + 127) / 128, 256, SMEM>>>(xj, NJOINT, g2, 3);
            GemmArgs g3;
            g3.s[0] = {WT(20 + po[3]), WTl(20 + po[3]), br + (size_t)po[3] * 128, pool + BC_XR_JF * 128};
            gemm_multi_k<<<(NFOOT + 127) / 128, 256, SMEM>>>(xf, NFOOT, g3, 1);

            edge_csr_k<<<(NJOINT + 7) / 8, 256>>>(pool + BC_XL_JJ * 128, pool + BC_XR_JJ * 128,
                csr + csrStart[2], off + offStart[2], att + (size_t)po[2] * 128,
                nullptr, nullptr, nullptr, agJ, 1, NJOINT);
            edge_csr_k<<<(NFOOT + 7) / 8, 256>>>(pool + BC_XL_JF * 128, pool + BC_XR_JF * 128,
                csr + csrStart[3], off + offStart[3], att + (size_t)po[3] * 128,
                cb + (size_t)po[3] * 128, nullptr, nullptr, agF, 0, NFOOT);

            // ---- Phase D: fj ----
            GemmArgs g4;
            g4.s[0] = {WT(po[4]), WTl(po[4]), bl + (size_t)po[4] * 128, pool + D_XL_FJ * 128};
            gemm_multi_k<<<(NFOOT + 127) / 128, 256, SMEM>>>(xf, NFOOT, g4, 1);
            GemmArgs g5;
            g5.s[0] = {WT(20 + po[4]), WTl(20 + po[4]), br + (size_t)po[4] * 128, pool + D_XR_FJ * 128};
            gemm_multi_k<<<(NJOINT + 127) / 128, 256, SMEM>>>(xj, NJOINT, g5, 1);

            edge_csr_k<<<(NJOINT + 7) / 8, 256>>>(pool + D_XL_FJ * 128, pool + D_XR_FJ * 128,
                csr + csrStart[4], off + offStart[4], att + (size_t)po[4] * 128,
                nullptr, nullptr, nullptr, agJ, 1, NJOINT);

            // swap ping-pong
            float* tmp = x; x = agg; agg = tmp;
        } else {
            // ---- last layer: only jf path matters ----
            GemmArgs g1;
            g1.s[0] = {WT(po[3]), WTl(po[3]), bl + (size_t)po[3] * 128, pool};
            gemm_multi_k<<<(NJOINT + 127) / 128, 256, SMEM>>>(xj, NJOINT, g1, 1);
            GemmArgs g2;
            g2.s[0] = {WT(20 + po[3]), WTl(20 + po[3]), br + (size_t)po[3] * 128, pool + (size_t)480000 * 128};
            gemm_multi_k<<<(NFOOT + 127) / 128, 256, SMEM>>>(xf, NFOOT, g2, 1);
            edge_csr_k<<<(NFOOT + 7) / 8, 256>>>(pool, pool + (size_t)480000 * 128,
                csr + csrStart[3], off + offStart[3], att + (size_t)po[3] * 128,
                cb + (size_t)po[3] * 128, nullptr, nullptr, agF, 0, NFOOT);
        }
    }

    decode_k<<<(NFOOT + 7) / 8, 256>>>(agg + XOFF[2], Wdec, bdec, (float*)d_out, NFOOT);
}

// round 6
// speedup vs baseline: 3.7018x; 1.5146x over previous
#include <cuda_runtime.h>
#include <cuda_bf16.h>
#include <math.h>

#define NBASE 40000
#define NJOINT 480000
#define NFOOT 160000
#define HDIM 128
#define NEG_SLOPE 0.2f

// ---------------- scratch (device globals; total ~1.66 GB, linker-safe) ----------------
__device__ float g_bufA[(size_t)680000 * 128];   // x / agg ping-pong
__device__ float g_bufB[(size_t)680000 * 128];
__device__ float g_pool[(size_t)1680000 * 128];  // compact xl/xr rows, all 10 roles live
__device__ __nv_bfloat16 g_Wthi[40 * 16384];     // 20 Wl^T then 20 Wr^T, [n][k], bf16 hi
__device__ __nv_bfloat16 g_Wtlo[40 * 16384];
__device__ int g_off[1640008];                   // CSR offsets per edge type
__device__ int g_csr[960000];                    // CSR src (compact indices)
__device__ int g_deg[480000];
__device__ int g_cur[480000];
__device__ int g_scan[480001];
__device__ int g_rank[10 * 480000];              // per-role node -> compact idx (-1 if unused)
__device__ int g_list[10 * 480000];              // per-role compact idx -> node
__device__ int g_cnt[16];
__device__ int g_part[1032];

// ---------------- small utility kernels ----------------
static __device__ __forceinline__ void bf16split(float v, __nv_bfloat16& h, __nv_bfloat16& l) {
    h = __float2bfloat16(v);
    l = __float2bfloat16(v - __bfloat162float(h));
}

__global__ void wprep_k(const float* __restrict__ Wl, const float* __restrict__ Wr,
                        __nv_bfloat16* __restrict__ hi, __nv_bfloat16* __restrict__ lo) {
    int idx = blockIdx.x * 256 + threadIdx.x;
    if (idx >= 40 * 16384) return;
    int m = idx >> 14, e = idx & 16383;
    int n = e >> 7, k = e & 127;
    const float* src = (m < 20) ? (Wl + (size_t)m * 16384) : (Wr + (size_t)(m - 20) * 16384);
    float v = src[k * 128 + n];
    __nv_bfloat16 h, l;
    bf16split(v, h, l);
    hi[idx] = h; lo[idx] = l;
}

__global__ void encode_k(const float* __restrict__ x, const float* __restrict__ W,
                         const float* __restrict__ b, float* __restrict__ y, int N, int K) {
    int idx = blockIdx.x * blockDim.x + threadIdx.x;
    if (idx >= N * HDIM) return;
    int n = idx >> 7, h = idx & 127;
    float acc = b[h];
    for (int k = 0; k < K; k++) acc += x[n * K + k] * W[k * HDIM + h];
    y[idx] = fmaxf(acc, 0.f);
}

// ---------------- scans / compaction / CSR ----------------
__global__ void hist_k(const int* __restrict__ dst, int* __restrict__ deg, int E) {
    int i = blockIdx.x * blockDim.x + threadIdx.x;
    if (i < E) atomicAdd(deg + dst[i], 1);
}
__global__ void mark_k(const int* __restrict__ idx, int* __restrict__ mark, int E) {
    int i = blockIdx.x * blockDim.x + threadIdx.x;
    if (i < E) mark[idx[i]] = 1;
}
__global__ void scan1_k(const int* __restrict__ v_in, int* __restrict__ out,
                        int* __restrict__ part, int n) {
    __shared__ int sh[1024];
    int i = blockIdx.x * 1024 + threadIdx.x;
    int v = (i < n) ? v_in[i] : 0;
    sh[threadIdx.x] = v;
    __syncthreads();
#pragma unroll
    for (int o = 1; o < 1024; o <<= 1) {
        int t = (threadIdx.x >= o) ? sh[threadIdx.x - o] : 0;
        __syncthreads();
        sh[threadIdx.x] += t;
        __syncthreads();
    }
    int incl = sh[threadIdx.x];
    if (i < n) out[i] = incl - v;
    if (threadIdx.x == 1023) part[blockIdx.x] = incl;
}
__global__ void scan2_k(int* part, int nb) {
    __shared__ int sh[1024];
    int v = (threadIdx.x < nb) ? part[threadIdx.x] : 0;
    sh[threadIdx.x] = v;
    __syncthreads();
#pragma unroll
    for (int o = 1; o < 1024; o <<= 1) {
        int t = (threadIdx.x >= o) ? sh[threadIdx.x - o] : 0;
        __syncthreads();
        sh[threadIdx.x] += t;
        __syncthreads();
    }
    int excl = sh[threadIdx.x] - v;
    if (threadIdx.x <= nb) part[threadIdx.x] = excl;   // part[nb] = total
}
__global__ void scan3_k(int* __restrict__ out, const int* __restrict__ part, int n, int nb,
                        int* __restrict__ cntOut) {
    int i = blockIdx.x * blockDim.x + threadIdx.x;
    if (i < n) out[i] += part[i >> 10];
    if (i == 0) {
        out[n] = part[nb];
        if (cntOut) *cntOut = part[nb];
    }
}
__global__ void compact_k(int* __restrict__ rank, const int* __restrict__ pref,
                          int* __restrict__ list, int N) {
    int i = blockIdx.x * blockDim.x + threadIdx.x;
    if (i >= N) return;
    int m = rank[i];
    int pos = pref[i];
    if (m) { list[pos] = i; rank[i] = pos; }
    else rank[i] = -1;
}
__global__ void fill_k(const int* __restrict__ src, const int* __restrict__ dst,
                       int* __restrict__ cur, int* __restrict__ csr,
                       const int* __restrict__ rankS, int E) {
    int i = blockIdx.x * blockDim.x + threadIdx.x;
    if (i >= E) return;
    int p = atomicAdd(cur + dst[i], 1);
    csr[p] = rankS[src[i]];
}

// ---------------- gather-GEMM: Y[c] = relu(X[list[c]]) @ W + b, bf16 3-term split ----------------
#define SA 17408  // 128*136 bf16 elems per smem matrix

#define LDSM4(R, addr) asm volatile( \
    "ldmatrix.sync.aligned.m8n8.x4.shared.b16 {%0,%1,%2,%3}, [%4];" \
    : "=r"((R)[0]), "=r"((R)[1]), "=r"((R)[2]), "=r"((R)[3]) : "r"(addr))

#define MMA16816(C, A, b0, b1) asm volatile( \
    "mma.sync.aligned.m16n8k16.row.col.f32.bf16.bf16.f32 " \
    "{%0,%1,%2,%3},{%4,%5,%6,%7},{%8,%9},{%0,%1,%2,%3};" \
    : "+f"((C)[0]), "+f"((C)[1]), "+f"((C)[2]), "+f"((C)[3]) \
    : "r"((A)[0]), "r"((A)[1]), "r"((A)[2]), "r"((A)[3]), "r"(b0), "r"(b1))

static __device__ __forceinline__ void cpasync16(unsigned dst, const void* src, int sz) {
    asm volatile("cp.async.cg.shared.global [%0], [%1], 16, %2;" :: "r"(dst), "l"(src), "r"(sz));
}

__global__ void __launch_bounds__(256) gemm_gather_k(
    const float* __restrict__ A_g, const int* __restrict__ rowlist,
    const int* __restrict__ cntPtr,
    const __nv_bfloat16* __restrict__ Bhi, const __nv_bfloat16* __restrict__ Blo,
    const float* __restrict__ bias, float* __restrict__ out) {
    extern __shared__ __nv_bfloat16 smem[];
    const int tid = threadIdx.x;
    const int cnt = *cntPtr;
    const int row0 = blockIdx.x * 128;
    if (row0 >= cnt) return;

    unsigned sAhi = (unsigned)__cvta_generic_to_shared(smem);   // [0, SA)
    unsigned sB = sAhi + 2 * SA * 2;                            // B hi/lo at [2SA, 4SA)
    float* stage = (float*)(smem + 2 * SA);                     // fp32 staging overlays B

    // 1) gather fp32 A rows via rowlist (zero-fill OOB)
#pragma unroll
    for (int i = 0; i < 16; i++) {
        int chunk = tid + i * 256;          // 4096 chunks of 16B
        int row = chunk >> 5;
        int c4 = (chunk & 31) * 4;
        int ok = (row0 + row) < cnt;
        int node = ok ? rowlist[row0 + row] : 0;
        unsigned d = (unsigned)__cvta_generic_to_shared(stage + row * 128 + c4);
        cpasync16(d, A_g + (size_t)node * 128 + c4, ok ? 16 : 0);
    }
    asm volatile("cp.async.commit_group;");
    asm volatile("cp.async.wait_group 0;");
    __syncthreads();

    // 2) relu + bf16 hi/lo split
#pragma unroll
    for (int i = 0; i < 64; i++) {
        int idx = tid + i * 256;
        int row = idx >> 7, col = idx & 127;
        float v = fmaxf(stage[idx], 0.f);
        __nv_bfloat16 h, l;
        bf16split(v, h, l);
        smem[row * 136 + col] = h;
        smem[SA + row * 136 + col] = l;
    }
    __syncthreads();   // all reads of stage done before B overwrites it

    // 3) load B hi/lo
#pragma unroll
    for (int i = 0; i < 8; i++) {
        int chunk = tid + i * 256;
        int row = chunk >> 4;
        int col = (chunk & 15) * 8;
        size_t off = (size_t)row * 128 + col;
        unsigned d = sB + (unsigned)(row * 136 + col) * 2;
        cpasync16(d, Bhi + off, 16);
        cpasync16(d + SA * 2, Blo + off, 16);
    }
    asm volatile("cp.async.commit_group;");
    asm volatile("cp.async.wait_group 0;");
    __syncthreads();

    int warp = tid >> 5, lane = tid & 31;
    int m0 = (warp >> 2) * 64;
    int n0 = (warp & 3) * 32;
    int frow = lane & 15;
    int fcolo = (lane >> 4) * 8;

    float acc[4][4][4];
#pragma unroll
    for (int a = 0; a < 4; a++)
#pragma unroll
        for (int c = 0; c < 4; c++)
#pragma unroll
            for (int r = 0; r < 4; r++) acc[a][c][r] = 0.f;

    for (int ks = 0; ks < 8; ks++) {
        int acol = ks * 16 + fcolo;
        unsigned ah[4][4], al[4][4];
#pragma unroll
        for (int mt = 0; mt < 4; mt++) {
            unsigned ad = sAhi + (unsigned)((m0 + mt * 16 + frow) * 136 + acol) * 2;
            LDSM4(ah[mt], ad);
            LDSM4(al[mt], ad + SA * 2);
        }
        unsigned bh[2][4], blx[2][4];
#pragma unroll
        for (int p = 0; p < 2; p++) {
            unsigned bd = sB + (unsigned)((n0 + p * 16 + frow) * 136 + acol) * 2;
            LDSM4(bh[p], bd);
            LDSM4(blx[p], bd + SA * 2);
        }
#pragma unroll
        for (int mt = 0; mt < 4; mt++)
#pragma unroll
            for (int nt = 0; nt < 4; nt++) {
                int p = nt >> 1, o = nt & 1;
                MMA16816(acc[mt][nt], ah[mt], bh[p][o], bh[p][2 + o]);
                MMA16816(acc[mt][nt], ah[mt], blx[p][o], blx[p][2 + o]);
                MMA16816(acc[mt][nt], al[mt], bh[p][o], bh[p][2 + o]);
            }
    }

    int crow = lane >> 2, ccol = (lane & 3) * 2;
#pragma unroll
    for (int nt = 0; nt < 4; nt++) {
        int col = n0 + nt * 8 + ccol;
        float b0v = bias[col], b1v = bias[col + 1];
#pragma unroll
        for (int mt = 0; mt < 4; mt++) {
            int r = row0 + m0 + mt * 16 + crow;
            if (r < cnt)
                *(float2*)(out + (size_t)r * 128 + col) =
                    make_float2(acc[mt][nt][0] + b0v, acc[mt][nt][1] + b1v);
            if (r + 8 < cnt)
                *(float2*)(out + (size_t)(r + 8) * 128 + col) =
                    make_float2(acc[mt][nt][2] + b0v, acc[mt][nt][3] + b1v);
        }
    }
}

// ---------------- fused multi-type edge kernel: warp-per-dst, online softmax ----------------
struct EdgeT {
    const float* xl;   // compact src rows
    const float* xr;   // compact dst rows
    const int* csr;    // compact src indices
    const int* off;    // CSR offsets (original dst index)
    const int* rank;   // dst node -> compact xr row
    const float* att;
    const float* bias;
};
struct EdgeArgs { EdgeT t[3]; };

__global__ void edge_multi_k(EdgeArgs ea, int nt, float* __restrict__ agg, int Nd) {
    int d = blockIdx.x * 8 + (threadIdx.x >> 5);
    if (d >= Nd) return;
    int lane = threadIdx.x & 31;
    float4 r = make_float4(0.f, 0.f, 0.f, 0.f);
    for (int k = 0; k < nt; k++) {
        const EdgeT& t = ea.t[k];
        float4 bb = ((const float4*)t.bias)[lane];
        r.x += bb.x; r.y += bb.y; r.z += bb.z; r.w += bb.w;
        int s0 = t.off[d], s1 = t.off[d + 1];
        if (s1 > s0) {
            int cr = t.rank[d];
            float4 xr4 = ((const float4*)(t.xr + (size_t)cr * 128))[lane];
            float4 at = ((const float4*)t.att)[lane];
            float m = -INFINITY, den = 0.f;
            float a0 = 0.f, a1 = 0.f, a2 = 0.f, a3 = 0.f;
            for (int e = s0; e < s1; e++) {
                int si = t.csr[e];
                float4 xv = ((const float4*)(t.xl + (size_t)si * 128))[lane];
                float t0 = xv.x + xr4.x, t1 = xv.y + xr4.y, t2 = xv.z + xr4.z, t3 = xv.w + xr4.w;
                t0 = t0 > 0.f ? t0 : NEG_SLOPE * t0;
                t1 = t1 > 0.f ? t1 : NEG_SLOPE * t1;
                t2 = t2 > 0.f ? t2 : NEG_SLOPE * t2;
                t3 = t3 > 0.f ? t3 : NEG_SLOPE * t3;
                float p = t0 * at.x + t1 * at.y + t2 * at.z + t3 * at.w;
#pragma unroll
                for (int o = 16; o; o >>= 1) p += __shfl_xor_sync(0xffffffffu, p, o);
                float mn = fmaxf(m, p);
                float corr = __expf(m - mn);
                float w = __expf(p - mn);
                den = den * corr + w;
                a0 = a0 * corr + w * xv.x;
                a1 = a1 * corr + w * xv.y;
                a2 = a2 * corr + w * xv.z;
                a3 = a3 * corr + w * xv.w;
                m = mn;
            }
            float inv = 1.f / den;
            r.x += a0 * inv; r.y += a1 * inv; r.z += a2 * inv; r.w += a3 * inv;
        }
    }
    *(float4*)(agg + (size_t)d * 128 + lane * 4) = r;
}

// ---------------- decoder with fused relu ----------------
__global__ void decode_k(const float* __restrict__ agg, const float* __restrict__ W,
                         const float* __restrict__ b, float* __restrict__ out, int N) {
    int f = blockIdx.x * 8 + (threadIdx.x >> 5);
    if (f >= N) return;
    int lane = threadIdx.x & 31;
    float4 v = ((const float4*)(agg + (size_t)f * 128))[lane];
    v.x = fmaxf(v.x, 0.f); v.y = fmaxf(v.y, 0.f); v.z = fmaxf(v.z, 0.f); v.w = fmaxf(v.w, 0.f);
    int h = lane * 4;
    float s0 = v.x * W[(h + 0) * 3 + 0] + v.y * W[(h + 1) * 3 + 0] + v.z * W[(h + 2) * 3 + 0] + v.w * W[(h + 3) * 3 + 0];
    float s1 = v.x * W[(h + 0) * 3 + 1] + v.y * W[(h + 1) * 3 + 1] + v.z * W[(h + 2) * 3 + 1] + v.w * W[(h + 3) * 3 + 1];
    float s2 = v.x * W[(h + 0) * 3 + 2] + v.y * W[(h + 1) * 3 + 2] + v.z * W[(h + 2) * 3 + 2] + v.w * W[(h + 3) * 3 + 2];
#pragma unroll
    for (int o = 16; o; o >>= 1) {
        s0 += __shfl_xor_sync(0xffffffffu, s0, o);
        s1 += __shfl_xor_sync(0xffffffffu, s1, o);
        s2 += __shfl_xor_sync(0xffffffffu, s2, o);
    }
    if (lane == 0) {
        out[f * 3 + 0] = s0 + b[0];
        out[f * 3 + 1] = s1 + b[1];
        out[f * 3 + 2] = s2 + b[2];
    }
}

// ---------------- host orchestration ----------------
extern "C" void kernel_launch(void* const* d_in, const int* in_sizes, int n_in,
                              void* d_out, int out_size) {
    int I[27];
    if (in_sizes[1] == 768) {
        const int m[27] = {0, 3, 6, 1, 2, 4, 5, 7, 8,
                           19, 20, 21, 22, 23, 24, 25, 26,
                           9, 10, 11, 12, 13, 14, 15, 16, 17, 18};
        for (int i = 0; i < 27; i++) I[i] = m[i];
    } else {
        for (int i = 0; i < 27; i++) I[i] = i;
    }

    const float* x_in[3] = {(const float*)d_in[I[0]], (const float*)d_in[I[1]], (const float*)d_in[I[2]]};
    const float* Wenc[3] = {(const float*)d_in[I[3]], (const float*)d_in[I[5]], (const float*)d_in[I[7]]};
    const float* benc[3] = {(const float*)d_in[I[4]], (const float*)d_in[I[6]], (const float*)d_in[I[8]]};
    const float* Wl = (const float*)d_in[I[9]];
    const float* bl = (const float*)d_in[I[10]];
    const float* Wr = (const float*)d_in[I[11]];
    const float* br = (const float*)d_in[I[12]];
    const float* att = (const float*)d_in[I[13]];
    const float* cb = (const float*)d_in[I[14]];
    const float* Wdec = (const float*)d_in[I[15]];
    const float* bdec = (const float*)d_in[I[16]];
    const int *srcA[5], *dstA[5];
    int E[5];
    for (int t = 0; t < 5; t++) {
        srcA[t] = (const int*)d_in[I[17 + 2 * t]];
        dstA[t] = (const int*)d_in[I[18 + 2 * t]];
        E[t] = in_sizes[I[17 + 2 * t]];
    }

    float *bufA, *bufB, *pool;
    __nv_bfloat16 *Wthi, *Wtlo;
    int *off, *csr, *deg, *cur, *scan, *rankB, *listB, *cnt, *part;
    cudaGetSymbolAddress((void**)&bufA, g_bufA);
    cudaGetSymbolAddress((void**)&bufB, g_bufB);
    cudaGetSymbolAddress((void**)&pool, g_pool);
    cudaGetSymbolAddress((void**)&Wthi, g_Wthi);
    cudaGetSymbolAddress((void**)&Wtlo, g_Wtlo);
    cudaGetSymbolAddress((void**)&off, g_off);
    cudaGetSymbolAddress((void**)&csr, g_csr);
    cudaGetSymbolAddress((void**)&deg, g_deg);
    cudaGetSymbolAddress((void**)&cur, g_cur);
    cudaGetSymbolAddress((void**)&scan, g_scan);
    cudaGetSymbolAddress((void**)&rankB, g_rank);
    cudaGetSymbolAddress((void**)&listB, g_list);
    cudaGetSymbolAddress((void**)&cnt, g_cnt);
    cudaGetSymbolAddress((void**)&part, g_part);

    const int Nn[3] = {NBASE, NJOINT, NFOOT};
    const int Kin[3] = {6, 2, 4};
    const size_t XOFF[3] = {0, (size_t)NBASE * 128, (size_t)(NBASE + NJOINT) * 128};
    const int sT[5] = {0, 1, 1, 1, 2};
    const int dT[5] = {1, 0, 1, 2, 1};
    const int dstN[5] = {NJOINT, NBASE, NJOINT, NFOOT, NJOINT};
    const int offStart[5] = {0, 480001, 520002, 1000003, 1160004};
    const int csrStart[5] = {0, 160000, 320000, 640000, 800000};
    // pool row offsets per role (role = 2*ei + side; side 0=src/xl, 1=dst/xr)
    const size_t POOL[10] = {0, 40000, 200000, 360000, 400000, 720000, 1040000, 1200000, 1360000, 1520000};
    const int GRID[10] = {313, 1250, 1250, 313, 2500, 2500, 1250, 1250, 1250, 1250};

    const int SMEM = 4 * SA * 2;  // 139264 B
    cudaFuncSetAttribute(gemm_gather_k, cudaFuncAttributeMaxDynamicSharedMemorySize, SMEM);

    // ---- once-per-call prep ----
    wprep_k<<<(40 * 16384 + 255) / 256, 256>>>(Wl, Wr, Wthi, Wtlo);
    for (int t = 0; t < 3; t++)
        encode_k<<<(Nn[t] * HDIM + 255) / 256, 256>>>(
            x_in[t], Wenc[t], benc[t], bufA + XOFF[t], Nn[t], Kin[t]);

    // per-role compaction (mark -> scan -> compact)
    for (int ei = 0; ei < 5; ei++) {
        for (int side = 0; side < 2; side++) {
            int role = 2 * ei + side;
            const int* idx = side ? dstA[ei] : srcA[ei];
            int N = Nn[side ? dT[ei] : sT[ei]];
            int Ee = E[ei];
            int* rank = rankB + (size_t)role * 480000;
            int nb = (N + 1023) / 1024;
            cudaMemsetAsync(rank, 0, (size_t)N * 4);
            mark_k<<<(Ee + 255) / 256, 256>>>(idx, rank, Ee);
            scan1_k<<<nb, 1024>>>(rank, scan, part, N);
            scan2_k<<<1, 1024>>>(part, nb);
            scan3_k<<<(N + 255) / 256, 256>>>(scan, part, N, nb, cnt + role);
            compact_k<<<(N + 255) / 256, 256>>>(rank, scan, listB + (size_t)role * 480000, N);
        }
    }

    // CSR build with compact-src remap
    for (int t = 0; t < 5; t++) {
        int Nd = dstN[t], Ee = E[t];
        int nb = (Nd + 1023) / 1024;
        int* offT = off + offStart[t];
        cudaMemsetAsync(deg, 0, (size_t)Nd * 4);
        hist_k<<<(Ee + 255) / 256, 256>>>(dstA[t], deg, Ee);
        scan1_k<<<nb, 1024>>>(deg, offT, part, Nd);
        scan2_k<<<1, 1024>>>(part, nb);
        scan3_k<<<(Nd + 255) / 256, 256>>>(offT, part, Nd, nb, nullptr);
        cudaMemcpyAsync(cur, offT, (size_t)Nd * 4, cudaMemcpyDeviceToDevice);
        fill_k<<<(Ee + 255) / 256, 256>>>(srcA[t], dstA[t], cur, csr + csrStart[t],
                                          rankB + (size_t)(2 * t) * 480000, Ee);
    }

    float* x = bufA;
    float* agg = bufB;

    auto gemmRole = [&](int ei, int side, int l) {
        int role = 2 * ei + side;
        int po = l * 5 + ei;
        int wIdx = side ? (20 + po) : po;
        const float* bias = side ? (br + (size_t)po * 128) : (bl + (size_t)po * 128);
        int nt = side ? dT[ei] : sT[ei];
        gemm_gather_k<<<GRID[role], 256, SMEM>>>(
            x + XOFF[nt], listB + (size_t)role * 480000, cnt + role,
            Wthi + (size_t)wIdx * 16384, Wtlo + (size_t)wIdx * 16384,
            bias, pool + POOL[role] * 128);
    };
    auto edgeT = [&](int ei, int l) {
        int po = l * 5 + ei;
        EdgeT t;
        t.xl = pool + POOL[2 * ei] * 128;
        t.xr = pool + POOL[2 * ei + 1] * 128;
        t.csr = csr + csrStart[ei];
        t.off = off + offStart[ei];
        t.rank = rankB + (size_t)(2 * ei + 1) * 480000;
        t.att = att + (size_t)po * 128;
        t.bias = cb + (size_t)po * 128;
        return t;
    };

    for (int l = 0; l < 4; l++) {
        bool last = (l == 3);
        if (!last) {
            for (int ei = 0; ei < 5; ei++) {
                gemmRole(ei, 0, l);
                gemmRole(ei, 1, l);
            }
            // joint dst: bj (0), jj (2), fj (4) fused
            EdgeArgs eaJ; eaJ.t[0] = edgeT(0, l); eaJ.t[1] = edgeT(2, l); eaJ.t[2] = edgeT(4, l);
            edge_multi_k<<<(NJOINT + 7) / 8, 256>>>(eaJ, 3, agg + XOFF[1], NJOINT);
            // base dst: jb (1)
            EdgeArgs eaB; eaB.t[0] = edgeT(1, l); eaB.t[1] = eaB.t[0]; eaB.t[2] = eaB.t[0];
            edge_multi_k<<<(NBASE + 7) / 8, 256>>>(eaB, 1, agg + XOFF[0], NBASE);
            // foot dst: jf (3)
            EdgeArgs eaF; eaF.t[0] = edgeT(3, l); eaF.t[1] = eaF.t[0]; eaF.t[2] = eaF.t[0];
            edge_multi_k<<<(NFOOT + 7) / 8, 256>>>(eaF, 1, agg + XOFF[2], NFOOT);
            float* tmp = x; x = agg; agg = tmp;
        } else {
            gemmRole(3, 0, l);
            gemmRole(3, 1, l);
            EdgeArgs eaF; eaF.t[0] = edgeT(3, l); eaF.t[1] = eaF.t[0]; eaF.t[2] = eaF.t[0];
            edge_multi_k<<<(NFOOT + 7) / 8, 256>>>(eaF, 1, agg + XOFF[2], NFOOT);
        }
    }

    decode_k<<<(NFOOT + 7) / 8, 256>>>(agg + XOFF[2], Wdec, bdec, (float*)d_out, NFOOT);
}

// round 7
// speedup vs baseline: 4.0072x; 1.0825x over previous
#include <cuda_runtime.h>
#include <cuda_bf16.h>
#include <math.h>

#define NBASE 40000
#define NJOINT 480000
#define NFOOT 160000
#define HDIM 128
#define NEG_SLOPE 0.2f
#define RSTR 481280      // padded per-role segment stride (= 470*1024)
#define NBLK 470         // 1024-elem scan blocks per segment

// ---------------- scratch (device globals; ~1.66 GB, linker-safe) ----------------
__device__ float g_bufA[(size_t)680000 * 128];   // x / agg ping-pong
__device__ float g_bufB[(size_t)680000 * 128];
__device__ float g_pool[(size_t)1680000 * 128];  // compact xl/xr rows, all 10 roles live
__device__ __nv_bfloat16 g_Wthi[40 * 16384];
__device__ __nv_bfloat16 g_Wtlo[40 * 16384];
__device__ int g_rank[10 * RSTR];   // per-role: mark -> compact idx (-1 unused)
__device__ int g_list[10 * RSTR];   // per-role compact idx -> node
__device__ int g_scan[10 * RSTR];
__device__ int g_deg[5 * RSTR];
__device__ int g_off5[5 * RSTR];    // CSR offsets, strided per type
__device__ int g_cur5[5 * RSTR];
__device__ int g_csr[960000];
__device__ int g_cnt[16];
__device__ int g_part[10 * 512];

// ---------------- helpers ----------------
static __device__ __forceinline__ void bf16split(float v, __nv_bfloat16& h, __nv_bfloat16& l) {
    h = __float2bfloat16(v);
    l = __float2bfloat16(v - __bfloat162float(h));
}

__global__ void wprep_k(const float* __restrict__ Wl, const float* __restrict__ Wr,
                        __nv_bfloat16* __restrict__ hi, __nv_bfloat16* __restrict__ lo) {
    int idx = blockIdx.x * 256 + threadIdx.x;
    if (idx >= 40 * 16384) return;
    int m = idx >> 14, e = idx & 16383;
    int n = e >> 7, k = e & 127;
    const float* src = (m < 20) ? (Wl + (size_t)m * 16384) : (Wr + (size_t)(m - 20) * 16384);
    float v = src[k * 128 + n];
    __nv_bfloat16 h, l;
    bf16split(v, h, l);
    hi[idx] = h; lo[idx] = l;
}

__global__ void encode_k(const float* __restrict__ x, const float* __restrict__ W,
                         const float* __restrict__ b, float* __restrict__ y, int N, int K) {
    int idx = blockIdx.x * blockDim.x + threadIdx.x;
    if (idx >= N * HDIM) return;
    int n = idx >> 7, h = idx & 127;
    float acc = b[h];
    for (int k = 0; k < K; k++) acc += x[n * K + k] * W[k * HDIM + h];
    y[idx] = fmaxf(acc, 0.f);
}

// ---------------- batched prep ----------------
struct EL {
    const int* src[5];
    const int* dst[5];
    int cumE[6];        // {0,160000,320000,640000,800000,960000}
};
struct NArr { int N[10]; };

// mark all 10 roles in one pass: items [0,total) = src marks, [total,2*total) = dst marks
__global__ void mark_all_k(EL el, int total) {
    int gi = blockIdx.x * 256 + threadIdx.x;
    if (gi >= 2 * total) return;
    int side = gi >= total;
    int j = gi - side * total;
    int t = 0;
    while (j >= el.cumE[t + 1]) t++;
    int e = j - el.cumE[t];
    int node = side ? el.dst[t][e] : el.src[t][e];
    g_rank[(2 * t + side) * RSTR + node] = 1;
}

// batched exclusive scan over nseg segments of RSTR each (src zero-padded beyond N)
__global__ void bscan1_k(const int* __restrict__ v, int* __restrict__ out,
                         int* __restrict__ part) {
    __shared__ int sh[1024];
    int r = blockIdx.x / NBLK, j = blockIdx.x % NBLK;
    int i = r * RSTR + j * 1024 + threadIdx.x;
    int val = v[i];
    sh[threadIdx.x] = val;
    __syncthreads();
#pragma unroll
    for (int o = 1; o < 1024; o <<= 1) {
        int t = (threadIdx.x >= o) ? sh[threadIdx.x - o] : 0;
        __syncthreads();
        sh[threadIdx.x] += t;
        __syncthreads();
    }
    int incl = sh[threadIdx.x];
    out[i] = incl - val;
    if (threadIdx.x == 1023) part[r * 512 + j] = incl;
}
__global__ void bscan2_k(int* part) {
    __shared__ int sh[512];
    int r = blockIdx.x;
    int v = (threadIdx.x < NBLK) ? part[r * 512 + threadIdx.x] : 0;
    sh[threadIdx.x] = v;
    __syncthreads();
#pragma unroll
    for (int o = 1; o < 512; o <<= 1) {
        int t = (threadIdx.x >= o) ? sh[threadIdx.x - o] : 0;
        __syncthreads();
        sh[threadIdx.x] += t;
        __syncthreads();
    }
    if (threadIdx.x < NBLK) part[r * 512 + threadIdx.x] = sh[threadIdx.x] - v;
}
__global__ void bscan3_k(int* __restrict__ out, const int* __restrict__ part) {
    int r = blockIdx.x / NBLK, j = blockIdx.x % NBLK;
    int i = r * RSTR + j * 1024 + threadIdx.x;
    out[i] += part[r * 512 + j];
}

__global__ void bcompact_k(NArr na) {
    int i = blockIdx.x * 256 + threadIdx.x;
    if (i >= 10 * RSTR) return;
    int r = i / RSTR, li = i % RSTR;
    if (li >= na.N[r]) return;
    if (g_rank[i]) {
        int pos = g_scan[i];
        g_list[r * RSTR + pos] = li;
        g_rank[i] = pos;
    } else {
        g_rank[i] = -1;
    }
}
__global__ void getcnt_k(NArr na) {
    int r = threadIdx.x;
    if (r < 10) g_cnt[r] = g_scan[r * RSTR + na.N[r]];   // exclusive prefix at N = total
}

__global__ void bhist_k(EL el, int total) {
    int j = blockIdx.x * 256 + threadIdx.x;
    if (j >= total) return;
    int t = 0;
    while (j >= el.cumE[t + 1]) t++;
    int e = j - el.cumE[t];
    atomicAdd(&g_deg[t * RSTR + el.dst[t][e]], 1);
}
__global__ void bfill_k(EL el, int total) {
    int j = blockIdx.x * 256 + threadIdx.x;
    if (j >= total) return;
    int t = 0;
    while (j >= el.cumE[t + 1]) t++;
    int e = j - el.cumE[t];
    int d = el.dst[t][e];
    int p = atomicAdd(&g_cur5[t * RSTR + d], 1);
    g_csr[el.cumE[t] + p] = g_rank[(2 * t) * RSTR + el.src[t][e]];
}

// ---------------- batched gather-GEMM ----------------
#define SA 17408

#define LDSM4(R, addr) asm volatile( \
    "ldmatrix.sync.aligned.m8n8.x4.shared.b16 {%0,%1,%2,%3}, [%4];" \
    : "=r"((R)[0]), "=r"((R)[1]), "=r"((R)[2]), "=r"((R)[3]) : "r"(addr))

#define MMA16816(C, A, b0, b1) asm volatile( \
    "mma.sync.aligned.m16n8k16.row.col.f32.bf16.bf16.f32 " \
    "{%0,%1,%2,%3},{%4,%5,%6,%7},{%8,%9},{%0,%1,%2,%3};" \
    : "+f"((C)[0]), "+f"((C)[1]), "+f"((C)[2]), "+f"((C)[3]) \
    : "r"((A)[0]), "r"((A)[1]), "r"((A)[2]), "r"((A)[3]), "r"(b0), "r"(b1))

static __device__ __forceinline__ void cpasync16(unsigned dst, const void* src, int sz) {
    asm volatile("cp.async.cg.shared.global [%0], [%1], 16, %2;" :: "r"(dst), "l"(src), "r"(sz));
}

struct GR {
    const float* A;
    const int* rowlist;
    const int* cntPtr;
    const __nv_bfloat16* Bhi;
    const __nv_bfloat16* Blo;
    const float* bias;
    float* out;
};
struct GB { GR r[10]; int cum[11]; int n; };

__global__ void __launch_bounds__(256) gemm_batch_k(GB gb) {
    int b = blockIdx.x;
    int k = 0;
    while (k < gb.n - 1 && b >= gb.cum[k + 1]) k++;
    GR R = gb.r[k];
    const int cnt = *R.cntPtr;
    const int row0 = (b - gb.cum[k]) * 128;
    if (row0 >= cnt) return;

    extern __shared__ __nv_bfloat16 smem[];
    const int tid = threadIdx.x;
    unsigned sAhi = (unsigned)__cvta_generic_to_shared(smem);
    unsigned sB = sAhi + 2 * SA * 2;
    float* stage = (float*)(smem + 2 * SA);

    // gather fp32 A rows
#pragma unroll
    for (int i = 0; i < 16; i++) {
        int chunk = tid + i * 256;
        int row = chunk >> 5;
        int c4 = (chunk & 31) * 4;
        int ok = (row0 + row) < cnt;
        int node = ok ? R.rowlist[row0 + row] : 0;
        unsigned d = (unsigned)__cvta_generic_to_shared(stage + row * 128 + c4);
        cpasync16(d, R.A + (size_t)node * 128 + c4, ok ? 16 : 0);
    }
    asm volatile("cp.async.commit_group;");
    asm volatile("cp.async.wait_group 0;");
    __syncthreads();

    // relu + bf16 hi/lo split
#pragma unroll
    for (int i = 0; i < 64; i++) {
        int idx = tid + i * 256;
        int row = idx >> 7, col = idx & 127;
        float v = fmaxf(stage[idx], 0.f);
        __nv_bfloat16 h, l;
        bf16split(v, h, l);
        smem[row * 136 + col] = h;
        smem[SA + row * 136 + col] = l;
    }
    __syncthreads();

    // load B hi/lo
#pragma unroll
    for (int i = 0; i < 8; i++) {
        int chunk = tid + i * 256;
        int row = chunk >> 4;
        int col = (chunk & 15) * 8;
        size_t off = (size_t)row * 128 + col;
        unsigned d = sB + (unsigned)(row * 136 + col) * 2;
        cpasync16(d, R.Bhi + off, 16);
        cpasync16(d + SA * 2, R.Blo + off, 16);
    }
    asm volatile("cp.async.commit_group;");
    asm volatile("cp.async.wait_group 0;");
    __syncthreads();

    int warp = tid >> 5, lane = tid & 31;
    int m0 = (warp >> 2) * 64;
    int n0 = (warp & 3) * 32;
    int frow = lane & 15;
    int fcolo = (lane >> 4) * 8;

    float acc[4][4][4];
#pragma unroll
    for (int a = 0; a < 4; a++)
#pragma unroll
        for (int c = 0; c < 4; c++)
#pragma unroll
            for (int r = 0; r < 4; r++) acc[a][c][r] = 0.f;

    for (int ks = 0; ks < 8; ks++) {
        int acol = ks * 16 + fcolo;
        unsigned ah[4][4], al[4][4];
#pragma unroll
        for (int mt = 0; mt < 4; mt++) {
            unsigned ad = sAhi + (unsigned)((m0 + mt * 16 + frow) * 136 + acol) * 2;
            LDSM4(ah[mt], ad);
            LDSM4(al[mt], ad + SA * 2);
        }
        unsigned bh[2][4], blx[2][4];
#pragma unroll
        for (int p = 0; p < 2; p++) {
            unsigned bd = sB + (unsigned)((n0 + p * 16 + frow) * 136 + acol) * 2;
            LDSM4(bh[p], bd);
            LDSM4(blx[p], bd + SA * 2);
        }
#pragma unroll
        for (int mt = 0; mt < 4; mt++)
#pragma unroll
            for (int nt = 0; nt < 4; nt++) {
                int p = nt >> 1, o = nt & 1;
                MMA16816(acc[mt][nt], ah[mt], bh[p][o], bh[p][2 + o]);
                MMA16816(acc[mt][nt], ah[mt], blx[p][o], blx[p][2 + o]);
                MMA16816(acc[mt][nt], al[mt], bh[p][o], bh[p][2 + o]);
            }
    }

    int crow = lane >> 2, ccol = (lane & 3) * 2;
#pragma unroll
    for (int nt = 0; nt < 4; nt++) {
        int col = n0 + nt * 8 + ccol;
        float b0v = R.bias[col], b1v = R.bias[col + 1];
#pragma unroll
        for (int mt = 0; mt < 4; mt++) {
            int r = row0 + m0 + mt * 16 + crow;
            if (r < cnt)
                *(float2*)(R.out + (size_t)r * 128 + col) =
                    make_float2(acc[mt][nt][0] + b0v, acc[mt][nt][1] + b1v);
            if (r + 8 < cnt)
                *(float2*)(R.out + (size_t)(r + 8) * 128 + col) =
                    make_float2(acc[mt][nt][2] + b0v, acc[mt][nt][3] + b1v);
        }
    }
}

// ---------------- fused multi-type edge kernel ----------------
struct EdgeT {
    const float* xl;
    const float* xr;
    const int* csr;
    const int* off;
    const int* rank;
    const float* att;
    const float* bias;
};
struct EdgeArgs { EdgeT t[3]; };

__global__ void edge_multi_k(EdgeArgs ea, int nt, float* __restrict__ agg, int Nd) {
    int d = blockIdx.x * 8 + (threadIdx.x >> 5);
    if (d >= Nd) return;
    int lane = threadIdx.x & 31;
    float4 r = make_float4(0.f, 0.f, 0.f, 0.f);
    for (int k = 0; k < nt; k++) {
        const EdgeT& t = ea.t[k];
        float4 bb = ((const float4*)t.bias)[lane];
        r.x += bb.x; r.y += bb.y; r.z += bb.z; r.w += bb.w;
        int s0 = t.off[d], s1 = t.off[d + 1];
        if (s1 > s0) {
            int cr = t.rank[d];
            float4 xr4 = ((const float4*)(t.xr + (size_t)cr * 128))[lane];
            float4 at = ((const float4*)t.att)[lane];
            float m = -INFINITY, den = 0.f;
            float a0 = 0.f, a1 = 0.f, a2 = 0.f, a3 = 0.f;
            for (int e = s0; e < s1; e++) {
                int si = t.csr[e];
                float4 xv = ((const float4*)(t.xl + (size_t)si * 128))[lane];
                float t0 = xv.x + xr4.x, t1 = xv.y + xr4.y, t2 = xv.z + xr4.z, t3 = xv.w + xr4.w;
                t0 = t0 > 0.f ? t0 : NEG_SLOPE * t0;
                t1 = t1 > 0.f ? t1 : NEG_SLOPE * t1;
                t2 = t2 > 0.f ? t2 : NEG_SLOPE * t2;
                t3 = t3 > 0.f ? t3 : NEG_SLOPE * t3;
                float p = t0 * at.x + t1 * at.y + t2 * at.z + t3 * at.w;
#pragma unroll
                for (int o = 16; o; o >>= 1) p += __shfl_xor_sync(0xffffffffu, p, o);
                float mn = fmaxf(m, p);
                float corr = __expf(m - mn);
                float w = __expf(p - mn);
                den = den * corr + w;
                a0 = a0 * corr + w * xv.x;
                a1 = a1 * corr + w * xv.y;
                a2 = a2 * corr + w * xv.z;
                a3 = a3 * corr + w * xv.w;
                m = mn;
            }
            float inv = 1.f / den;
            r.x += a0 * inv; r.y += a1 * inv; r.z += a2 * inv; r.w += a3 * inv;
        }
    }
    *(float4*)(agg + (size_t)d * 128 + lane * 4) = r;
}

// ---------------- decoder with fused relu ----------------
__global__ void decode_k(const float* __restrict__ agg, const float* __restrict__ W,
                         const float* __restrict__ b, float* __restrict__ out, int N) {
    int f = blockIdx.x * 8 + (threadIdx.x >> 5);
    if (f >= N) return;
    int lane = threadIdx.x & 31;
    float4 v = ((const float4*)(agg + (size_t)f * 128))[lane];
    v.x = fmaxf(v.x, 0.f); v.y = fmaxf(v.y, 0.f); v.z = fmaxf(v.z, 0.f); v.w = fmaxf(v.w, 0.f);
    int h = lane * 4;
    float s0 = v.x * W[(h + 0) * 3 + 0] + v.y * W[(h + 1) * 3 + 0] + v.z * W[(h + 2) * 3 + 0] + v.w * W[(h + 3) * 3 + 0];
    float s1 = v.x * W[(h + 0) * 3 + 1] + v.y * W[(h + 1) * 3 + 1] + v.z * W[(h + 2) * 3 + 1] + v.w * W[(h + 3) * 3 + 1];
    float s2 = v.x * W[(h + 0) * 3 + 2] + v.y * W[(h + 1) * 3 + 2] + v.z * W[(h + 2) * 3 + 2] + v.w * W[(h + 3) * 3 + 2];
#pragma unroll
    for (int o = 16; o; o >>= 1) {
        s0 += __shfl_xor_sync(0xffffffffu, s0, o);
        s1 += __shfl_xor_sync(0xffffffffu, s1, o);
        s2 += __shfl_xor_sync(0xffffffffu, s2, o);
    }
    if (lane == 0) {
        out[f * 3 + 0] = s0 + b[0];
        out[f * 3 + 1] = s1 + b[1];
        out[f * 3 + 2] = s2 + b[2];
    }
}

// ---------------- host orchestration ----------------
extern "C" void kernel_launch(void* const* d_in, const int* in_sizes, int n_in,
                              void* d_out, int out_size) {
    int I[27];
    if (in_sizes[1] == 768) {
        const int m[27] = {0, 3, 6, 1, 2, 4, 5, 7, 8,
                           19, 20, 21, 22, 23, 24, 25, 26,
                           9, 10, 11, 12, 13, 14, 15, 16, 17, 18};
        for (int i = 0; i < 27; i++) I[i] = m[i];
    } else {
        for (int i = 0; i < 27; i++) I[i] = i;
    }

    const float* x_in[3] = {(const float*)d_in[I[0]], (const float*)d_in[I[1]], (const float*)d_in[I[2]]};
    const float* Wenc[3] = {(const float*)d_in[I[3]], (const float*)d_in[I[5]], (const float*)d_in[I[7]]};
    const float* benc[3] = {(const float*)d_in[I[4]], (const float*)d_in[I[6]], (const float*)d_in[I[8]]};
    const float* Wl = (const float*)d_in[I[9]];
    const float* bl = (const float*)d_in[I[10]];
    const float* Wr = (const float*)d_in[I[11]];
    const float* br = (const float*)d_in[I[12]];
    const float* att = (const float*)d_in[I[13]];
    const float* cb = (const float*)d_in[I[14]];
    const float* Wdec = (const float*)d_in[I[15]];
    const float* bdec = (const float*)d_in[I[16]];
    const int *srcA[5], *dstA[5];
    int E[5];
    for (int t = 0; t < 5; t++) {
        srcA[t] = (const int*)d_in[I[17 + 2 * t]];
        dstA[t] = (const int*)d_in[I[18 + 2 * t]];
        E[t] = in_sizes[I[17 + 2 * t]];
    }

    float *bufA, *bufB, *pool;
    __nv_bfloat16 *Wthi, *Wtlo;
    int *rankB, *listB, *scanB, *degB, *off5, *cur5, *csrB, *cnt, *part;
    cudaGetSymbolAddress((void**)&bufA, g_bufA);
    cudaGetSymbolAddress((void**)&bufB, g_bufB);
    cudaGetSymbolAddress((void**)&pool, g_pool);
    cudaGetSymbolAddress((void**)&Wthi, g_Wthi);
    cudaGetSymbolAddress((void**)&Wtlo, g_Wtlo);
    cudaGetSymbolAddress((void**)&rankB, g_rank);
    cudaGetSymbolAddress((void**)&listB, g_list);
    cudaGetSymbolAddress((void**)&scanB, g_scan);
    cudaGetSymbolAddress((void**)&degB, g_deg);
    cudaGetSymbolAddress((void**)&off5, g_off5);
    cudaGetSymbolAddress((void**)&cur5, g_cur5);
    cudaGetSymbolAddress((void**)&csrB, g_csr);
    cudaGetSymbolAddress((void**)&cnt, g_cnt);
    cudaGetSymbolAddress((void**)&part, g_part);

    const int Nn[3] = {NBASE, NJOINT, NFOOT};
    const int Kin[3] = {6, 2, 4};
    const size_t XOFF[3] = {0, (size_t)NBASE * 128, (size_t)(NBASE + NJOINT) * 128};
    const int sT[5] = {0, 1, 1, 1, 2};
    const int dT[5] = {1, 0, 1, 2, 1};
    const int dstN[5] = {NJOINT, NBASE, NJOINT, NFOOT, NJOINT};
    const size_t POOL[10] = {0, 40000, 200000, 360000, 400000, 720000, 1040000, 1200000, 1360000, 1520000};
    const int GRIDR[10] = {313, 1250, 1250, 313, 2500, 2500, 1250, 1250, 1250, 1250};

    const int SMEM = 4 * SA * 2;  // 139264 B
    cudaFuncSetAttribute(gemm_batch_k, cudaFuncAttributeMaxDynamicSharedMemorySize, SMEM);

    // ---- once-per-call prep ----
    wprep_k<<<(40 * 16384 + 255) / 256, 256>>>(Wl, Wr, Wthi, Wtlo);
    for (int t = 0; t < 3; t++)
        encode_k<<<(Nn[t] * HDIM + 255) / 256, 256>>>(
            x_in[t], Wenc[t], benc[t], bufA + XOFF[t], Nn[t], Kin[t]);

    EL el;
    el.cumE[0] = 0;
    for (int t = 0; t < 5; t++) {
        el.src[t] = srcA[t];
        el.dst[t] = dstA[t];
        el.cumE[t + 1] = el.cumE[t] + E[t];
    }
    int Etot = el.cumE[5];
    NArr na;
    for (int ei = 0; ei < 5; ei++) {
        na.N[2 * ei] = Nn[sT[ei]];
        na.N[2 * ei + 1] = Nn[dT[ei]];
    }

    // role compaction (batched)
    cudaMemsetAsync(rankB, 0, (size_t)10 * RSTR * 4);
    mark_all_k<<<(2 * Etot + 255) / 256, 256>>>(el, Etot);
    bscan1_k<<<10 * NBLK, 1024>>>(rankB, scanB, part);
    bscan2_k<<<10, 512>>>(part);
    bscan3_k<<<10 * NBLK, 1024>>>(scanB, part);
    bcompact_k<<<(10 * RSTR + 255) / 256, 256>>>(na);
    getcnt_k<<<1, 16>>>(na);

    // CSR build (batched)
    cudaMemsetAsync(degB, 0, (size_t)5 * RSTR * 4);
    bhist_k<<<(Etot + 255) / 256, 256>>>(el, Etot);
    bscan1_k<<<5 * NBLK, 1024>>>(degB, off5, part);
    bscan2_k<<<5, 512>>>(part);
    bscan3_k<<<5 * NBLK, 1024>>>(off5, part);
    cudaMemcpyAsync(cur5, off5, (size_t)5 * RSTR * 4, cudaMemcpyDeviceToDevice);
    bfill_k<<<(Etot + 255) / 256, 256>>>(el, Etot);

    float* x = bufA;
    float* agg = bufB;

    auto makeRole = [&](int ei, int side, int l) {
        int role = 2 * ei + side;
        int po = l * 5 + ei;
        int wIdx = side ? (20 + po) : po;
        GR R;
        R.A = x + XOFF[side ? dT[ei] : sT[ei]];
        R.rowlist = listB + (size_t)role * RSTR;
        R.cntPtr = cnt + role;
        R.Bhi = Wthi + (size_t)wIdx * 16384;
        R.Blo = Wtlo + (size_t)wIdx * 16384;
        R.bias = side ? (br + (size_t)po * 128) : (bl + (size_t)po * 128);
        R.out = pool + POOL[role] * 128;
        return R;
    };
    auto edgeT = [&](int ei, int l) {
        int po = l * 5 + ei;
        EdgeT t;
        t.xl = pool + POOL[2 * ei] * 128;
        t.xr = pool + POOL[2 * ei + 1] * 128;
        t.csr = csrB + el.cumE[ei];
        t.off = off5 + (size_t)ei * RSTR;
        t.rank = rankB + (size_t)(2 * ei + 1) * RSTR;
        t.att = att + (size_t)po * 128;
        t.bias = cb + (size_t)po * 128;
        return t;
    };

    for (int l = 0; l < 4; l++) {
        bool last = (l == 3);
        bool skipJb = (l == 2);   // layer-2 base agg never consumed by layer 3

        // --- batched GEMM launch for this layer ---
        GB gb;
        int nr = 0, cum = 0;
        if (!last) {
            for (int ei = 0; ei < 5; ei++) {
                if (skipJb && ei == 1) continue;
                for (int side = 0; side < 2; side++) {
                    gb.r[nr] = makeRole(ei, side, l);
                    gb.cum[nr] = cum;
                    cum += GRIDR[2 * ei + side];
                    nr++;
                }
            }
        } else {
            for (int side = 0; side < 2; side++) {
                gb.r[nr] = makeRole(3, side, l);
                gb.cum[nr] = cum;
                cum += GRIDR[6 + side];
                nr++;
            }
        }
        gb.cum[nr] = cum;
        gb.n = nr;
        gemm_batch_k<<<cum, 256, SMEM>>>(gb);

        // --- edge kernels ---
        if (!last) {
            EdgeArgs eaJ; eaJ.t[0] = edgeT(0, l); eaJ.t[1] = edgeT(2, l); eaJ.t[2] = edgeT(4, l);
            edge_multi_k<<<(NJOINT + 7) / 8, 256>>>(eaJ, 3, agg + XOFF[1], NJOINT);
            if (!skipJb) {
                EdgeArgs eaB; eaB.t[0] = edgeT(1, l); eaB.t[1] = eaB.t[0]; eaB.t[2] = eaB.t[0];
                edge_multi_k<<<(NBASE + 7) / 8, 256>>>(eaB, 1, agg + XOFF[0], NBASE);
            }
            EdgeArgs eaF; eaF.t[0] = edgeT(3, l); eaF.t[1] = eaF.t[0]; eaF.t[2] = eaF.t[0];
            edge_multi_k<<<(NFOOT + 7) / 8, 256>>>(eaF, 1, agg + XOFF[2], NFOOT);
            float* tmp = x; x = agg; agg = tmp;
        } else {
            EdgeArgs eaF; eaF.t[0] = edgeT(3, l); eaF.t[1] = eaF.t[0]; eaF.t[2] = eaF.t[0];
            edge_multi_k<<<(NFOOT + 7) / 8, 256>>>(eaF, 1, agg + XOFF[2], NFOOT);
        }
    }

    decode_k<<<(NFOOT + 7) / 8, 256>>>(agg + XOFF[2], Wdec, bdec, (float*)d_out, NFOOT);
}

// round 8
// speedup vs baseline: 5.1810x; 1.2929x over previous
#include <cuda_runtime.h>
#include <cuda_bf16.h>
#include <math.h>

#define NBASE 40000
#define NJOINT 480000
#define NFOOT 160000
#define HDIM 128
#define NEG_SLOPE 0.2f
#define RSTR 481280      // padded per-role segment stride (= 470*1024)
#define NBLK 470         // 1024-elem scan blocks per segment

// ---------------- scratch (device globals; ~1.66 GB, linker-safe) ----------------
__device__ float g_bufA[(size_t)680000 * 128];   // x / agg ping-pong
__device__ float g_bufB[(size_t)680000 * 128];
__device__ float g_pool[(size_t)1680000 * 128];  // compact xl/xr rows, all 10 roles live
__device__ __nv_bfloat16 g_Wthi[40 * 16384];
__device__ __nv_bfloat16 g_Wtlo[40 * 16384];
__device__ int g_rank[10 * RSTR];   // per-role: mark -> compact idx (-1 unused)
__device__ int g_list[10 * RSTR];   // per-role compact idx -> node
__device__ int g_scan[10 * RSTR];
__device__ int g_deg[5 * RSTR];
__device__ int g_off5[5 * RSTR];    // CSR offsets, strided per type
__device__ int g_cur5[5 * RSTR];
__device__ int g_csr[960000];
__device__ int g_cnt[16];
__device__ int g_part[10 * 512];

// ---------------- helpers ----------------
static __device__ __forceinline__ void bf16split(float v, __nv_bfloat16& h, __nv_bfloat16& l) {
    h = __float2bfloat16(v);
    l = __float2bfloat16(v - __bfloat162float(h));
}

__global__ void wprep_k(const float* __restrict__ Wl, const float* __restrict__ Wr,
                        __nv_bfloat16* __restrict__ hi, __nv_bfloat16* __restrict__ lo) {
    int idx = blockIdx.x * 256 + threadIdx.x;
    if (idx >= 40 * 16384) return;
    int m = idx >> 14, e = idx & 16383;
    int n = e >> 7, k = e & 127;
    const float* src = (m < 20) ? (Wl + (size_t)m * 16384) : (Wr + (size_t)(m - 20) * 16384);
    float v = src[k * 128 + n];
    __nv_bfloat16 h, l;
    bf16split(v, h, l);
    hi[idx] = h; lo[idx] = l;
}

__global__ void encode_k(const float* __restrict__ x, const float* __restrict__ W,
                         const float* __restrict__ b, float* __restrict__ y, int N, int K) {
    int idx = blockIdx.x * blockDim.x + threadIdx.x;
    if (idx >= N * HDIM) return;
    int n = idx >> 7, h = idx & 127;
    float acc = b[h];
    for (int k = 0; k < K; k++) acc += x[n * K + k] * W[k * HDIM + h];
    y[idx] = fmaxf(acc, 0.f);
}

// ---------------- batched prep ----------------
struct EL {
    const int* src[5];
    const int* dst[5];
    int cumE[6];
};
struct NArr { int N[10]; };

__global__ void mark_all_k(EL el, int total) {
    int gi = blockIdx.x * 256 + threadIdx.x;
    if (gi >= 2 * total) return;
    int side = gi >= total;
    int j = gi - side * total;
    int t = 0;
    while (j >= el.cumE[t + 1]) t++;
    int e = j - el.cumE[t];
    int node = side ? el.dst[t][e] : el.src[t][e];
    g_rank[(2 * t + side) * RSTR + node] = 1;
}

__global__ void bscan1_k(const int* __restrict__ v, int* __restrict__ out,
                         int* __restrict__ part) {
    __shared__ int sh[1024];
    int r = blockIdx.x / NBLK, j = blockIdx.x % NBLK;
    int i = r * RSTR + j * 1024 + threadIdx.x;
    int val = v[i];
    sh[threadIdx.x] = val;
    __syncthreads();
#pragma unroll
    for (int o = 1; o < 1024; o <<= 1) {
        int t = (threadIdx.x >= o) ? sh[threadIdx.x - o] : 0;
        __syncthreads();
        sh[threadIdx.x] += t;
        __syncthreads();
    }
    int incl = sh[threadIdx.x];
    out[i] = incl - val;
    if (threadIdx.x == 1023) part[r * 512 + j] = incl;
}
__global__ void bscan2_k(int* part) {
    __shared__ int sh[512];
    int r = blockIdx.x;
    int v = (threadIdx.x < NBLK) ? part[r * 512 + threadIdx.x] : 0;
    sh[threadIdx.x] = v;
    __syncthreads();
#pragma unroll
    for (int o = 1; o < 512; o <<= 1) {
        int t = (threadIdx.x >= o) ? sh[threadIdx.x - o] : 0;
        __syncthreads();
        sh[threadIdx.x] += t;
        __syncthreads();
    }
    if (threadIdx.x < NBLK) part[r * 512 + threadIdx.x] = sh[threadIdx.x] - v;
}
__global__ void bscan3_k(int* __restrict__ out, const int* __restrict__ part) {
    int r = blockIdx.x / NBLK, j = blockIdx.x % NBLK;
    int i = r * RSTR + j * 1024 + threadIdx.x;
    out[i] += part[r * 512 + j];
}

__global__ void bcompact_k(NArr na) {
    int i = blockIdx.x * 256 + threadIdx.x;
    if (i >= 10 * RSTR) return;
    int r = i / RSTR, li = i % RSTR;
    if (li >= na.N[r]) return;
    if (g_rank[i]) {
        int pos = g_scan[i];
        g_list[r * RSTR + pos] = li;
        g_rank[i] = pos;
    } else {
        g_rank[i] = -1;
    }
}
__global__ void getcnt_k(NArr na) {
    int r = threadIdx.x;
    if (r < 10) g_cnt[r] = g_scan[r * RSTR + na.N[r]];
}

__global__ void bhist_k(EL el, int total) {
    int j = blockIdx.x * 256 + threadIdx.x;
    if (j >= total) return;
    int t = 0;
    while (j >= el.cumE[t + 1]) t++;
    int e = j - el.cumE[t];
    atomicAdd(&g_deg[t * RSTR + el.dst[t][e]], 1);
}
__global__ void bfill_k(EL el, int total) {
    int j = blockIdx.x * 256 + threadIdx.x;
    if (j >= total) return;
    int t = 0;
    while (j >= el.cumE[t + 1]) t++;
    int e = j - el.cumE[t];
    int d = el.dst[t][e];
    int p = atomicAdd(&g_cur5[t * RSTR + d], 1);
    g_csr[el.cumE[t] + p] = g_rank[(2 * t) * RSTR + el.src[t][e]];
}

// ---------------- batched gather-GEMM (M-tile 64, dual-CTA occupancy) ----------------
#define SAE 8704    // 64*136 bf16 elems (A matrix)
#define SBE 17408   // 128*136 bf16 elems (B matrix)
// smem: [Ahi SAE][Alo SAE][Bhi SBE][Blo SBE] = 52224 elems = 104448 B -> 2 CTAs/SM

#define LDSM4(R, addr) asm volatile( \
    "ldmatrix.sync.aligned.m8n8.x4.shared.b16 {%0,%1,%2,%3}, [%4];" \
    : "=r"((R)[0]), "=r"((R)[1]), "=r"((R)[2]), "=r"((R)[3]) : "r"(addr))

#define MMA16816(C, A, b0, b1) asm volatile( \
    "mma.sync.aligned.m16n8k16.row.col.f32.bf16.bf16.f32 " \
    "{%0,%1,%2,%3},{%4,%5,%6,%7},{%8,%9},{%0,%1,%2,%3};" \
    : "+f"((C)[0]), "+f"((C)[1]), "+f"((C)[2]), "+f"((C)[3]) \
    : "r"((A)[0]), "r"((A)[1]), "r"((A)[2]), "r"((A)[3]), "r"(b0), "r"(b1))

static __device__ __forceinline__ void cpasync16(unsigned dst, const void* src, int sz) {
    asm volatile("cp.async.cg.shared.global [%0], [%1], 16, %2;" :: "r"(dst), "l"(src), "r"(sz));
}

struct GR {
    const float* A;
    const int* rowlist;
    const int* cntPtr;
    const __nv_bfloat16* Bhi;
    const __nv_bfloat16* Blo;
    const float* bias;
    float* out;
};
struct GB { GR r[10]; int cum[11]; int n; };

__global__ void __launch_bounds__(256, 2) gemm_batch_k(GB gb) {
    int b = blockIdx.x;
    int k = 0;
    while (k < gb.n - 1 && b >= gb.cum[k + 1]) k++;
    GR R = gb.r[k];
    const int cnt = *R.cntPtr;
    const int row0 = (b - gb.cum[k]) * 64;
    if (row0 >= cnt) return;

    extern __shared__ __nv_bfloat16 smem[];
    const int tid = threadIdx.x;
    unsigned sAhi = (unsigned)__cvta_generic_to_shared(smem);
    unsigned sB = sAhi + 2 * SAE * 2;

    // 1) B hi/lo via cp.async FIRST (overlaps with A's ld.global below)
#pragma unroll
    for (int i = 0; i < 8; i++) {
        int chunk = tid + i * 256;          // 2048 chunks of 8 bf16
        int row = chunk >> 4;
        int col = (chunk & 15) * 8;
        size_t off = (size_t)row * 128 + col;
        unsigned d = sB + (unsigned)(row * 136 + col) * 2;
        cpasync16(d, R.Bhi + off, 16);
        cpasync16(d + SBE * 2, R.Blo + off, 16);
    }
    asm volatile("cp.async.commit_group;");

    // 2) A: gather fp32 rows -> relu -> bf16 hi/lo split -> smem (64 rows x 128)
#pragma unroll
    for (int i = 0; i < 8; i++) {
        int chunk = tid + i * 256;          // 2048 float4 chunks (64 rows x 32)
        int row = chunk >> 5;
        int c4 = (chunk & 31) * 4;
        int ok = (row0 + row) < cnt;
        int node = ok ? R.rowlist[row0 + row] : 0;
        float4 v = ok ? *(const float4*)(R.A + (size_t)node * 128 + c4)
                      : make_float4(0.f, 0.f, 0.f, 0.f);
        v.x = fmaxf(v.x, 0.f); v.y = fmaxf(v.y, 0.f);
        v.z = fmaxf(v.z, 0.f); v.w = fmaxf(v.w, 0.f);
        __nv_bfloat16 h0, l0, h1, l1, h2, l2, h3, l3;
        bf16split(v.x, h0, l0); bf16split(v.y, h1, l1);
        bf16split(v.z, h2, l2); bf16split(v.w, h3, l3);
        int base = row * 136 + c4;
        *(__nv_bfloat162*)(smem + base)           = __nv_bfloat162(h0, h1);
        *(__nv_bfloat162*)(smem + base + 2)       = __nv_bfloat162(h2, h3);
        *(__nv_bfloat162*)(smem + SAE + base)     = __nv_bfloat162(l0, l1);
        *(__nv_bfloat162*)(smem + SAE + base + 2) = __nv_bfloat162(l2, l3);
    }
    asm volatile("cp.async.wait_group 0;");
    __syncthreads();

    // 3) MMA: 8 warps as 2M x 4N (each warp 32 rows x 32 cols)
    int warp = tid >> 5, lane = tid & 31;
    int m0 = (warp >> 2) * 32;
    int n0 = (warp & 3) * 32;
    int frow = lane & 15;
    int fcolo = (lane >> 4) * 8;

    float acc[2][4][4];
#pragma unroll
    for (int a = 0; a < 2; a++)
#pragma unroll
        for (int c = 0; c < 4; c++)
#pragma unroll
            for (int r = 0; r < 4; r++) acc[a][c][r] = 0.f;

    for (int ks = 0; ks < 8; ks++) {
        int acol = ks * 16 + fcolo;
        unsigned ah[2][4], al[2][4];
#pragma unroll
        for (int mt = 0; mt < 2; mt++) {
            unsigned ad = sAhi + (unsigned)((m0 + mt * 16 + frow) * 136 + acol) * 2;
            LDSM4(ah[mt], ad);
            LDSM4(al[mt], ad + SAE * 2);
        }
        unsigned bh[2][4], blx[2][4];
#pragma unroll
        for (int p = 0; p < 2; p++) {
            unsigned bd = sB + (unsigned)((n0 + p * 16 + frow) * 136 + acol) * 2;
            LDSM4(bh[p], bd);
            LDSM4(blx[p], bd + SBE * 2);
        }
#pragma unroll
        for (int mt = 0; mt < 2; mt++)
#pragma unroll
            for (int nt = 0; nt < 4; nt++) {
                int p = nt >> 1, o = nt & 1;
                MMA16816(acc[mt][nt], ah[mt], bh[p][o], bh[p][2 + o]);
                MMA16816(acc[mt][nt], ah[mt], blx[p][o], blx[p][2 + o]);
                MMA16816(acc[mt][nt], al[mt], bh[p][o], bh[p][2 + o]);
            }
    }

    int crow = lane >> 2, ccol = (lane & 3) * 2;
#pragma unroll
    for (int nt = 0; nt < 4; nt++) {
        int col = n0 + nt * 8 + ccol;
        float b0v = R.bias[col], b1v = R.bias[col + 1];
#pragma unroll
        for (int mt = 0; mt < 2; mt++) {
            int r = row0 + m0 + mt * 16 + crow;
            if (r < cnt)
                *(float2*)(R.out + (size_t)r * 128 + col) =
                    make_float2(acc[mt][nt][0] + b0v, acc[mt][nt][1] + b1v);
            if (r + 8 < cnt)
                *(float2*)(R.out + (size_t)(r + 8) * 128 + col) =
                    make_float2(acc[mt][nt][2] + b0v, acc[mt][nt][3] + b1v);
        }
    }
}

// ---------------- fused multi-type edge kernel ----------------
struct EdgeT {
    const float* xl;
    const float* xr;
    const int* csr;
    const int* off;
    const int* rank;
    const float* att;
    const float* bias;
};
struct EdgeArgs { EdgeT t[3]; };

__global__ void edge_multi_k(EdgeArgs ea, int nt, float* __restrict__ agg, int Nd) {
    int d = blockIdx.x * 8 + (threadIdx.x >> 5);
    if (d >= Nd) return;
    int lane = threadIdx.x & 31;
    float4 r = make_float4(0.f, 0.f, 0.f, 0.f);
    for (int k = 0; k < nt; k++) {
        const EdgeT& t = ea.t[k];
        float4 bb = ((const float4*)t.bias)[lane];
        r.x += bb.x; r.y += bb.y; r.z += bb.z; r.w += bb.w;
        int s0 = t.off[d], s1 = t.off[d + 1];
        if (s1 > s0) {
            int cr = t.rank[d];
            float4 xr4 = ((const float4*)(t.xr + (size_t)cr * 128))[lane];
            float4 at = ((const float4*)t.att)[lane];
            float m = -INFINITY, den = 0.f;
            float a0 = 0.f, a1 = 0.f, a2 = 0.f, a3 = 0.f;
            for (int e = s0; e < s1; e++) {
                int si = t.csr[e];
                float4 xv = ((const float4*)(t.xl + (size_t)si * 128))[lane];
                float t0 = xv.x + xr4.x, t1 = xv.y + xr4.y, t2 = xv.z + xr4.z, t3 = xv.w + xr4.w;
                t0 = t0 > 0.f ? t0 : NEG_SLOPE * t0;
                t1 = t1 > 0.f ? t1 : NEG_SLOPE * t1;
                t2 = t2 > 0.f ? t2 : NEG_SLOPE * t2;
                t3 = t3 > 0.f ? t3 : NEG_SLOPE * t3;
                float p = t0 * at.x + t1 * at.y + t2 * at.z + t3 * at.w;
#pragma unroll
                for (int o = 16; o; o >>= 1) p += __shfl_xor_sync(0xffffffffu, p, o);
                float mn = fmaxf(m, p);
                float corr = __expf(m - mn);
                float w = __expf(p - mn);
                den = den * corr + w;
                a0 = a0 * corr + w * xv.x;
                a1 = a1 * corr + w * xv.y;
                a2 = a2 * corr + w * xv.z;
                a3 = a3 * corr + w * xv.w;
                m = mn;
            }
            float inv = 1.f / den;
            r.x += a0 * inv; r.y += a1 * inv; r.z += a2 * inv; r.w += a3 * inv;
        }
    }
    *(float4*)(agg + (size_t)d * 128 + lane * 4) = r;
}

// ---------------- decoder with fused relu ----------------
__global__ void decode_k(const float* __restrict__ agg, const float* __restrict__ W,
                         const float* __restrict__ b, float* __restrict__ out, int N) {
    int f = blockIdx.x * 8 + (threadIdx.x >> 5);
    if (f >= N) return;
    int lane = threadIdx.x & 31;
    float4 v = ((const float4*)(agg + (size_t)f * 128))[lane];
    v.x = fmaxf(v.x, 0.f); v.y = fmaxf(v.y, 0.f); v.z = fmaxf(v.z, 0.f); v.w = fmaxf(v.w, 0.f);
    int h = lane * 4;
    float s0 = v.x * W[(h + 0) * 3 + 0] + v.y * W[(h + 1) * 3 + 0] + v.z * W[(h + 2) * 3 + 0] + v.w * W[(h + 3) * 3 + 0];
    float s1 = v.x * W[(h + 0) * 3 + 1] + v.y * W[(h + 1) * 3 + 1] + v.z * W[(h + 2) * 3 + 1] + v.w * W[(h + 3) * 3 + 1];
    float s2 = v.x * W[(h + 0) * 3 + 2] + v.y * W[(h + 1) * 3 + 2] + v.z * W[(h + 2) * 3 + 2] + v.w * W[(h + 3) * 3 + 2];
#pragma unroll
    for (int o = 16; o; o >>= 1) {
        s0 += __shfl_xor_sync(0xffffffffu, s0, o);
        s1 += __shfl_xor_sync(0xffffffffu, s1, o);
        s2 += __shfl_xor_sync(0xffffffffu, s2, o);
    }
    if (lane == 0) {
        out[f * 3 + 0] = s0 + b[0];
        out[f * 3 + 1] = s1 + b[1];
        out[f * 3 + 2] = s2 + b[2];
    }
}

// ---------------- host orchestration ----------------
extern "C" void kernel_launch(void* const* d_in, const int* in_sizes, int n_in,
                              void* d_out, int out_size) {
    int I[27];
    if (in_sizes[1] == 768) {
        const int m[27] = {0, 3, 6, 1, 2, 4, 5, 7, 8,
                           19, 20, 21, 22, 23, 24, 25, 26,
                           9, 10, 11, 12, 13, 14, 15, 16, 17, 18};
        for (int i = 0; i < 27; i++) I[i] = m[i];
    } else {
        for (int i = 0; i < 27; i++) I[i] = i;
    }

    const float* x_in[3] = {(const float*)d_in[I[0]], (const float*)d_in[I[1]], (const float*)d_in[I[2]]};
    const float* Wenc[3] = {(const float*)d_in[I[3]], (const float*)d_in[I[5]], (const float*)d_in[I[7]]};
    const float* benc[3] = {(const float*)d_in[I[4]], (const float*)d_in[I[6]], (const float*)d_in[I[8]]};
    const float* Wl = (const float*)d_in[I[9]];
    const float* bl = (const float*)d_in[I[10]];
    const float* Wr = (const float*)d_in[I[11]];
    const float* br = (const float*)d_in[I[12]];
    const float* att = (const float*)d_in[I[13]];
    const float* cb = (const float*)d_in[I[14]];
    const float* Wdec = (const float*)d_in[I[15]];
    const float* bdec = (const float*)d_in[I[16]];
    const int *srcA[5], *dstA[5];
    int E[5];
    for (int t = 0; t < 5; t++) {
        srcA[t] = (const int*)d_in[I[17 + 2 * t]];
        dstA[t] = (const int*)d_in[I[18 + 2 * t]];
        E[t] = in_sizes[I[17 + 2 * t]];
    }

    float *bufA, *bufB, *pool;
    __nv_bfloat16 *Wthi, *Wtlo;
    int *rankB, *listB, *scanB, *degB, *off5, *cur5, *csrB, *cnt, *part;
    cudaGetSymbolAddress((void**)&bufA, g_bufA);
    cudaGetSymbolAddress((void**)&bufB, g_bufB);
    cudaGetSymbolAddress((void**)&pool, g_pool);
    cudaGetSymbolAddress((void**)&Wthi, g_Wthi);
    cudaGetSymbolAddress((void**)&Wtlo, g_Wtlo);
    cudaGetSymbolAddress((void**)&rankB, g_rank);
    cudaGetSymbolAddress((void**)&listB, g_list);
    cudaGetSymbolAddress((void**)&scanB, g_scan);
    cudaGetSymbolAddress((void**)&degB, g_deg);
    cudaGetSymbolAddress((void**)&off5, g_off5);
    cudaGetSymbolAddress((void**)&cur5, g_cur5);
    cudaGetSymbolAddress((void**)&csrB, g_csr);
    cudaGetSymbolAddress((void**)&cnt, g_cnt);
    cudaGetSymbolAddress((void**)&part, g_part);

    const int Nn[3] = {NBASE, NJOINT, NFOOT};
    const int Kin[3] = {6, 2, 4};
    const size_t XOFF[3] = {0, (size_t)NBASE * 128, (size_t)(NBASE + NJOINT) * 128};
    const int sT[5] = {0, 1, 1, 1, 2};
    const int dT[5] = {1, 0, 1, 2, 1};
    const size_t POOL[10] = {0, 40000, 200000, 360000, 400000, 720000, 1040000, 1200000, 1360000, 1520000};
    // 64-row tiles; per-role bound = min(node count, edge count)
    const int GRIDR[10] = {625, 2500, 2500, 625, 5000, 5000, 2500, 2500, 2500, 2500};

    const int SMEM = (2 * SAE + 2 * SBE) * 2;   // 104448 B -> 2 CTAs/SM
    cudaFuncSetAttribute(gemm_batch_k, cudaFuncAttributeMaxDynamicSharedMemorySize, SMEM);

    // ---- once-per-call prep ----
    wprep_k<<<(40 * 16384 + 255) / 256, 256>>>(Wl, Wr, Wthi, Wtlo);
    for (int t = 0; t < 3; t++)
        encode_k<<<(Nn[t] * HDIM + 255) / 256, 256>>>(
            x_in[t], Wenc[t], benc[t], bufA + XOFF[t], Nn[t], Kin[t]);

    EL el;
    el.cumE[0] = 0;
    for (int t = 0; t < 5; t++) {
        el.src[t] = srcA[t];
        el.dst[t] = dstA[t];
        el.cumE[t + 1] = el.cumE[t] + E[t];
    }
    int Etot = el.cumE[5];
    NArr na;
    for (int ei = 0; ei < 5; ei++) {
        na.N[2 * ei] = Nn[sT[ei]];
        na.N[2 * ei + 1] = Nn[dT[ei]];
    }

    // role compaction (batched)
    cudaMemsetAsync(rankB, 0, (size_t)10 * RSTR * 4);
    mark_all_k<<<(2 * Etot + 255) / 256, 256>>>(el, Etot);
    bscan1_k<<<10 * NBLK, 1024>>>(rankB, scanB, part);
    bscan2_k<<<10, 512>>>(part);
    bscan3_k<<<10 * NBLK, 1024>>>(scanB, part);
    bcompact_k<<<(10 * RSTR + 255) / 256, 256>>>(na);
    getcnt_k<<<1, 16>>>(na);

    // CSR build (batched)
    cudaMemsetAsync(degB, 0, (size_t)5 * RSTR * 4);
    bhist_k<<<(Etot + 255) / 256, 256>>>(el, Etot);
    bscan1_k<<<5 * NBLK, 1024>>>(degB, off5, part);
    bscan2_k<<<5, 512>>>(part);
    bscan3_k<<<5 * NBLK, 1024>>>(off5, part);
    cudaMemcpyAsync(cur5, off5, (size_t)5 * RSTR * 4, cudaMemcpyDeviceToDevice);
    bfill_k<<<(Etot + 255) / 256, 256>>>(el, Etot);

    float* x = bufA;
    float* agg = bufB;

    auto makeRole = [&](int ei, int side, int l) {
        int role = 2 * ei + side;
        int po = l * 5 + ei;
        int wIdx = side ? (20 + po) : po;
        GR R;
        R.A = x + XOFF[side ? dT[ei] : sT[ei]];
        R.rowlist = listB + (size_t)role * RSTR;
        R.cntPtr = cnt + role;
        R.Bhi = Wthi + (size_t)wIdx * 16384;
        R.Blo = Wtlo + (size_t)wIdx * 16384;
        R.bias = side ? (br + (size_t)po * 128) : (bl + (size_t)po * 128);
        R.out = pool + POOL[role] * 128;
        return R;
    };
    auto edgeT = [&](int ei, int l) {
        int po = l * 5 + ei;
        EdgeT t;
        t.xl = pool + POOL[2 * ei] * 128;
        t.xr = pool + POOL[2 * ei + 1] * 128;
        t.csr = csrB + el.cumE[ei];
        t.off = off5 + (size_t)ei * RSTR;
        t.rank = rankB + (size_t)(2 * ei + 1) * RSTR;
        t.att = att + (size_t)po * 128;
        t.bias = cb + (size_t)po * 128;
        return t;
    };

    for (int l = 0; l < 4; l++) {
        bool last = (l == 3);
        bool skipJb = (l == 2);   // layer-2 base agg never consumed by layer 3

        GB gb;
        int nr = 0, cum = 0;
        if (!last) {
            for (int ei = 0; ei < 5; ei++) {
                if (skipJb && ei == 1) continue;
                for (int side = 0; side < 2; side++) {
                    gb.r[nr] = makeRole(ei, side, l);
                    gb.cum[nr] = cum;
                    cum += GRIDR[2 * ei + side];
                    nr++;
                }
            }
        } else {
            for (int side = 0; side < 2; side++) {
                gb.r[nr] = makeRole(3, side, l);
                gb.cum[nr] = cum;
                cum += GRIDR[6 + side];
                nr++;
            }
        }
        gb.cum[nr] = cum;
        gb.n = nr;
        gemm_batch_k<<<cum, 256, SMEM>>>(gb);

        if (!last) {
            EdgeArgs eaJ; eaJ.t[0] = edgeT(0, l); eaJ.t[1] = edgeT(2, l); eaJ.t[2] = edgeT(4, l);
            edge_multi_k<<<(NJOINT + 7) / 8, 256>>>(eaJ, 3, agg + XOFF[1], NJOINT);
            if (!skipJb) {
                EdgeArgs eaB; eaB.t[0] = edgeT(1, l); eaB.t[1] = eaB.t[0]; eaB.t[2] = eaB.t[0];
                edge_multi_k<<<(NBASE + 7) / 8, 256>>>(eaB, 1, agg + XOFF[0], NBASE);
            }
            EdgeArgs eaF; eaF.t[0] = edgeT(3, l); eaF.t[1] = eaF.t[0]; eaF.t[2] = eaF.t[0];
            edge_multi_k<<<(NFOOT + 7) / 8, 256>>>(eaF, 1, agg + XOFF[2], NFOOT);
            float* tmp = x; x = agg; agg = tmp;
        } else {
            EdgeArgs eaF; eaF.t[0] = edgeT(3, l); eaF.t[1] = eaF.t[0]; eaF.t[2] = eaF.t[0];
            edge_multi_k<<<(NFOOT + 7) / 8, 256>>>(eaF, 1, agg + XOFF[2], NFOOT);
        }
    }

    decode_k<<<(NFOOT + 7) / 8, 256>>>(agg + XOFF[2], Wdec, bdec, (float*)d_out, NFOOT);
}

// round 9
// speedup vs baseline: 5.4108x; 1.0444x over previous
#include <cuda_runtime.h>
#include <cuda_bf16.h>
#include <cuda_fp16.h>
#include <math.h>

#define NBASE 40000
#define NJOINT 480000
#define NFOOT 160000
#define HDIM 128
#define NEG_SLOPE 0.2f
#define RSTR 481280      // padded per-role segment stride (= 470*1024)
#define NBLK 470         // 1024-elem scan blocks per segment

// ---------------- scratch (device globals; ~1.0 GB, linker-safe) ----------------
__device__ __half g_bufA[(size_t)680000 * 128];   // x / agg ping-pong (fp16 storage)
__device__ __half g_bufB[(size_t)680000 * 128];
__device__ __half g_pool[(size_t)1680000 * 128];  // compact xl/xr rows (fp16)
__device__ __nv_bfloat16 g_Wthi[40 * 16384];
__device__ __nv_bfloat16 g_Wtlo[40 * 16384];
__device__ int g_rank[10 * RSTR];
__device__ int g_list[10 * RSTR];
__device__ int g_scan[10 * RSTR];
__device__ int g_deg[5 * RSTR];
__device__ int g_off5[5 * RSTR];
__device__ int g_cur5[5 * RSTR];
__device__ int g_csr[960000];
__device__ int g_cnt[16];
__device__ int g_part[10 * 512];

// ---------------- helpers ----------------
static __device__ __forceinline__ void bf16split(float v, __nv_bfloat16& h, __nv_bfloat16& l) {
    h = __float2bfloat16(v);
    l = __float2bfloat16(v - __bfloat162float(h));
}

__global__ void wprep_k(const float* __restrict__ Wl, const float* __restrict__ Wr,
                        __nv_bfloat16* __restrict__ hi, __nv_bfloat16* __restrict__ lo) {
    int idx = blockIdx.x * 256 + threadIdx.x;
    if (idx >= 40 * 16384) return;
    int m = idx >> 14, e = idx & 16383;
    int n = e >> 7, k = e & 127;
    const float* src = (m < 20) ? (Wl + (size_t)m * 16384) : (Wr + (size_t)(m - 20) * 16384);
    float v = src[k * 128 + n];
    __nv_bfloat16 h, l;
    bf16split(v, h, l);
    hi[idx] = h; lo[idx] = l;
}

__global__ void encode_k(const float* __restrict__ x, const float* __restrict__ W,
                         const float* __restrict__ b, __half* __restrict__ y, int N, int K) {
    int idx = blockIdx.x * blockDim.x + threadIdx.x;
    if (idx >= N * HDIM) return;
    int n = idx >> 7, h = idx & 127;
    float acc = b[h];
    for (int k = 0; k < K; k++) acc += x[n * K + k] * W[k * HDIM + h];
    y[idx] = __float2half(fmaxf(acc, 0.f));
}

// ---------------- batched prep ----------------
struct EL {
    const int* src[5];
    const int* dst[5];
    int cumE[6];
};
struct NArr { int N[10]; };

__global__ void mark_all_k(EL el, int total) {
    int gi = blockIdx.x * 256 + threadIdx.x;
    if (gi >= 2 * total) return;
    int side = gi >= total;
    int j = gi - side * total;
    int t = 0;
    while (j >= el.cumE[t + 1]) t++;
    int e = j - el.cumE[t];
    int node = side ? el.dst[t][e] : el.src[t][e];
    g_rank[(2 * t + side) * RSTR + node] = 1;
}

__global__ void bscan1_k(const int* __restrict__ v, int* __restrict__ out,
                         int* __restrict__ part) {
    __shared__ int sh[1024];
    int r = blockIdx.x / NBLK, j = blockIdx.x % NBLK;
    int i = r * RSTR + j * 1024 + threadIdx.x;
    int val = v[i];
    sh[threadIdx.x] = val;
    __syncthreads();
#pragma unroll
    for (int o = 1; o < 1024; o <<= 1) {
        int t = (threadIdx.x >= o) ? sh[threadIdx.x - o] : 0;
        __syncthreads();
        sh[threadIdx.x] += t;
        __syncthreads();
    }
    int incl = sh[threadIdx.x];
    out[i] = incl - val;
    if (threadIdx.x == 1023) part[r * 512 + j] = incl;
}
__global__ void bscan2_k(int* part) {
    __shared__ int sh[512];
    int r = blockIdx.x;
    int v = (threadIdx.x < NBLK) ? part[r * 512 + threadIdx.x] : 0;
    sh[threadIdx.x] = v;
    __syncthreads();
#pragma unroll
    for (int o = 1; o < 512; o <<= 1) {
        int t = (threadIdx.x >= o) ? sh[threadIdx.x - o] : 0;
        __syncthreads();
        sh[threadIdx.x] += t;
        __syncthreads();
    }
    if (threadIdx.x < NBLK) part[r * 512 + threadIdx.x] = sh[threadIdx.x] - v;
}
__global__ void bscan3_k(int* __restrict__ out, const int* __restrict__ part) {
    int r = blockIdx.x / NBLK, j = blockIdx.x % NBLK;
    int i = r * RSTR + j * 1024 + threadIdx.x;
    out[i] += part[r * 512 + j];
}

__global__ void bcompact_k(NArr na) {
    int i = blockIdx.x * 256 + threadIdx.x;
    if (i >= 10 * RSTR) return;
    int r = i / RSTR, li = i % RSTR;
    if (li >= na.N[r]) return;
    if (g_rank[i]) {
        int pos = g_scan[i];
        g_list[r * RSTR + pos] = li;
        g_rank[i] = pos;
    } else {
        g_rank[i] = -1;
    }
}
__global__ void getcnt_k(NArr na) {
    int r = threadIdx.x;
    if (r < 10) g_cnt[r] = g_scan[r * RSTR + na.N[r]];
}

__global__ void bhist_k(EL el, int total) {
    int j = blockIdx.x * 256 + threadIdx.x;
    if (j >= total) return;
    int t = 0;
    while (j >= el.cumE[t + 1]) t++;
    int e = j - el.cumE[t];
    atomicAdd(&g_deg[t * RSTR + el.dst[t][e]], 1);
}
__global__ void bfill_k(EL el, int total) {
    int j = blockIdx.x * 256 + threadIdx.x;
    if (j >= total) return;
    int t = 0;
    while (j >= el.cumE[t + 1]) t++;
    int e = j - el.cumE[t];
    int d = el.dst[t][e];
    int p = atomicAdd(&g_cur5[t * RSTR + d], 1);
    g_csr[el.cumE[t] + p] = g_rank[(2 * t) * RSTR + el.src[t][e]];
}

// ---------------- batched gather-GEMM (M-tile 64, dual-CTA, fp16 I/O) ----------------
#define SAE 8704    // 64*136 bf16 elems (A matrix)
#define SBE 17408   // 128*136 bf16 elems (B matrix)

#define LDSM4(R, addr) asm volatile( \
    "ldmatrix.sync.aligned.m8n8.x4.shared.b16 {%0,%1,%2,%3}, [%4];" \
    : "=r"((R)[0]), "=r"((R)[1]), "=r"((R)[2]), "=r"((R)[3]) : "r"(addr))

#define MMA16816(C, A, b0, b1) asm volatile( \
    "mma.sync.aligned.m16n8k16.row.col.f32.bf16.bf16.f32 " \
    "{%0,%1,%2,%3},{%4,%5,%6,%7},{%8,%9},{%0,%1,%2,%3};" \
    : "+f"((C)[0]), "+f"((C)[1]), "+f"((C)[2]), "+f"((C)[3]) \
    : "r"((A)[0]), "r"((A)[1]), "r"((A)[2]), "r"((A)[3]), "r"(b0), "r"(b1))

static __device__ __forceinline__ void cpasync16(unsigned dst, const void* src, int sz) {
    asm volatile("cp.async.cg.shared.global [%0], [%1], 16, %2;" :: "r"(dst), "l"(src), "r"(sz));
}

struct GR {
    const __half* A;
    const int* rowlist;
    const int* cntPtr;
    const __nv_bfloat16* Bhi;
    const __nv_bfloat16* Blo;
    const float* bias;
    __half* out;
};
struct GB { GR r[10]; int cum[11]; int n; };

__global__ void __launch_bounds__(256, 2) gemm_batch_k(GB gb) {
    int b = blockIdx.x;
    int k = 0;
    while (k < gb.n - 1 && b >= gb.cum[k + 1]) k++;
    GR R = gb.r[k];
    const int cnt = *R.cntPtr;
    const int row0 = (b - gb.cum[k]) * 64;
    if (row0 >= cnt) return;

    extern __shared__ __nv_bfloat16 smem[];
    const int tid = threadIdx.x;
    unsigned sAhi = (unsigned)__cvta_generic_to_shared(smem);
    unsigned sB = sAhi + 2 * SAE * 2;

    // 1) B hi/lo via cp.async FIRST
#pragma unroll
    for (int i = 0; i < 8; i++) {
        int chunk = tid + i * 256;
        int row = chunk >> 4;
        int col = (chunk & 15) * 8;
        size_t off = (size_t)row * 128 + col;
        unsigned d = sB + (unsigned)(row * 136 + col) * 2;
        cpasync16(d, R.Bhi + off, 16);
        cpasync16(d + SBE * 2, R.Blo + off, 16);
    }
    asm volatile("cp.async.commit_group;");

    // 2) A: gather fp16 rows -> relu -> bf16 hi/lo split -> smem (64 rows x 128)
#pragma unroll
    for (int i = 0; i < 4; i++) {
        int chunk = tid + i * 256;          // 1024 chunks of 8 halves (16 B)
        int row = chunk >> 4;
        int c8 = (chunk & 15) * 8;
        int ok = (row0 + row) < cnt;
        int node = ok ? R.rowlist[row0 + row] : 0;
        uint4 raw = ok ? *(const uint4*)(R.A + (size_t)node * 128 + c8)
                       : make_uint4(0u, 0u, 0u, 0u);
        const __half2* hp = (const __half2*)&raw;
        int base = row * 136 + c8;
#pragma unroll
        for (int q = 0; q < 4; q++) {
            float2 f = __half22float2(hp[q]);
            f.x = fmaxf(f.x, 0.f);
            f.y = fmaxf(f.y, 0.f);
            __nv_bfloat16 h0, l0, h1, l1;
            bf16split(f.x, h0, l0);
            bf16split(f.y, h1, l1);
            *(__nv_bfloat162*)(smem + base + 2 * q)       = __nv_bfloat162(h0, h1);
            *(__nv_bfloat162*)(smem + SAE + base + 2 * q) = __nv_bfloat162(l0, l1);
        }
    }
    asm volatile("cp.async.wait_group 0;");
    __syncthreads();

    // 3) MMA: 8 warps as 2M x 4N
    int warp = tid >> 5, lane = tid & 31;
    int m0 = (warp >> 2) * 32;
    int n0 = (warp & 3) * 32;
    int frow = lane & 15;
    int fcolo = (lane >> 4) * 8;

    float acc[2][4][4];
#pragma unroll
    for (int a = 0; a < 2; a++)
#pragma unroll
        for (int c = 0; c < 4; c++)
#pragma unroll
            for (int r = 0; r < 4; r++) acc[a][c][r] = 0.f;

    for (int ks = 0; ks < 8; ks++) {
        int acol = ks * 16 + fcolo;
        unsigned ah[2][4], al[2][4];
#pragma unroll
        for (int mt = 0; mt < 2; mt++) {
            unsigned ad = sAhi + (unsigned)((m0 + mt * 16 + frow) * 136 + acol) * 2;
            LDSM4(ah[mt], ad);
            LDSM4(al[mt], ad + SAE * 2);
        }
        unsigned bh[2][4], blx[2][4];
#pragma unroll
        for (int p = 0; p < 2; p++) {
            unsigned bd = sB + (unsigned)((n0 + p * 16 + frow) * 136 + acol) * 2;
            LDSM4(bh[p], bd);
            LDSM4(blx[p], bd + SBE * 2);
        }
#pragma unroll
        for (int mt = 0; mt < 2; mt++)
#pragma unroll
            for (int nt = 0; nt < 4; nt++) {
                int p = nt >> 1, o = nt & 1;
                MMA16816(acc[mt][nt], ah[mt], bh[p][o], bh[p][2 + o]);
                MMA16816(acc[mt][nt], ah[mt], blx[p][o], blx[p][2 + o]);
                MMA16816(acc[mt][nt], al[mt], bh[p][o], bh[p][2 + o]);
            }
    }

    // epilogue: bias + fp16 store
    int crow = lane >> 2, ccol = (lane & 3) * 2;
#pragma unroll
    for (int nt = 0; nt < 4; nt++) {
        int col = n0 + nt * 8 + ccol;
        float b0v = R.bias[col], b1v = R.bias[col + 1];
#pragma unroll
        for (int mt = 0; mt < 2; mt++) {
            int r = row0 + m0 + mt * 16 + crow;
            if (r < cnt)
                *(__half2*)(R.out + (size_t)r * 128 + col) =
                    __floats2half2_rn(acc[mt][nt][0] + b0v, acc[mt][nt][1] + b1v);
            if (r + 8 < cnt)
                *(__half2*)(R.out + (size_t)(r + 8) * 128 + col) =
                    __floats2half2_rn(acc[mt][nt][2] + b0v, acc[mt][nt][3] + b1v);
        }
    }
}

// ---------------- fused multi-type edge kernel (fp16 I/O, fp32 math) ----------------
struct EdgeT {
    const __half* xl;
    const __half* xr;
    const int* csr;
    const int* off;
    const int* rank;
    const float* att;
    const float* bias;
};
struct EdgeArgs { EdgeT t[3]; };

static __device__ __forceinline__ float4 ldh4(const __half* p) {
    uint2 raw = *(const uint2*)p;
    const __half2* hp = (const __half2*)&raw;
    float2 a = __half22float2(hp[0]);
    float2 b = __half22float2(hp[1]);
    return make_float4(a.x, a.y, b.x, b.y);
}

__global__ void edge_multi_k(EdgeArgs ea, int nt, __half* __restrict__ agg, int Nd) {
    int d = blockIdx.x * 8 + (threadIdx.x >> 5);
    if (d >= Nd) return;
    int lane = threadIdx.x & 31;
    float4 r = make_float4(0.f, 0.f, 0.f, 0.f);
    for (int k = 0; k < nt; k++) {
        const EdgeT& t = ea.t[k];
        float4 bb = ((const float4*)t.bias)[lane];
        r.x += bb.x; r.y += bb.y; r.z += bb.z; r.w += bb.w;
        int s0 = t.off[d], s1 = t.off[d + 1];
        if (s1 > s0) {
            int cr = t.rank[d];
            float4 xr4 = ldh4(t.xr + (size_t)cr * 128 + lane * 4);
            float4 at = ((const float4*)t.att)[lane];
            float m = -INFINITY, den = 0.f;
            float a0 = 0.f, a1 = 0.f, a2 = 0.f, a3 = 0.f;
            for (int e = s0; e < s1; e++) {
                int si = t.csr[e];
                float4 xv = ldh4(t.xl + (size_t)si * 128 + lane * 4);
                float t0 = xv.x + xr4.x, t1 = xv.y + xr4.y, t2 = xv.z + xr4.z, t3 = xv.w + xr4.w;
                t0 = t0 > 0.f ? t0 : NEG_SLOPE * t0;
                t1 = t1 > 0.f ? t1 : NEG_SLOPE * t1;
                t2 = t2 > 0.f ? t2 : NEG_SLOPE * t2;
                t3 = t3 > 0.f ? t3 : NEG_SLOPE * t3;
                float p = t0 * at.x + t1 * at.y + t2 * at.z + t3 * at.w;
#pragma unroll
                for (int o = 16; o; o >>= 1) p += __shfl_xor_sync(0xffffffffu, p, o);
                float mn = fmaxf(m, p);
                float corr = __expf(m - mn);
                float w = __expf(p - mn);
                den = den * corr + w;
                a0 = a0 * corr + w * xv.x;
                a1 = a1 * corr + w * xv.y;
                a2 = a2 * corr + w * xv.z;
                a3 = a3 * corr + w * xv.w;
                m = mn;
            }
            float inv = 1.f / den;
            r.x += a0 * inv; r.y += a1 * inv; r.z += a2 * inv; r.w += a3 * inv;
        }
    }
    __half2 p0 = __floats2half2_rn(r.x, r.y);
    __half2 p1 = __floats2half2_rn(r.z, r.w);
    uint2 packed;
    packed.x = *(unsigned*)&p0;
    packed.y = *(unsigned*)&p1;
    *(uint2*)(agg + (size_t)d * 128 + lane * 4) = packed;
}

// ---------------- decoder with fused relu (fp16 in, fp32 out) ----------------
__global__ void decode_k(const __half* __restrict__ agg, const float* __restrict__ W,
                         const float* __restrict__ b, float* __restrict__ out, int N) {
    int f = blockIdx.x * 8 + (threadIdx.x >> 5);
    if (f >= N) return;
    int lane = threadIdx.x & 31;
    float4 v = ldh4(agg + (size_t)f * 128 + lane * 4);
    v.x = fmaxf(v.x, 0.f); v.y = fmaxf(v.y, 0.f); v.z = fmaxf(v.z, 0.f); v.w = fmaxf(v.w, 0.f);
    int h = lane * 4;
    float s0 = v.x * W[(h + 0) * 3 + 0] + v.y * W[(h + 1) * 3 + 0] + v.z * W[(h + 2) * 3 + 0] + v.w * W[(h + 3) * 3 + 0];
    float s1 = v.x * W[(h + 0) * 3 + 1] + v.y * W[(h + 1) * 3 + 1] + v.z * W[(h + 2) * 3 + 1] + v.w * W[(h + 3) * 3 + 1];
    float s2 = v.x * W[(h + 0) * 3 + 2] + v.y * W[(h + 1) * 3 + 2] + v.z * W[(h + 2) * 3 + 2] + v.w * W[(h + 3) * 3 + 2];
#pragma unroll
    for (int o = 16; o; o >>= 1) {
        s0 += __shfl_xor_sync(0xffffffffu, s0, o);
        s1 += __shfl_xor_sync(0xffffffffu, s1, o);
        s2 += __shfl_xor_sync(0xffffffffu, s2, o);
    }
    if (lane == 0) {
        out[f * 3 + 0] = s0 + b[0];
        out[f * 3 + 1] = s1 + b[1];
        out[f * 3 + 2] = s2 + b[2];
    }
}

// ---------------- host orchestration ----------------
extern "C" void kernel_launch(void* const* d_in, const int* in_sizes, int n_in,
                              void* d_out, int out_size) {
    int I[27];
    if (in_sizes[1] == 768) {
        const int m[27] = {0, 3, 6, 1, 2, 4, 5, 7, 8,
                           19, 20, 21, 22, 23, 24, 25, 26,
                           9, 10, 11, 12, 13, 14, 15, 16, 17, 18};
        for (int i = 0; i < 27; i++) I[i] = m[i];
    } else {
        for (int i = 0; i < 27; i++) I[i] = i;
    }

    const float* x_in[3] = {(const float*)d_in[I[0]], (const float*)d_in[I[1]], (const float*)d_in[I[2]]};
    const float* Wenc[3] = {(const float*)d_in[I[3]], (const float*)d_in[I[5]], (const float*)d_in[I[7]]};
    const float* benc[3] = {(const float*)d_in[I[4]], (const float*)d_in[I[6]], (const float*)d_in[I[8]]};
    const float* Wl = (const float*)d_in[I[9]];
    const float* bl = (const float*)d_in[I[10]];
    const float* Wr = (const float*)d_in[I[11]];
    const float* br = (const float*)d_in[I[12]];
    const float* att = (const float*)d_in[I[13]];
    const float* cb = (const float*)d_in[I[14]];
    const float* Wdec = (const float*)d_in[I[15]];
    const float* bdec = (const float*)d_in[I[16]];
    const int *srcA[5], *dstA[5];
    int E[5];
    for (int t = 0; t < 5; t++) {
        srcA[t] = (const int*)d_in[I[17 + 2 * t]];
        dstA[t] = (const int*)d_in[I[18 + 2 * t]];
        E[t] = in_sizes[I[17 + 2 * t]];
    }

    __half *bufA, *bufB, *pool;
    __nv_bfloat16 *Wthi, *Wtlo;
    int *rankB, *listB, *scanB, *degB, *off5, *cur5, *csrB, *cnt, *part;
    cudaGetSymbolAddress((void**)&bufA, g_bufA);
    cudaGetSymbolAddress((void**)&bufB, g_bufB);
    cudaGetSymbolAddress((void**)&pool, g_pool);
    cudaGetSymbolAddress((void**)&Wthi, g_Wthi);
    cudaGetSymbolAddress((void**)&Wtlo, g_Wtlo);
    cudaGetSymbolAddress((void**)&rankB, g_rank);
    cudaGetSymbolAddress((void**)&listB, g_list);
    cudaGetSymbolAddress((void**)&scanB, g_scan);
    cudaGetSymbolAddress((void**)&degB, g_deg);
    cudaGetSymbolAddress((void**)&off5, g_off5);
    cudaGetSymbolAddress((void**)&cur5, g_cur5);
    cudaGetSymbolAddress((void**)&csrB, g_csr);
    cudaGetSymbolAddress((void**)&cnt, g_cnt);
    cudaGetSymbolAddress((void**)&part, g_part);

    const int Nn[3] = {NBASE, NJOINT, NFOOT};
    const int Kin[3] = {6, 2, 4};
    const size_t XOFF[3] = {0, (size_t)NBASE * 128, (size_t)(NBASE + NJOINT) * 128};
    const int sT[5] = {0, 1, 1, 1, 2};
    const int dT[5] = {1, 0, 1, 2, 1};
    const size_t POOL[10] = {0, 40000, 200000, 360000, 400000, 720000, 1040000, 1200000, 1360000, 1520000};
    const int GRIDR[10] = {625, 2500, 2500, 625, 5000, 5000, 2500, 2500, 2500, 2500};

    const int SMEM = (2 * SAE + 2 * SBE) * 2;   // 104448 B -> 2 CTAs/SM
    cudaFuncSetAttribute(gemm_batch_k, cudaFuncAttributeMaxDynamicSharedMemorySize, SMEM);

    // ---- once-per-call prep ----
    wprep_k<<<(40 * 16384 + 255) / 256, 256>>>(Wl, Wr, Wthi, Wtlo);
    for (int t = 0; t < 3; t++)
        encode_k<<<(Nn[t] * HDIM + 255) / 256, 256>>>(
            x_in[t], Wenc[t], benc[t], bufA + XOFF[t], Nn[t], Kin[t]);

    EL el;
    el.cumE[0] = 0;
    for (int t = 0; t < 5; t++) {
        el.src[t] = srcA[t];
        el.dst[t] = dstA[t];
        el.cumE[t + 1] = el.cumE[t] + E[t];
    }
    int Etot = el.cumE[5];
    NArr na;
    for (int ei = 0; ei < 5; ei++) {
        na.N[2 * ei] = Nn[sT[ei]];
        na.N[2 * ei + 1] = Nn[dT[ei]];
    }

    // role compaction (batched)
    cudaMemsetAsync(rankB, 0, (size_t)10 * RSTR * 4);
    mark_all_k<<<(2 * Etot + 255) / 256, 256>>>(el, Etot);
    bscan1_k<<<10 * NBLK, 1024>>>(rankB, scanB, part);
    bscan2_k<<<10, 512>>>(part);
    bscan3_k<<<10 * NBLK, 1024>>>(scanB, part);
    bcompact_k<<<(10 * RSTR + 255) / 256, 256>>>(na);
    getcnt_k<<<1, 16>>>(na);

    // CSR build (batched)
    cudaMemsetAsync(degB, 0, (size_t)5 * RSTR * 4);
    bhist_k<<<(Etot + 255) / 256, 256>>>(el, Etot);
    bscan1_k<<<5 * NBLK, 1024>>>(degB, off5, part);
    bscan2_k<<<5, 512>>>(part);
    bscan3_k<<<5 * NBLK, 1024>>>(off5, part);
    cudaMemcpyAsync(cur5, off5, (size_t)5 * RSTR * 4, cudaMemcpyDeviceToDevice);
    bfill_k<<<(Etot + 255) / 256, 256>>>(el, Etot);

    __half* x = bufA;
    __half* agg = bufB;

    auto makeRole = [&](int ei, int side, int l) {
        int role = 2 * ei + side;
        int po = l * 5 + ei;
        int wIdx = side ? (20 + po) : po;
        GR R;
        R.A = x + XOFF[side ? dT[ei] : sT[ei]];
        R.rowlist = listB + (size_t)role * RSTR;
        R.cntPtr = cnt + role;
        R.Bhi = Wthi + (size_t)wIdx * 16384;
        R.Blo = Wtlo + (size_t)wIdx * 16384;
        R.bias = side ? (br + (size_t)po * 128) : (bl + (size_t)po * 128);
        R.out = pool + POOL[role] * 128;
        return R;
    };
    auto edgeT = [&](int ei, int l) {
        int po = l * 5 + ei;
        EdgeT t;
        t.xl = pool + POOL[2 * ei] * 128;
        t.xr = pool + POOL[2 * ei + 1] * 128;
        t.csr = csrB + el.cumE[ei];
        t.off = off5 + (size_t)ei * RSTR;
        t.rank = rankB + (size_t)(2 * ei + 1) * RSTR;
        t.att = att + (size_t)po * 128;
        t.bias = cb + (size_t)po * 128;
        return t;
    };

    for (int l = 0; l < 4; l++) {
        bool last = (l == 3);
        bool skipJb = (l == 2);   // layer-2 base agg never consumed by layer 3

        GB gb;
        int nr = 0, cum = 0;
        if (!last) {
            for (int ei = 0; ei < 5; ei++) {
                if (skipJb && ei == 1) continue;
                for (int side = 0; side < 2; side++) {
                    gb.r[nr] = makeRole(ei, side, l);
                    gb.cum[nr] = cum;
                    cum += GRIDR[2 * ei + side];
                    nr++;
                }
            }
        } else {
            for (int side = 0; side < 2; side++) {
                gb.r[nr] = makeRole(3, side, l);
                gb.cum[nr] = cum;
                cum += GRIDR[6 + side];
                nr++;
            }
        }
        gb.cum[nr] = cum;
        gb.n = nr;
        gemm_batch_k<<<cum, 256, SMEM>>>(gb);

        if (!last) {
            EdgeArgs eaJ; eaJ.t[0] = edgeT(0, l); eaJ.t[1] = edgeT(2, l); eaJ.t[2] = edgeT(4, l);
            edge_multi_k<<<(NJOINT + 7) / 8, 256>>>(eaJ, 3, agg + XOFF[1], NJOINT);
            if (!skipJb) {
                EdgeArgs eaB; eaB.t[0] = edgeT(1, l); eaB.t[1] = eaB.t[0]; eaB.t[2] = eaB.t[0];
                edge_multi_k<<<(NBASE + 7) / 8, 256>>>(eaB, 1, agg + XOFF[0], NBASE);
            }
            EdgeArgs eaF; eaF.t[0] = edgeT(3, l); eaF.t[1] = eaF.t[0]; eaF.t[2] = eaF.t[0];
            edge_multi_k<<<(NFOOT + 7) / 8, 256>>>(eaF, 1, agg + XOFF[2], NFOOT);
            __half* tmp = x; x = agg; agg = tmp;
        } else {
            EdgeArgs eaF; eaF.t[0] = edgeT(3, l); eaF.t[1] = eaF.t[0]; eaF.t[2] = eaF.t[0];
            edge_multi_k<<<(NFOOT + 7) / 8, 256>>>(eaF, 1, agg + XOFF[2], NFOOT);
        }
    }

    decode_k<<<(NFOOT + 7) / 8, 256>>>(agg + XOFF[2], Wdec, bdec, (float*)d_out, NFOOT);
}

// round 10
// speedup vs baseline: 5.8825x; 1.0872x over previous
#include <cuda_runtime.h>
#include <cuda_bf16.h>
#include <cuda_fp16.h>
#include <math.h>

#define NBASE 40000
#define NJOINT 480000
#define NFOOT 160000
#define HDIM 128
#define NEG_SLOPE 0.2f
#define RSTR 481280      // padded per-role segment stride (= 470*1024)
#define NBLK 470         // 1024-elem scan blocks per segment

// ---------------- scratch (device globals; ~1.0 GB, linker-safe) ----------------
__device__ __half g_bufA[(size_t)680000 * 128];   // x / agg ping-pong (fp16 storage)
__device__ __half g_bufB[(size_t)680000 * 128];
__device__ __half g_pool[(size_t)1680000 * 128];  // compact xl/xr rows (fp16)
__device__ __nv_bfloat16 g_Wthi[40 * 16384];
__device__ __nv_bfloat16 g_Wtlo[40 * 16384];
__device__ int g_rank[10 * RSTR];
__device__ int g_list[10 * RSTR];
__device__ int g_scan[10 * RSTR];
__device__ int g_deg[5 * RSTR];
__device__ int g_off5[5 * RSTR];
__device__ int g_cur5[5 * RSTR];
__device__ int g_csr[960000];
__device__ int g_cnt[16];
__device__ int g_part[10 * 512];

// ---------------- helpers ----------------
static __device__ __forceinline__ void bf16split(float v, __nv_bfloat16& h, __nv_bfloat16& l) {
    h = __float2bfloat16(v);
    l = __float2bfloat16(v - __bfloat162float(h));
}

__global__ void wprep_k(const float* __restrict__ Wl, const float* __restrict__ Wr,
                        __nv_bfloat16* __restrict__ hi, __nv_bfloat16* __restrict__ lo) {
    int idx = blockIdx.x * 256 + threadIdx.x;
    if (idx >= 40 * 16384) return;
    int m = idx >> 14, e = idx & 16383;
    int n = e >> 7, k = e & 127;
    const float* src = (m < 20) ? (Wl + (size_t)m * 16384) : (Wr + (size_t)(m - 20) * 16384);
    float v = src[k * 128 + n];
    __nv_bfloat16 h, l;
    bf16split(v, h, l);
    hi[idx] = h; lo[idx] = l;
}

// vectorized encoder: each thread computes 4 output cols via float4 W loads
__global__ void encode_k(const float* __restrict__ x, const float* __restrict__ W,
                         const float* __restrict__ b, __half* __restrict__ y, int N, int K) {
    int idx = blockIdx.x * 256 + threadIdx.x;   // over N*32 float4-groups
    if (idx >= N * 32) return;
    int n = idx >> 5, q = idx & 31;
    float4 acc = ((const float4*)b)[q];
    for (int k = 0; k < K; k++) {
        float xv = __ldg(x + (size_t)n * K + k);
        float4 w = ((const float4*)W)[k * 32 + q];
        acc.x += xv * w.x; acc.y += xv * w.y; acc.z += xv * w.z; acc.w += xv * w.w;
    }
    __half2 h0 = __floats2half2_rn(fmaxf(acc.x, 0.f), fmaxf(acc.y, 0.f));
    __half2 h1 = __floats2half2_rn(fmaxf(acc.z, 0.f), fmaxf(acc.w, 0.f));
    uint2 p;
    p.x = *(unsigned*)&h0;
    p.y = *(unsigned*)&h1;
    *(uint2*)(y + (size_t)n * 128 + q * 4) = p;
}

// ---------------- batched prep ----------------
struct EL {
    const int* src[5];
    const int* dst[5];
    int cumE[6];
};
struct NArr { int N[10]; };

__global__ void mark_all_k(EL el, int total) {
    int gi = blockIdx.x * 256 + threadIdx.x;
    if (gi >= 2 * total) return;
    int side = gi >= total;
    int j = gi - side * total;
    int t = 0;
    while (j >= el.cumE[t + 1]) t++;
    int e = j - el.cumE[t];
    int node = side ? el.dst[t][e] : el.src[t][e];
    g_rank[(2 * t + side) * RSTR + node] = 1;
}

__global__ void bscan1_k(const int* __restrict__ v, int* __restrict__ out,
                         int* __restrict__ part) {
    __shared__ int sh[1024];
    int r = blockIdx.x / NBLK, j = blockIdx.x % NBLK;
    int i = r * RSTR + j * 1024 + threadIdx.x;
    int val = v[i];
    sh[threadIdx.x] = val;
    __syncthreads();
#pragma unroll
    for (int o = 1; o < 1024; o <<= 1) {
        int t = (threadIdx.x >= o) ? sh[threadIdx.x - o] : 0;
        __syncthreads();
        sh[threadIdx.x] += t;
        __syncthreads();
    }
    int incl = sh[threadIdx.x];
    out[i] = incl - val;
    if (threadIdx.x == 1023) part[r * 512 + j] = incl;
}
__global__ void bscan2_k(int* part) {
    __shared__ int sh[512];
    int r = blockIdx.x;
    int v = (threadIdx.x < NBLK) ? part[r * 512 + threadIdx.x] : 0;
    sh[threadIdx.x] = v;
    __syncthreads();
#pragma unroll
    for (int o = 1; o < 512; o <<= 1) {
        int t = (threadIdx.x >= o) ? sh[threadIdx.x - o] : 0;
        __syncthreads();
        sh[threadIdx.x] += t;
        __syncthreads();
    }
    if (threadIdx.x < NBLK) part[r * 512 + threadIdx.x] = sh[threadIdx.x] - v;
}
__global__ void bscan3_k(int* __restrict__ out, const int* __restrict__ part) {
    int r = blockIdx.x / NBLK, j = blockIdx.x % NBLK;
    int i = r * RSTR + j * 1024 + threadIdx.x;
    out[i] += part[r * 512 + j];
}

__global__ void bcompact_k(NArr na) {
    int i = blockIdx.x * 256 + threadIdx.x;
    if (i >= 10 * RSTR) return;
    int r = i / RSTR, li = i % RSTR;
    if (li >= na.N[r]) return;
    if (g_rank[i]) {
        int pos = g_scan[i];
        g_list[r * RSTR + pos] = li;
        g_rank[i] = pos;
    } else {
        g_rank[i] = -1;
    }
}
__global__ void getcnt_k(NArr na) {
    int r = threadIdx.x;
    if (r < 10) g_cnt[r] = g_scan[r * RSTR + na.N[r]];
}

__global__ void bhist_k(EL el, int total) {
    int j = blockIdx.x * 256 + threadIdx.x;
    if (j >= total) return;
    int t = 0;
    while (j >= el.cumE[t + 1]) t++;
    int e = j - el.cumE[t];
    atomicAdd(&g_deg[t * RSTR + el.dst[t][e]], 1);
}
__global__ void bfill_k(EL el, int total) {
    int j = blockIdx.x * 256 + threadIdx.x;
    if (j >= total) return;
    int t = 0;
    while (j >= el.cumE[t + 1]) t++;
    int e = j - el.cumE[t];
    int d = el.dst[t][e];
    int p = atomicAdd(&g_cur5[t * RSTR + d], 1);
    g_csr[el.cumE[t] + p] = g_rank[(2 * t) * RSTR + el.src[t][e]];
}

// ---------------- batched gather-GEMM (M-tile 64, dual-CTA, fp16 I/O) ----------------
#define SAE 8704    // 64*136 bf16 elems (A matrix)
#define SBE 17408   // 128*136 bf16 elems (B matrix)

#define LDSM4(R, addr) asm volatile( \
    "ldmatrix.sync.aligned.m8n8.x4.shared.b16 {%0,%1,%2,%3}, [%4];" \
    : "=r"((R)[0]), "=r"((R)[1]), "=r"((R)[2]), "=r"((R)[3]) : "r"(addr))

#define MMA16816(C, A, b0, b1) asm volatile( \
    "mma.sync.aligned.m16n8k16.row.col.f32.bf16.bf16.f32 " \
    "{%0,%1,%2,%3},{%4,%5,%6,%7},{%8,%9},{%0,%1,%2,%3};" \
    : "+f"((C)[0]), "+f"((C)[1]), "+f"((C)[2]), "+f"((C)[3]) \
    : "r"((A)[0]), "r"((A)[1]), "r"((A)[2]), "r"((A)[3]), "r"(b0), "r"(b1))

static __device__ __forceinline__ void cpasync16(unsigned dst, const void* src, int sz) {
    asm volatile("cp.async.cg.shared.global [%0], [%1], 16, %2;" :: "r"(dst), "l"(src), "r"(sz));
}

struct GR {
    const __half* A;
    const int* rowlist;
    const int* cntPtr;
    const __nv_bfloat16* Bhi;
    const __nv_bfloat16* Blo;
    const float* bias;
    __half* out;
};
struct GB { GR r[10]; int cum[11]; int n; };

__global__ void __launch_bounds__(256, 2) gemm_batch_k(GB gb) {
    int b = blockIdx.x;
    int k = 0;
    while (k < gb.n - 1 && b >= gb.cum[k + 1]) k++;
    GR R = gb.r[k];
    const int cnt = *R.cntPtr;
    const int row0 = (b - gb.cum[k]) * 64;
    if (row0 >= cnt) return;

    extern __shared__ __nv_bfloat16 smem[];
    const int tid = threadIdx.x;
    unsigned sAhi = (unsigned)__cvta_generic_to_shared(smem);
    unsigned sB = sAhi + 2 * SAE * 2;

    // 1) B hi/lo via cp.async FIRST
#pragma unroll
    for (int i = 0; i < 8; i++) {
        int chunk = tid + i * 256;
        int row = chunk >> 4;
        int col = (chunk & 15) * 8;
        size_t off = (size_t)row * 128 + col;
        unsigned d = sB + (unsigned)(row * 136 + col) * 2;
        cpasync16(d, R.Bhi + off, 16);
        cpasync16(d + SBE * 2, R.Blo + off, 16);
    }
    asm volatile("cp.async.commit_group;");

    // 2) A: gather fp16 rows -> relu -> bf16 hi/lo split -> smem
#pragma unroll
    for (int i = 0; i < 4; i++) {
        int chunk = tid + i * 256;
        int row = chunk >> 4;
        int c8 = (chunk & 15) * 8;
        int ok = (row0 + row) < cnt;
        int node = ok ? R.rowlist[row0 + row] : 0;
        uint4 raw = ok ? *(const uint4*)(R.A + (size_t)node * 128 + c8)
                       : make_uint4(0u, 0u, 0u, 0u);
        const __half2* hp = (const __half2*)&raw;
        int base = row * 136 + c8;
#pragma unroll
        for (int q = 0; q < 4; q++) {
            float2 f = __half22float2(hp[q]);
            f.x = fmaxf(f.x, 0.f);
            f.y = fmaxf(f.y, 0.f);
            __nv_bfloat16 h0, l0, h1, l1;
            bf16split(f.x, h0, l0);
            bf16split(f.y, h1, l1);
            *(__nv_bfloat162*)(smem + base + 2 * q)       = __nv_bfloat162(h0, h1);
            *(__nv_bfloat162*)(smem + SAE + base + 2 * q) = __nv_bfloat162(l0, l1);
        }
    }
    asm volatile("cp.async.wait_group 0;");
    __syncthreads();

    // 3) MMA: 8 warps as 2M x 4N
    int warp = tid >> 5, lane = tid & 31;
    int m0 = (warp >> 2) * 32;
    int n0 = (warp & 3) * 32;
    int frow = lane & 15;
    int fcolo = (lane >> 4) * 8;

    float acc[2][4][4];
#pragma unroll
    for (int a = 0; a < 2; a++)
#pragma unroll
        for (int c = 0; c < 4; c++)
#pragma unroll
            for (int r = 0; r < 4; r++) acc[a][c][r] = 0.f;

    for (int ks = 0; ks < 8; ks++) {
        int acol = ks * 16 + fcolo;
        unsigned ah[2][4], al[2][4];
#pragma unroll
        for (int mt = 0; mt < 2; mt++) {
            unsigned ad = sAhi + (unsigned)((m0 + mt * 16 + frow) * 136 + acol) * 2;
            LDSM4(ah[mt], ad);
            LDSM4(al[mt], ad + SAE * 2);
        }
        unsigned bh[2][4], blx[2][4];
#pragma unroll
        for (int p = 0; p < 2; p++) {
            unsigned bd = sB + (unsigned)((n0 + p * 16 + frow) * 136 + acol) * 2;
            LDSM4(bh[p], bd);
            LDSM4(blx[p], bd + SBE * 2);
        }
#pragma unroll
        for (int mt = 0; mt < 2; mt++)
#pragma unroll
            for (int nt = 0; nt < 4; nt++) {
                int p = nt >> 1, o = nt & 1;
                MMA16816(acc[mt][nt], ah[mt], bh[p][o], bh[p][2 + o]);
                MMA16816(acc[mt][nt], ah[mt], blx[p][o], blx[p][2 + o]);
                MMA16816(acc[mt][nt], al[mt], bh[p][o], bh[p][2 + o]);
            }
    }

    int crow = lane >> 2, ccol = (lane & 3) * 2;
#pragma unroll
    for (int nt = 0; nt < 4; nt++) {
        int col = n0 + nt * 8 + ccol;
        float b0v = R.bias[col], b1v = R.bias[col + 1];
#pragma unroll
        for (int mt = 0; mt < 2; mt++) {
            int r = row0 + m0 + mt * 16 + crow;
            if (r < cnt)
                *(__half2*)(R.out + (size_t)r * 128 + col) =
                    __floats2half2_rn(acc[mt][nt][0] + b0v, acc[mt][nt][1] + b1v);
            if (r + 8 < cnt)
                *(__half2*)(R.out + (size_t)(r + 8) * 128 + col) =
                    __floats2half2_rn(acc[mt][nt][2] + b0v, acc[mt][nt][3] + b1v);
        }
    }
}

// ---------------- fused per-layer edge kernel ----------------
struct EdgeT {
    const __half* xl;
    const __half* xr;
    const int* csr;
    const int* off;
    const int* rank;
    const float* att;
    const float* bias;
};

static __device__ __forceinline__ float4 ldh4(const __half* p) {
    uint2 raw = *(const uint2*)p;
    const __half2* hp = (const __half2*)&raw;
    float2 a = __half22float2(hp[0]);
    float2 b = __half22float2(hp[1]);
    return make_float4(a.x, a.y, b.x, b.y);
}

static __device__ __forceinline__ float edge_logit(float4 xv, float4 xr4, float4 at) {
    float t0 = xv.x + xr4.x, t1 = xv.y + xr4.y, t2 = xv.z + xr4.z, t3 = xv.w + xr4.w;
    t0 = t0 > 0.f ? t0 : NEG_SLOPE * t0;
    t1 = t1 > 0.f ? t1 : NEG_SLOPE * t1;
    t2 = t2 > 0.f ? t2 : NEG_SLOPE * t2;
    t3 = t3 > 0.f ? t3 : NEG_SLOPE * t3;
    return t0 * at.x + t1 * at.y + t2 * at.z + t3 * at.w;
}

// accumulate bias + softmax-weighted mean for one edge type into r (unroll-2, MLP=2)
static __device__ __forceinline__ void proc_one(const EdgeT& t, int d, int lane, float4& r) {
    float4 bb = ((const float4*)t.bias)[lane];
    r.x += bb.x; r.y += bb.y; r.z += bb.z; r.w += bb.w;
    int s0 = t.off[d], s1 = t.off[d + 1];
    if (s1 <= s0) return;
    int cr = t.rank[d];
    float4 xr4 = ldh4(t.xr + (size_t)cr * 128 + lane * 4);
    float4 at = ((const float4*)t.att)[lane];
    float m = -INFINITY, den = 0.f;
    float a0 = 0.f, a1 = 0.f, a2 = 0.f, a3 = 0.f;
    int e = s0;
    for (; e + 1 < s1; e += 2) {
        int si0 = t.csr[e], si1 = t.csr[e + 1];
        float4 x0 = ldh4(t.xl + (size_t)si0 * 128 + lane * 4);
        float4 x1 = ldh4(t.xl + (size_t)si1 * 128 + lane * 4);
        float p0 = edge_logit(x0, xr4, at);
        float p1 = edge_logit(x1, xr4, at);
#pragma unroll
        for (int o = 16; o; o >>= 1) {
            p0 += __shfl_xor_sync(0xffffffffu, p0, o);
            p1 += __shfl_xor_sync(0xffffffffu, p1, o);
        }
        float mn = fmaxf(m, fmaxf(p0, p1));
        float c = __expf(m - mn);
        float w0 = __expf(p0 - mn);
        float w1 = __expf(p1 - mn);
        den = den * c + w0 + w1;
        a0 = a0 * c + w0 * x0.x + w1 * x1.x;
        a1 = a1 * c + w0 * x0.y + w1 * x1.y;
        a2 = a2 * c + w0 * x0.z + w1 * x1.z;
        a3 = a3 * c + w0 * x0.w + w1 * x1.w;
        m = mn;
    }
    if (e < s1) {
        int si = t.csr[e];
        float4 xv = ldh4(t.xl + (size_t)si * 128 + lane * 4);
        float p = edge_logit(xv, xr4, at);
#pragma unroll
        for (int o = 16; o; o >>= 1) p += __shfl_xor_sync(0xffffffffu, p, o);
        float mn = fmaxf(m, p);
        float c = __expf(m - mn);
        float w = __expf(p - mn);
        den = den * c + w;
        a0 = a0 * c + w * xv.x;
        a1 = a1 * c + w * xv.y;
        a2 = a2 * c + w * xv.z;
        a3 = a3 * c + w * xv.w;
    }
    float inv = 1.f / den;
    r.x += a0 * inv; r.y += a1 * inv; r.z += a2 * inv; r.w += a3 * inv;
}

static __device__ __forceinline__ void store_agg(__half* agg, int d, int lane, float4 r) {
    __half2 p0 = __floats2half2_rn(r.x, r.y);
    __half2 p1 = __floats2half2_rn(r.z, r.w);
    uint2 packed;
    packed.x = *(unsigned*)&p0;
    packed.y = *(unsigned*)&p1;
    *(uint2*)(agg + (size_t)d * 128 + lane * 4) = packed;
}

struct LayerED {
    EdgeT tJ0, tJ1, tJ2;   // joint dst types (bj, jj, fj)
    EdgeT tB;              // base dst (jb)
    EdgeT tF;              // foot dst (jf)
    __half *aggJ, *aggB, *aggF;
    int bB0, bF0;          // block ranges: joint [0,bB0), base [bB0,bF0), foot [bF0,...)
    const float* Wdec;
    const float* bdec;
    float* dec_out;
    int doDecode;
};

__global__ void edge_layer_k(LayerED L) {
    int blk = blockIdx.x;
    int w = threadIdx.x >> 5;
    int lane = threadIdx.x & 31;
    float4 r = make_float4(0.f, 0.f, 0.f, 0.f);
    if (blk < L.bB0) {
        int d = blk * 8 + w;
        proc_one(L.tJ0, d, lane, r);
        proc_one(L.tJ1, d, lane, r);
        proc_one(L.tJ2, d, lane, r);
        store_agg(L.aggJ, d, lane, r);
    } else if (blk < L.bF0) {
        int d = (blk - L.bB0) * 8 + w;
        proc_one(L.tB, d, lane, r);
        store_agg(L.aggB, d, lane, r);
    } else {
        int d = (blk - L.bF0) * 8 + w;
        proc_one(L.tF, d, lane, r);
        if (!L.doDecode) {
            store_agg(L.aggF, d, lane, r);
        } else {
            // fused decoder: relu + [128]x[128,3] matvec
            r.x = fmaxf(r.x, 0.f); r.y = fmaxf(r.y, 0.f);
            r.z = fmaxf(r.z, 0.f); r.w = fmaxf(r.w, 0.f);
            int h = lane * 4;
            const float* W = L.Wdec;
            float s0 = r.x * W[(h + 0) * 3 + 0] + r.y * W[(h + 1) * 3 + 0] + r.z * W[(h + 2) * 3 + 0] + r.w * W[(h + 3) * 3 + 0];
            float s1 = r.x * W[(h + 0) * 3 + 1] + r.y * W[(h + 1) * 3 + 1] + r.z * W[(h + 2) * 3 + 1] + r.w * W[(h + 3) * 3 + 1];
            float s2 = r.x * W[(h + 0) * 3 + 2] + r.y * W[(h + 1) * 3 + 2] + r.z * W[(h + 2) * 3 + 2] + r.w * W[(h + 3) * 3 + 2];
#pragma unroll
            for (int o = 16; o; o >>= 1) {
                s0 += __shfl_xor_sync(0xffffffffu, s0, o);
                s1 += __shfl_xor_sync(0xffffffffu, s1, o);
                s2 += __shfl_xor_sync(0xffffffffu, s2, o);
            }
            if (lane == 0) {
                L.dec_out[d * 3 + 0] = s0 + L.bdec[0];
                L.dec_out[d * 3 + 1] = s1 + L.bdec[1];
                L.dec_out[d * 3 + 2] = s2 + L.bdec[2];
            }
        }
    }
}

// ---------------- host orchestration ----------------
extern "C" void kernel_launch(void* const* d_in, const int* in_sizes, int n_in,
                              void* d_out, int out_size) {
    int I[27];
    if (in_sizes[1] == 768) {
        const int m[27] = {0, 3, 6, 1, 2, 4, 5, 7, 8,
                           19, 20, 21, 22, 23, 24, 25, 26,
                           9, 10, 11, 12, 13, 14, 15, 16, 17, 18};
        for (int i = 0; i < 27; i++) I[i] = m[i];
    } else {
        for (int i = 0; i < 27; i++) I[i] = i;
    }

    const float* x_in[3] = {(const float*)d_in[I[0]], (const float*)d_in[I[1]], (const float*)d_in[I[2]]};
    const float* Wenc[3] = {(const float*)d_in[I[3]], (const float*)d_in[I[5]], (const float*)d_in[I[7]]};
    const float* benc[3] = {(const float*)d_in[I[4]], (const float*)d_in[I[6]], (const float*)d_in[I[8]]};
    const float* Wl = (const float*)d_in[I[9]];
    const float* bl = (const float*)d_in[I[10]];
    const float* Wr = (const float*)d_in[I[11]];
    const float* br = (const float*)d_in[I[12]];
    const float* att = (const float*)d_in[I[13]];
    const float* cb = (const float*)d_in[I[14]];
    const float* Wdec = (const float*)d_in[I[15]];
    const float* bdec = (const float*)d_in[I[16]];
    const int *srcA[5], *dstA[5];
    int E[5];
    for (int t = 0; t < 5; t++) {
        srcA[t] = (const int*)d_in[I[17 + 2 * t]];
        dstA[t] = (const int*)d_in[I[18 + 2 * t]];
        E[t] = in_sizes[I[17 + 2 * t]];
    }

    __half *bufA, *bufB, *pool;
    __nv_bfloat16 *Wthi, *Wtlo;
    int *rankB, *listB, *scanB, *degB, *off5, *cur5, *csrB, *cnt, *part;
    cudaGetSymbolAddress((void**)&bufA, g_bufA);
    cudaGetSymbolAddress((void**)&bufB, g_bufB);
    cudaGetSymbolAddress((void**)&pool, g_pool);
    cudaGetSymbolAddress((void**)&Wthi, g_Wthi);
    cudaGetSymbolAddress((void**)&Wtlo, g_Wtlo);
    cudaGetSymbolAddress((void**)&rankB, g_rank);
    cudaGetSymbolAddress((void**)&listB, g_list);
    cudaGetSymbolAddress((void**)&scanB, g_scan);
    cudaGetSymbolAddress((void**)&degB, g_deg);
    cudaGetSymbolAddress((void**)&off5, g_off5);
    cudaGetSymbolAddress((void**)&cur5, g_cur5);
    cudaGetSymbolAddress((void**)&csrB, g_csr);
    cudaGetSymbolAddress((void**)&cnt, g_cnt);
    cudaGetSymbolAddress((void**)&part, g_part);

    const int Nn[3] = {NBASE, NJOINT, NFOOT};
    const int Kin[3] = {6, 2, 4};
    const size_t XOFF[3] = {0, (size_t)NBASE * 128, (size_t)(NBASE + NJOINT) * 128};
    const int sT[5] = {0, 1, 1, 1, 2};
    const int dT[5] = {1, 0, 1, 2, 1};
    const size_t POOL[10] = {0, 40000, 200000, 360000, 400000, 720000, 1040000, 1200000, 1360000, 1520000};
    const int GRIDR[10] = {625, 2500, 2500, 625, 5000, 5000, 2500, 2500, 2500, 2500};

    const int SMEM = (2 * SAE + 2 * SBE) * 2;   // 104448 B -> 2 CTAs/SM
    cudaFuncSetAttribute(gemm_batch_k, cudaFuncAttributeMaxDynamicSharedMemorySize, SMEM);

    // ---- once-per-call prep ----
    wprep_k<<<(40 * 16384 + 255) / 256, 256>>>(Wl, Wr, Wthi, Wtlo);
    for (int t = 0; t < 3; t++)
        encode_k<<<(Nn[t] * 32 + 255) / 256, 256>>>(
            x_in[t], Wenc[t], benc[t], bufA + XOFF[t], Nn[t], Kin[t]);

    EL el;
    el.cumE[0] = 0;
    for (int t = 0; t < 5; t++) {
        el.src[t] = srcA[t];
        el.dst[t] = dstA[t];
        el.cumE[t + 1] = el.cumE[t] + E[t];
    }
    int Etot = el.cumE[5];
    NArr na;
    for (int ei = 0; ei < 5; ei++) {
        na.N[2 * ei] = Nn[sT[ei]];
        na.N[2 * ei + 1] = Nn[dT[ei]];
    }

    // role compaction (batched)
    cudaMemsetAsync(rankB, 0, (size_t)10 * RSTR * 4);
    mark_all_k<<<(2 * Etot + 255) / 256, 256>>>(el, Etot);
    bscan1_k<<<10 * NBLK, 1024>>>(rankB, scanB, part);
    bscan2_k<<<10, 512>>>(part);
    bscan3_k<<<10 * NBLK, 1024>>>(scanB, part);
    bcompact_k<<<(10 * RSTR + 255) / 256, 256>>>(na);
    getcnt_k<<<1, 16>>>(na);

    // CSR build (batched)
    cudaMemsetAsync(degB, 0, (size_t)5 * RSTR * 4);
    bhist_k<<<(Etot + 255) / 256, 256>>>(el, Etot);
    bscan1_k<<<5 * NBLK, 1024>>>(degB, off5, part);
    bscan2_k<<<5, 512>>>(part);
    bscan3_k<<<5 * NBLK, 1024>>>(off5, part);
    cudaMemcpyAsync(cur5, off5, (size_t)5 * RSTR * 4, cudaMemcpyDeviceToDevice);
    bfill_k<<<(Etot + 255) / 256, 256>>>(el, Etot);

    __half* x = bufA;
    __half* agg = bufB;

    auto makeRole = [&](int ei, int side, int l) {
        int role = 2 * ei + side;
        int po = l * 5 + ei;
        int wIdx = side ? (20 + po) : po;
        GR R;
        R.A = x + XOFF[side ? dT[ei] : sT[ei]];
        R.rowlist = listB + (size_t)role * RSTR;
        R.cntPtr = cnt + role;
        R.Bhi = Wthi + (size_t)wIdx * 16384;
        R.Blo = Wtlo + (size_t)wIdx * 16384;
        R.bias = side ? (br + (size_t)po * 128) : (bl + (size_t)po * 128);
        R.out = pool + POOL[role] * 128;
        return R;
    };
    auto edgeT = [&](int ei, int l) {
        int po = l * 5 + ei;
        EdgeT t;
        t.xl = pool + POOL[2 * ei] * 128;
        t.xr = pool + POOL[2 * ei + 1] * 128;
        t.csr = csrB + el.cumE[ei];
        t.off = off5 + (size_t)ei * RSTR;
        t.rank = rankB + (size_t)(2 * ei + 1) * RSTR;
        t.att = att + (size_t)po * 128;
        t.bias = cb + (size_t)po * 128;
        return t;
    };

    for (int l = 0; l < 4; l++) {
        bool last = (l == 3);
        bool skipJb = (l == 2);

        GB gb;
        int nr = 0, cum = 0;
        if (!last) {
            for (int ei = 0; ei < 5; ei++) {
                if (skipJb && ei == 1) continue;
                for (int side = 0; side < 2; side++) {
                    gb.r[nr] = makeRole(ei, side, l);
                    gb.cum[nr] = cum;
                    cum += GRIDR[2 * ei + side];
                    nr++;
                }
            }
        } else {
            for (int side = 0; side < 2; side++) {
                gb.r[nr] = makeRole(3, side, l);
                gb.cum[nr] = cum;
                cum += GRIDR[6 + side];
                nr++;
            }
        }
        gb.cum[nr] = cum;
        gb.n = nr;
        gemm_batch_k<<<cum, 256, SMEM>>>(gb);

        LayerED L;
        L.Wdec = Wdec; L.bdec = bdec; L.dec_out = (float*)d_out;
        if (!last) {
            L.tJ0 = edgeT(0, l); L.tJ1 = edgeT(2, l); L.tJ2 = edgeT(4, l);
            L.tB = edgeT(1, l);
            L.tF = edgeT(3, l);
            L.aggJ = agg + XOFF[1];
            L.aggB = agg + XOFF[0];
            L.aggF = agg + XOFF[2];
            L.doDecode = 0;
            int gJ = NJOINT / 8;                       // 60000
            int gB = skipJb ? 0 : NBASE / 8;           // 5000 or 0
            int gF = NFOOT / 8;                        // 20000
            L.bB0 = gJ;
            L.bF0 = gJ + gB;
            edge_layer_k<<<gJ + gB + gF, 256>>>(L);
            __half* tmp = x; x = agg; agg = tmp;
        } else {
            L.tJ0 = L.tJ1 = L.tJ2 = edgeT(3, l);
            L.tB = edgeT(3, l);
            L.tF = edgeT(3, l);
            L.aggJ = L.aggB = L.aggF = agg + XOFF[2];
            L.doDecode = 1;
            L.bB0 = 0;
            L.bF0 = 0;
            edge_layer_k<<<NFOOT / 8, 256>>>(L);
        }
    }
}